// round 9
// baseline (speedup 1.0000x reference)
#include <cuda_runtime.h>
#include <cuda_bf16.h>
#include <cstdint>
#include <math.h>

// Problem constants
#define S_LEN 2048
#define HID 2048
#define NH 16
#define NKV 4
#define HD 128
#define QKV_OUT 3072
#define Q_SZ 2048
#define KV_SZ 512
#define SCALE_Q 0.08838834764831845f

typedef __nv_bfloat16 bf16;

// ---------------- scratch ----------------------------------------------------
__device__ float g_qkv[S_LEN * QKV_OUT];
__device__ bf16 g_hidh[S_LEN * HID], g_hidl[S_LEN * HID];
__device__ bf16 g_wqh[QKV_OUT * HID], g_wql[QKV_OUT * HID];
__device__ bf16 g_woh[HID * HID], g_wol[HID * HID];
__device__ bf16 g_qh[S_LEN * NH * HD], g_ql[S_LEN * NH * HD];
__device__ bf16 g_kh[S_LEN * NKV * HD], g_kl[S_LEN * NKV * HD];
__device__ bf16 g_vh[S_LEN * NKV * HD], g_vl[S_LEN * NKV * HD];
__device__ bf16 g_ah[S_LEN * NH * HD], g_al[S_LEN * NH * HD];

// ---------------- helpers ----------------------------------------------------
__device__ __forceinline__ uint32_t smem_u32(const void* p) {
    return (uint32_t)__cvta_generic_to_shared(p);
}
__device__ __forceinline__ float bfhi(float x) {
    return __bfloat162float(__float2bfloat16(x));
}
__device__ __forceinline__ uint32_t packbf(float lo_v, float hi_v) {
    uint32_t r;
    asm("cvt.rn.bf16x2.f32 %0, %1, %2;" : "=r"(r) : "f"(hi_v), "f"(lo_v));
    return r;
}

#define MMA_BF2(d, a, b0, b1) \
    asm volatile( \
        "mma.sync.aligned.m16n8k16.row.col.f32.bf16.bf16.f32 " \
        "{%0,%1,%2,%3}, {%4,%5,%6,%7}, {%8,%9}, {%0,%1,%2,%3};" \
        : "+f"((d)[0]), "+f"((d)[1]), "+f"((d)[2]), "+f"((d)[3]) \
        : "r"((a)[0]), "r"((a)[1]), "r"((a)[2]), "r"((a)[3]), \
          "r"(b0), "r"(b1))

#define LDSM4(r, addr) \
    asm volatile("ldmatrix.sync.aligned.m8n8.x4.shared.b16 {%0,%1,%2,%3}, [%4];" \
        : "=r"((r)[0]), "=r"((r)[1]), "=r"((r)[2]), "=r"((r)[3]) : "r"(addr))

#define LDSM4T(r, addr) \
    asm volatile("ldmatrix.sync.aligned.m8n8.x4.trans.shared.b16 {%0,%1,%2,%3}, [%4];" \
        : "=r"((r)[0]), "=r"((r)[1]), "=r"((r)[2]), "=r"((r)[3]) : "r"(addr))

#define CP16(dst, src) \
    asm volatile("cp.async.cg.shared.global [%0], [%1], 16;" :: "r"(dst), "l"(src))
#define CP_COMMIT() asm volatile("cp.async.commit_group;" ::: "memory")
#define CP_WAIT(n) asm volatile("cp.async.wait_group %0;" :: "n"(n) : "memory")

// ---------------- split kernels ---------------------------------------------
__global__ void split_bf16k(const float* __restrict__ src, bf16* __restrict__ hi,
                            bf16* __restrict__ lo, int n4) {
    __nv_bfloat162* H = (__nv_bfloat162*)hi;
    __nv_bfloat162* L = (__nv_bfloat162*)lo;
    for (int i = blockIdx.x * blockDim.x + threadIdx.x; i < n4;
         i += gridDim.x * blockDim.x) {
        float4 v = ((const float4*)src)[i];
        bf16 h0 = __float2bfloat16(v.x), h1 = __float2bfloat16(v.y);
        bf16 h2 = __float2bfloat16(v.z), h3 = __float2bfloat16(v.w);
        bf16 l0 = __float2bfloat16(v.x - __bfloat162float(h0));
        bf16 l1 = __float2bfloat16(v.y - __bfloat162float(h1));
        bf16 l2 = __float2bfloat16(v.z - __bfloat162float(h2));
        bf16 l3 = __float2bfloat16(v.w - __bfloat162float(h3));
        H[2 * i] = __nv_bfloat162(h0, h1);
        H[2 * i + 1] = __nv_bfloat162(h2, h3);
        L[2 * i] = __nv_bfloat162(l0, l1);
        L[2 * i + 1] = __nv_bfloat162(l2, l3);
    }
}

__global__ void copy_caches(const float* __restrict__ kc, const float* __restrict__ vc) {
    int n = S_LEN * NKV * HD;
    for (int i = blockIdx.x * blockDim.x + threadIdx.x; i < n;
         i += gridDim.x * blockDim.x) {
        float k = kc[i], v = vc[i];
        bf16 kh = __float2bfloat16(k);
        bf16 vh = __float2bfloat16(v);
        g_kh[i] = kh; g_kl[i] = __float2bfloat16(k - __bfloat162float(kh));
        g_vh[i] = vh; g_vl[i] = __float2bfloat16(v - __bfloat162float(vh));
    }
}

// ---------------- fused RMSNorm + RoPE + scale + scatter ---------------------
__global__ void norm_rope_scatter(const float* __restrict__ cosb,
                                  const float* __restrict__ sinb,
                                  const float* __restrict__ qw,
                                  const float* __restrict__ kw,
                                  const int* __restrict__ widx) {
    const int s = blockIdx.x;
    const int head = blockIdx.y;
    const int d = threadIdx.x;
    __shared__ float sh[128];
    __shared__ float wsum[4];

    int col;
    if (head < 16)      col = head * HD + d;
    else if (head < 20) col = Q_SZ + (head - 16) * HD + d;
    else                col = Q_SZ + KV_SZ + (head - 20) * HD + d;

    float x = g_qkv[(size_t)s * QKV_OUT + col];

    if (head >= 20) {
        size_t o = ((size_t)widx[s] * NKV + (head - 20)) * HD + d;
        bf16 h = __float2bfloat16(x);
        g_vh[o] = h;
        g_vl[o] = __float2bfloat16(x - __bfloat162float(h));
        return;
    }

    float sq = x * x;
#pragma unroll
    for (int m = 16; m; m >>= 1) sq += __shfl_xor_sync(0xffffffffu, sq, m);
    if ((d & 31) == 0) wsum[d >> 5] = sq;
    __syncthreads();
    float ms = (wsum[0] + wsum[1] + wsum[2] + wsum[3]) * (1.0f / 128.0f);
    float inv = rsqrtf(ms + 1e-6f);
    const float* w = (head < 16) ? qw : kw;
    float y = x * inv * w[d];
    sh[d] = y;
    __syncthreads();

    if (d < 64) {
        float c = cosb[s * 64 + d], sn = sinb[s * 64 + d];
        float x1 = sh[d], x2 = sh[d + 64];
        float y1 = x1 * c - x2 * sn;
        float y2 = x1 * sn + x2 * c;
        if (head < 16) {
            y1 *= SCALE_Q; y2 *= SCALE_Q;
            size_t o = ((size_t)s * NH + head) * HD;
            bf16 h1 = __float2bfloat16(y1), h2 = __float2bfloat16(y2);
            g_qh[o + d] = h1;
            g_ql[o + d] = __float2bfloat16(y1 - __bfloat162float(h1));
            g_qh[o + d + 64] = h2;
            g_ql[o + d + 64] = __float2bfloat16(y2 - __bfloat162float(h2));
        } else {
            size_t o = ((size_t)widx[s] * NKV + (head - 16)) * HD;
            bf16 h1 = __float2bfloat16(y1), h2 = __float2bfloat16(y2);
            g_kh[o + d] = h1;
            g_kl[o + d] = __float2bfloat16(y1 - __bfloat162float(h1));
            g_kh[o + d + 64] = h2;
            g_kl[o + d + 64] = __float2bfloat16(y2 - __bfloat162float(h2));
        }
    }
}

// =================== 3xBF16 GEMM: 512 thr, 128x256 tile, 3-stage =============
// C[M,N] = (Ah+Al)[M,K] @ (Bh+Bl)[N,K]^T + bias[N].
// 16 warps in 4x4 grid, warp tile 32x64, k-chunk 32.
#define GSTRIDE 40
#define ABUF_E (128 * GSTRIDE)            // 5120 elems
#define ABUF_B (ABUF_E * 2)               // 10240 bytes
#define BBUF_E (256 * GSTRIDE)            // 10240 elems
#define BBUF_B (BBUF_E * 2)               // 20480 bytes
#define GSTAGE_B (2 * ABUF_B + 2 * BBUF_B) // 61440 bytes
#define G_SMEM (3 * GSTAGE_B)              // 184320 bytes

__global__ void __launch_bounds__(512, 1)
gemm_bf(const bf16* __restrict__ Ah_g, const bf16* __restrict__ Al_g,
        const bf16* __restrict__ Bh_g, const bf16* __restrict__ Bl_g,
        const float* __restrict__ bias, float* __restrict__ C,
        int N, int K) {
    extern __shared__ bf16 smg[];
    const int t = threadIdx.x;
    const int lane = t & 31, wid = t >> 5;
    const int g = lane >> 2, tg = lane & 3;
    const int wm = (wid & 3) * 32;          // 0..96
    const int wn = (wid >> 2) * 64;         // 0..192
    const int m0 = blockIdx.y << 7, n0 = blockIdx.x << 8;
    const int nch = K >> 5;

    const int l15 = lane & 15, lh = lane >> 4;
    const uint32_t sb = smem_u32(smg);
    const uint32_t offA = (uint32_t)((wm + l15) * 80 + lh * 16);
    const uint32_t offB = (uint32_t)((wn + l15) * 80 + lh * 16);

    float d[2][8][4];
#pragma unroll
    for (int i = 0; i < 2; i++)
#pragma unroll
        for (int j = 0; j < 8; j++)
#pragma unroll
            for (int q = 0; q < 4; q++) d[i][j][q] = 0.f;

#define G_ISSUE(c) do { \
    uint32_t base = sb + ((c) % 3) * GSTAGE_B; \
    _Pragma("unroll") \
    for (int j = 0; j < 2; j++) { \
        int u = t + (j << 9); int r = u >> 2, q = u & 3; \
        int row = r & 127, bsel = r >> 7; \
        uint32_t dst = base + bsel * ABUF_B + (uint32_t)(row * GSTRIDE + (q << 3)) * 2; \
        const bf16* sp = (bsel ? Al_g : Ah_g) + (size_t)(m0 + row) * K + ((c) << 5) + (q << 3); \
        CP16(dst, sp); \
    } \
    _Pragma("unroll") \
    for (int j = 0; j < 4; j++) { \
        int u = t + (j << 9); int r = u >> 2, q = u & 3; \
        int row = r & 255, bsel = r >> 8; \
        uint32_t dst = base + 2 * ABUF_B + bsel * BBUF_B + (uint32_t)(row * GSTRIDE + (q << 3)) * 2; \
        const bf16* sp = (bsel ? Bl_g : Bh_g) + (size_t)(n0 + row) * K + ((c) << 5) + (q << 3); \
        CP16(dst, sp); \
    } } while (0)

    G_ISSUE(0); CP_COMMIT();
    G_ISSUE(1); CP_COMMIT();
    G_ISSUE(2); CP_COMMIT();

    for (int c = 0; c < nch; c++) {
        CP_WAIT(2);
        __syncthreads();
        const uint32_t base = sb + (c % 3) * GSTAGE_B;
#pragma unroll
        for (int ks = 0; ks < 2; ks++) {
            const uint32_t ko = ks * 32;
            uint32_t ah[2][4], al[2][4];
#pragma unroll
            for (int mt = 0; mt < 2; mt++) {
                LDSM4(ah[mt], base + offA + mt * 1280 + ko);
                LDSM4(al[mt], base + ABUF_B + offA + mt * 1280 + ko);
            }
#pragma unroll
            for (int jp = 0; jp < 4; jp++) {
                uint32_t bh4[4], bl4[4];
                LDSM4(bh4, base + 2 * ABUF_B + offB + jp * 1280 + ko);
                LDSM4(bl4, base + 2 * ABUF_B + BBUF_B + offB + jp * 1280 + ko);
#pragma unroll
                for (int mt = 0; mt < 2; mt++) {
                    MMA_BF2(d[mt][2 * jp], ah[mt], bh4[0], bh4[2]);
                    MMA_BF2(d[mt][2 * jp], ah[mt], bl4[0], bl4[2]);
                    MMA_BF2(d[mt][2 * jp], al[mt], bh4[0], bh4[2]);
                    MMA_BF2(d[mt][2 * jp + 1], ah[mt], bh4[1], bh4[3]);
                    MMA_BF2(d[mt][2 * jp + 1], ah[mt], bl4[1], bl4[3]);
                    MMA_BF2(d[mt][2 * jp + 1], al[mt], bh4[1], bh4[3]);
                }
            }
        }
        __syncthreads();
        if (c + 3 < nch) { G_ISSUE(c + 3); CP_COMMIT(); }
    }

    // epilogue
#pragma unroll
    for (int i = 0; i < 2; i++) {
        int r = m0 + wm + i * 16 + g;
#pragma unroll
        for (int j = 0; j < 8; j++) {
            int cix = n0 + wn + j * 8 + tg * 2;
            float2 b2 = *(const float2*)(bias + cix);
            float2 v0, v1;
            v0.x = d[i][j][0] + b2.x; v0.y = d[i][j][1] + b2.y;
            v1.x = d[i][j][2] + b2.x; v1.y = d[i][j][3] + b2.y;
            *(float2*)(C + (size_t)r * N + cix) = v0;
            *(float2*)(C + (size_t)(r + 8) * N + cix) = v1;
        }
    }
#undef G_ISSUE
}

// =================== bf16 flash attention (unchanged) ========================
#define APAD 136
#define QBUF_E (128 * APAD)
#define KVBUF_E (64 * APAD)
#define KVBUF_B (KVBUF_E * 2)
#define KVSTAGE_B (4 * KVBUF_B)
#define ATTN_SMEM (2 * QBUF_E * 2 + 2 * KVSTAGE_B)   // 208896 bytes

__global__ void __launch_bounds__(256, 1) attn_tc() {
    extern __shared__ bf16 sma[];
    bf16* Qh = sma;
    bf16* Ql = sma + QBUF_E;

    const int t = threadIdx.x;
    const int lane = t & 31, w = t >> 5;
    const int g = lane >> 2, tg = lane & 3;
    const int qt = gridDim.x - 1 - blockIdx.x;
    const int q0 = qt * 128;
    const int h = blockIdx.y, kvh = h >> 2;
    const int wq = w * 16;

    const uint32_t kvb = smem_u32(sma) + 2 * QBUF_E * 2;

#define A_ISSUE(kt) do { \
    uint32_t base = kvb + ((kt) & 1) * KVSTAGE_B; \
    _Pragma("unroll") \
    for (int i = 0; i < 4; i++) { \
        int u = t + (i << 8); int r = u >> 4, cc = u & 15; \
        size_t so = ((size_t)(((kt) << 6) + r) * NKV + kvh) * HD + cc * 8; \
        uint32_t dd = base + (uint32_t)(r * 272 + cc * 16); \
        CP16(dd, g_kh + so); \
        CP16(dd + KVBUF_B, g_kl + so); \
        CP16(dd + 2 * KVBUF_B, g_vh + so); \
        CP16(dd + 3 * KVBUF_B, g_vl + so); \
    } } while (0)

    A_ISSUE(0); CP_COMMIT();

#pragma unroll
    for (int i = 0; i < 8; i++) {
        int u = t + i * 256;
        int r = u >> 4, cc = u & 15;
        size_t qo = ((size_t)(q0 + r) * NH + h) * HD + cc * 8;
        *(uint4*)((char*)Qh + r * 272 + cc * 16) = *(const uint4*)(g_qh + qo);
        *(uint4*)((char*)Ql + r * 272 + cc * 16) = *(const uint4*)(g_ql + qo);
    }

    const int l15 = lane & 15, lh = lane >> 4;
    const uint32_t qb_h = smem_u32(Qh) + (wq + l15) * 272 + lh * 16;
    const uint32_t qb_l = qb_h + QBUF_E * 2;
    uint32_t kb[4];
#pragma unroll
    for (int jp = 0; jp < 4; jp++)
        kb[jp] = kvb + (jp * 16 + l15) * 272 + lh * 16;
    const uint32_t vb = kvb + 2 * KVBUF_B + l15 * 272 + lh * 16;

    float o[16][4];
#pragma unroll
    for (int dt = 0; dt < 16; dt++)
#pragma unroll
        for (int q = 0; q < 4; q++) o[dt][q] = 0.f;
    float mrow[2] = {-1e30f, -1e30f};
    float lrow[2] = {0.f, 0.f};

    const int nkt = 2 * (qt + 1);
    for (int kt = 0; kt < nkt; kt++) {
        CP_WAIT(0);
        __syncthreads();
        if (kt + 1 < nkt) { A_ISSUE(kt + 1); CP_COMMIT(); }
        const uint32_t kvo = (kt & 1) * KVSTAGE_B;
        const int k0 = kt * 64;

        float s[8][4];
#pragma unroll
        for (int j = 0; j < 8; j++)
#pragma unroll
            for (int q = 0; q < 4; q++) s[j][q] = 0.f;

#pragma unroll
        for (int ks = 0; ks < 8; ks++) {
            const uint32_t ko = ks * 32;
            uint32_t aqh[4], aql[4];
            LDSM4(aqh, qb_h + ko);
            LDSM4(aql, qb_l + ko);
#pragma unroll
            for (int jp = 0; jp < 4; jp++) {
                uint32_t kh4[4], kl4[4];
                LDSM4(kh4, kb[jp] + kvo + ko);
                LDSM4(kl4, kb[jp] + kvo + KVBUF_B + ko);
                MMA_BF2(s[2 * jp], aqh, kh4[0], kh4[2]);
                MMA_BF2(s[2 * jp], aqh, kl4[0], kl4[2]);
                MMA_BF2(s[2 * jp], aql, kh4[0], kh4[2]);
                MMA_BF2(s[2 * jp + 1], aqh, kh4[1], kh4[3]);
                MMA_BF2(s[2 * jp + 1], aqh, kl4[1], kl4[3]);
                MMA_BF2(s[2 * jp + 1], aql, kh4[1], kh4[3]);
            }
        }

        if (kt >= nkt - 2) {
            const int rbase = q0 + wq + g;
#pragma unroll
            for (int j = 0; j < 8; j++) {
                int cg = k0 + 8 * j + 2 * tg;
                if (cg > rbase) s[j][0] = -1e9f;
                if (cg + 1 > rbase) s[j][1] = -1e9f;
                if (cg > rbase + 8) s[j][2] = -1e9f;
                if (cg + 1 > rbase + 8) s[j][3] = -1e9f;
            }
        }

#pragma unroll
        for (int rr = 0; rr < 2; rr++) {
            float tmax = -1e30f;
#pragma unroll
            for (int j = 0; j < 8; j++)
                tmax = fmaxf(tmax, fmaxf(s[j][rr * 2], s[j][rr * 2 + 1]));
            tmax = fmaxf(tmax, __shfl_xor_sync(0xffffffffu, tmax, 1));
            tmax = fmaxf(tmax, __shfl_xor_sync(0xffffffffu, tmax, 2));
            float mnew = fmaxf(mrow[rr], tmax);
            float scalef = __expf(mrow[rr] - mnew);
            mrow[rr] = mnew;
            float tsum = 0.f;
#pragma unroll
            for (int j = 0; j < 8; j++) {
                float p0 = __expf(s[j][rr * 2] - mnew);
                float p1 = __expf(s[j][rr * 2 + 1] - mnew);
                s[j][rr * 2] = p0;
                s[j][rr * 2 + 1] = p1;
                tsum += p0 + p1;
            }
            tsum += __shfl_xor_sync(0xffffffffu, tsum, 1);
            tsum += __shfl_xor_sync(0xffffffffu, tsum, 2);
            lrow[rr] = lrow[rr] * scalef + tsum;
#pragma unroll
            for (int dt = 0; dt < 16; dt++) {
                o[dt][rr * 2] *= scalef;
                o[dt][rr * 2 + 1] *= scalef;
            }
        }

#pragma unroll
        for (int c = 0; c < 4; c++) {
            uint32_t pah[4], pal[4];
#pragma unroll
            for (int hq = 0; hq < 2; hq++) {
                float p0 = s[2 * c + hq][0], p1 = s[2 * c + hq][1];
                float p2 = s[2 * c + hq][2], p3 = s[2 * c + hq][3];
                float h0 = bfhi(p0), h1 = bfhi(p1), h2 = bfhi(p2), h3 = bfhi(p3);
                pah[hq * 2 + 0] = packbf(p0, p1);
                pah[hq * 2 + 1] = packbf(p2, p3);
                pal[hq * 2 + 0] = packbf(p0 - h0, p1 - h1);
                pal[hq * 2 + 1] = packbf(p2 - h2, p3 - h3);
            }
            const uint32_t vrow = vb + kvo + c * (16 * 272);
            uint32_t vh4[8][4];
#pragma unroll
            for (int dt16 = 0; dt16 < 8; dt16++) {
                LDSM4T(vh4[dt16], vrow + dt16 * 32);
                MMA_BF2(o[2 * dt16], pah, vh4[dt16][0], vh4[dt16][1]);
                MMA_BF2(o[2 * dt16 + 1], pah, vh4[dt16][2], vh4[dt16][3]);
            }
#pragma unroll
            for (int dt16 = 0; dt16 < 8; dt16++) {
                uint32_t vl4[4];
                LDSM4T(vl4, vrow + KVBUF_B + dt16 * 32);
                MMA_BF2(o[2 * dt16], pah, vl4[0], vl4[1]);
                MMA_BF2(o[2 * dt16 + 1], pah, vl4[2], vl4[3]);
            }
#pragma unroll
            for (int dt16 = 0; dt16 < 8; dt16++) {
                MMA_BF2(o[2 * dt16], pal, vh4[dt16][0], vh4[dt16][1]);
                MMA_BF2(o[2 * dt16 + 1], pal, vh4[dt16][2], vh4[dt16][3]);
            }
        }
    }

#pragma unroll
    for (int rr = 0; rr < 2; rr++) {
        float invl = 1.0f / lrow[rr];
        int row = q0 + wq + g + rr * 8;
#pragma unroll
        for (int dt = 0; dt < 16; dt++) {
            float x0 = o[dt][rr * 2] * invl;
            float x1 = o[dt][rr * 2 + 1] * invl;
            float h0 = bfhi(x0), h1 = bfhi(x1);
            size_t off = (size_t)row * (NH * HD) + h * HD + dt * 8 + 2 * tg;
            *(uint32_t*)(g_ah + off) = packbf(x0, x1);
            *(uint32_t*)(g_al + off) = packbf(x0 - h0, x1 - h1);
        }
    }
#undef A_ISSUE
}

// ---------------- launch -----------------------------------------------------
extern "C" void kernel_launch(void* const* d_in, const int* in_sizes, int n_in,
                              void* d_out, int out_size) {
    const float* hidden = (const float*)d_in[0];
    const float* cosb   = (const float*)d_in[1];
    const float* sinb   = (const float*)d_in[2];
    const float* kcache = (const float*)d_in[3];
    const float* vcache = (const float*)d_in[4];
    const float* wqkv   = (const float*)d_in[6];
    const float* bqkv   = (const float*)d_in[7];
    const float* wo     = (const float*)d_in[8];
    const float* bo     = (const float*)d_in[9];
    const float* qw     = (const float*)d_in[10];
    const float* kw     = (const float*)d_in[11];
    const int*   widx   = (const int*)d_in[12];
    float* out = (float*)d_out;

    float* p_qkv;
    bf16 *p_hidh, *p_hidl, *p_wqh, *p_wql, *p_woh, *p_wol, *p_ah, *p_al;
    cudaGetSymbolAddress((void**)&p_qkv, g_qkv);
    cudaGetSymbolAddress((void**)&p_hidh, g_hidh);
    cudaGetSymbolAddress((void**)&p_hidl, g_hidl);
    cudaGetSymbolAddress((void**)&p_wqh, g_wqh);
    cudaGetSymbolAddress((void**)&p_wql, g_wql);
    cudaGetSymbolAddress((void**)&p_woh, g_woh);
    cudaGetSymbolAddress((void**)&p_wol, g_wol);
    cudaGetSymbolAddress((void**)&p_ah, g_ah);
    cudaGetSymbolAddress((void**)&p_al, g_al);

    static bool attr_set = false;
    if (!attr_set) {
        cudaFuncSetAttribute(gemm_bf, cudaFuncAttributeMaxDynamicSharedMemorySize, G_SMEM);
        cudaFuncSetAttribute(attn_tc, cudaFuncAttributeMaxDynamicSharedMemorySize, ATTN_SMEM);
        attr_set = true;
    }

    split_bf16k<<<1024, 256>>>(hidden, p_hidh, p_hidl, S_LEN * HID / 4);
    split_bf16k<<<1024, 256>>>(wqkv, p_wqh, p_wql, QKV_OUT * HID / 4);
    split_bf16k<<<1024, 256>>>(wo, p_woh, p_wol, HID * HID / 4);

    // 1. QKV GEMM: grid (3072/256, 2048/128), 512 threads
    gemm_bf<<<dim3(QKV_OUT / 256, S_LEN / 128), 512, G_SMEM>>>(
        p_hidh, p_hidl, p_wqh, p_wql, bqkv, p_qkv, QKV_OUT, HID);

    copy_caches<<<256, 256>>>(kcache, vcache);

    norm_rope_scatter<<<dim3(S_LEN, 24), 128>>>(cosb, sinb, qw, kw, widx);

    attn_tc<<<dim3(S_LEN / 128, NH), 256, ATTN_SMEM>>>();

    // 5. O-proj: grid (2048/256, 2048/128)
    gemm_bf<<<dim3(HID / 256, S_LEN / 128), 512, G_SMEM>>>(
        p_ah, p_al, p_woh, p_wol, bo, out, HID, NH * HD);
}

// round 10
// speedup vs baseline: 1.4253x; 1.4253x over previous
#include <cuda_runtime.h>
#include <cuda_fp16.h>
#include <cstdint>
#include <math.h>

// Problem constants
#define S_LEN 2048
#define HID 2048
#define NH 16
#define NKV 4
#define HD 128
#define QKV_OUT 3072
#define Q_SZ 2048
#define KV_SZ 512
#define SCALE_Q 0.08838834764831845f

typedef __half f16;

// ---------------- scratch ----------------------------------------------------
__device__ float g_qkv[S_LEN * QKV_OUT];
__device__ f16 g_hidh[S_LEN * HID];
__device__ f16 g_wqh[QKV_OUT * HID], g_wql[QKV_OUT * HID];
__device__ f16 g_woh[HID * HID], g_wol[HID * HID];
__device__ f16 g_qh[S_LEN * NH * HD];
__device__ f16 g_kh[S_LEN * NKV * HD], g_kl[S_LEN * NKV * HD];
__device__ f16 g_vh[S_LEN * NKV * HD], g_vl[S_LEN * NKV * HD];
__device__ f16 g_ah[S_LEN * NH * HD];

// ---------------- helpers ----------------------------------------------------
__device__ __forceinline__ uint32_t smem_u32(const void* p) {
    return (uint32_t)__cvta_generic_to_shared(p);
}
__device__ __forceinline__ uint32_t packh(float lo_v, float hi_v) {
    uint32_t r;
    asm("cvt.rn.f16x2.f32 %0, %1, %2;" : "=r"(r) : "f"(hi_v), "f"(lo_v));
    return r;
}

#define MMA_H2(d, a, b0, b1) \
    asm volatile( \
        "mma.sync.aligned.m16n8k16.row.col.f32.f16.f16.f32 " \
        "{%0,%1,%2,%3}, {%4,%5,%6,%7}, {%8,%9}, {%0,%1,%2,%3};" \
        : "+f"((d)[0]), "+f"((d)[1]), "+f"((d)[2]), "+f"((d)[3]) \
        : "r"((a)[0]), "r"((a)[1]), "r"((a)[2]), "r"((a)[3]), \
          "r"(b0), "r"(b1))

#define LDSM4(r, addr) \
    asm volatile("ldmatrix.sync.aligned.m8n8.x4.shared.b16 {%0,%1,%2,%3}, [%4];" \
        : "=r"((r)[0]), "=r"((r)[1]), "=r"((r)[2]), "=r"((r)[3]) : "r"(addr))

#define LDSM4T(r, addr) \
    asm volatile("ldmatrix.sync.aligned.m8n8.x4.trans.shared.b16 {%0,%1,%2,%3}, [%4];" \
        : "=r"((r)[0]), "=r"((r)[1]), "=r"((r)[2]), "=r"((r)[3]) : "r"(addr))

#define CP16(dst, src) \
    asm volatile("cp.async.cg.shared.global [%0], [%1], 16;" :: "r"(dst), "l"(src))
#define CP_COMMIT() asm volatile("cp.async.commit_group;" ::: "memory")
#define CP_WAIT(n) asm volatile("cp.async.wait_group %0;" :: "n"(n) : "memory")

// ---------------- conversion kernels ----------------------------------------
__global__ void conv_h(const float* __restrict__ src, f16* __restrict__ hi, int n4) {
    __half2* H = (__half2*)hi;
    for (int i = blockIdx.x * blockDim.x + threadIdx.x; i < n4;
         i += gridDim.x * blockDim.x) {
        float4 v = ((const float4*)src)[i];
        H[2 * i] = __floats2half2_rn(v.x, v.y);
        H[2 * i + 1] = __floats2half2_rn(v.z, v.w);
    }
}

__global__ void split_h(const float* __restrict__ src, f16* __restrict__ hi,
                        f16* __restrict__ lo, int n4) {
    __half2* H = (__half2*)hi;
    __half2* L = (__half2*)lo;
    for (int i = blockIdx.x * blockDim.x + threadIdx.x; i < n4;
         i += gridDim.x * blockDim.x) {
        float4 v = ((const float4*)src)[i];
        f16 h0 = __float2half_rn(v.x), h1 = __float2half_rn(v.y);
        f16 h2 = __float2half_rn(v.z), h3 = __float2half_rn(v.w);
        H[2 * i] = __halves2half2(h0, h1);
        H[2 * i + 1] = __halves2half2(h2, h3);
        L[2 * i] = __floats2half2_rn(v.x - __half2float(h0), v.y - __half2float(h1));
        L[2 * i + 1] = __floats2half2_rn(v.z - __half2float(h2), v.w - __half2float(h3));
    }
}

__global__ void copy_caches(const float* __restrict__ kc, const float* __restrict__ vc) {
    int n = S_LEN * NKV * HD;
    for (int i = blockIdx.x * blockDim.x + threadIdx.x; i < n;
         i += gridDim.x * blockDim.x) {
        float k = kc[i], v = vc[i];
        f16 kh = __float2half_rn(k), vh = __float2half_rn(v);
        g_kh[i] = kh; g_kl[i] = __float2half_rn(k - __half2float(kh));
        g_vh[i] = vh; g_vl[i] = __float2half_rn(v - __half2float(vh));
    }
}

// ---------------- fused RMSNorm + RoPE + scale + scatter ---------------------
__global__ void norm_rope_scatter(const float* __restrict__ cosb,
                                  const float* __restrict__ sinb,
                                  const float* __restrict__ qw,
                                  const float* __restrict__ kw,
                                  const int* __restrict__ widx) {
    const int s = blockIdx.x;
    const int head = blockIdx.y;
    const int d = threadIdx.x;
    __shared__ float sh[128];
    __shared__ float wsum[4];

    int col;
    if (head < 16)      col = head * HD + d;
    else if (head < 20) col = Q_SZ + (head - 16) * HD + d;
    else                col = Q_SZ + KV_SZ + (head - 20) * HD + d;

    float x = g_qkv[(size_t)s * QKV_OUT + col];

    if (head >= 20) {
        size_t o = ((size_t)widx[s] * NKV + (head - 20)) * HD + d;
        f16 h = __float2half_rn(x);
        g_vh[o] = h;
        g_vl[o] = __float2half_rn(x - __half2float(h));
        return;
    }

    float sq = x * x;
#pragma unroll
    for (int m = 16; m; m >>= 1) sq += __shfl_xor_sync(0xffffffffu, sq, m);
    if ((d & 31) == 0) wsum[d >> 5] = sq;
    __syncthreads();
    float ms = (wsum[0] + wsum[1] + wsum[2] + wsum[3]) * (1.0f / 128.0f);
    float inv = rsqrtf(ms + 1e-6f);
    const float* w = (head < 16) ? qw : kw;
    float y = x * inv * w[d];
    sh[d] = y;
    __syncthreads();

    if (d < 64) {
        float c = cosb[s * 64 + d], sn = sinb[s * 64 + d];
        float x1 = sh[d], x2 = sh[d + 64];
        float y1 = x1 * c - x2 * sn;
        float y2 = x1 * sn + x2 * c;
        if (head < 16) {
            y1 *= SCALE_Q; y2 *= SCALE_Q;
            size_t o = ((size_t)s * NH + head) * HD;
            g_qh[o + d] = __float2half_rn(y1);
            g_qh[o + d + 64] = __float2half_rn(y2);
        } else {
            size_t o = ((size_t)widx[s] * NKV + (head - 16)) * HD;
            f16 h1 = __float2half_rn(y1), h2 = __float2half_rn(y2);
            g_kh[o + d] = h1;
            g_kl[o + d] = __float2half_rn(y1 - __half2float(h1));
            g_kh[o + d + 64] = h2;
            g_kl[o + d + 64] = __float2half_rn(y2 - __half2float(h2));
        }
    }
}

// =================== fp16 2-term GEMM ========================================
// C[M,N] = Ah[M,K] @ (Bh+Bl)[N,K]^T + bias[N].
// CTA 128x128, 256 thr (8 warps 4x2), warp 32x64, k-chunk 32, 4-stage cp.async.
#define GSTRIDE 40
#define GB_E (128 * GSTRIDE)              // 5120 elems
#define GB_B (GB_E * 2)                   // 10240 bytes
#define GSTAGE_B (3 * GB_B)               // 30720 bytes
#define G_SMEM (4 * GSTAGE_B)             // 122880 bytes

__global__ void __launch_bounds__(256)
gemm_h(const f16* __restrict__ Ah_g, const f16* __restrict__ Bh_g,
       const f16* __restrict__ Bl_g, const float* __restrict__ bias,
       float* __restrict__ C, int N, int K) {
    extern __shared__ f16 smg[];
    const int t = threadIdx.x;
    const int lane = t & 31, wid = t >> 5;
    const int g = lane >> 2, tg = lane & 3;
    const int wm = (wid & 3) * 32, wn = (wid >> 2) * 64;
    const int m0 = blockIdx.y << 7, n0 = blockIdx.x << 7;
    const int nch = K >> 5;

    const int l15 = lane & 15, lh = lane >> 4;
    const uint32_t sb = smem_u32(smg);
    const uint32_t offA = (uint32_t)((wm + l15) * 80 + lh * 16);
    const uint32_t offB = (uint32_t)((wn + l15) * 80 + lh * 16);

    float d[2][8][4];
#pragma unroll
    for (int i = 0; i < 2; i++)
#pragma unroll
        for (int j = 0; j < 8; j++)
#pragma unroll
            for (int q = 0; q < 4; q++) d[i][j][q] = 0.f;

#define G_ISSUE(c) do { \
    uint32_t base = sb + ((c) & 3) * GSTAGE_B; \
    _Pragma("unroll") \
    for (int j = 0; j < 2; j++) { \
        int u = t + (j << 8); int row = u >> 2, q = u & 3; \
        uint32_t dst = base + (uint32_t)(row * GSTRIDE + (q << 3)) * 2; \
        size_t ao = (size_t)(m0 + row) * K + ((c) << 5) + (q << 3); \
        size_t bo = (size_t)(n0 + row) * K + ((c) << 5) + (q << 3); \
        CP16(dst, Ah_g + ao); \
        CP16(dst + GB_B, Bh_g + bo); \
        CP16(dst + 2 * GB_B, Bl_g + bo); \
    } } while (0)

    G_ISSUE(0); CP_COMMIT();
    G_ISSUE(1); CP_COMMIT();
    G_ISSUE(2); CP_COMMIT();

    for (int c = 0; c < nch; c++) {
        CP_WAIT(2);
        __syncthreads();
        const uint32_t base = sb + (c & 3) * GSTAGE_B;
#pragma unroll
        for (int ks = 0; ks < 2; ks++) {
            const uint32_t ko = ks * 32;
            uint32_t ah[2][4];
#pragma unroll
            for (int mt = 0; mt < 2; mt++)
                LDSM4(ah[mt], base + offA + mt * 1280 + ko);
#pragma unroll
            for (int jp = 0; jp < 4; jp++) {
                uint32_t bh4[4], bl4[4];
                LDSM4(bh4, base + GB_B + offB + jp * 1280 + ko);
                LDSM4(bl4, base + 2 * GB_B + offB + jp * 1280 + ko);
#pragma unroll
                for (int mt = 0; mt < 2; mt++) {
                    MMA_H2(d[mt][2 * jp], ah[mt], bh4[0], bh4[2]);
                    MMA_H2(d[mt][2 * jp], ah[mt], bl4[0], bl4[2]);
                    MMA_H2(d[mt][2 * jp + 1], ah[mt], bh4[1], bh4[3]);
                    MMA_H2(d[mt][2 * jp + 1], ah[mt], bl4[1], bl4[3]);
                }
            }
        }
        __syncthreads();
        if (c + 3 < nch) { G_ISSUE(c + 3); CP_COMMIT(); }
    }

    // epilogue
#pragma unroll
    for (int i = 0; i < 2; i++) {
        int r = m0 + wm + i * 16 + g;
#pragma unroll
        for (int j = 0; j < 8; j++) {
            int cix = n0 + wn + j * 8 + tg * 2;
            float2 b2 = *(const float2*)(bias + cix);
            float2 v0, v1;
            v0.x = d[i][j][0] + b2.x; v0.y = d[i][j][1] + b2.y;
            v1.x = d[i][j][2] + b2.x; v1.y = d[i][j][3] + b2.y;
            *(float2*)(C + (size_t)r * N + cix) = v0;
            *(float2*)(C + (size_t)(r + 8) * N + cix) = v1;
        }
    }
#undef G_ISSUE
}

// =================== fp16 2-term flash attention =============================
// 256 threads (8 warps), CTA = 128 q rows of one head; warp w owns rows
// [16w,16w+16). k-tiles of 64 keys, cp.async double-buffered.
// scores = Qh·(Kh+Kl); PV = Ph·(Vh+Vl).
#define APAD 136
#define QBUF_E (128 * APAD)               // 17408 elems (34816 B)
#define KVBUF_E (64 * APAD)
#define KVBUF_B (KVBUF_E * 2)             // 17408 B
#define KVSTAGE_B (4 * KVBUF_B)           // 69632 B
#define ATTN_SMEM (QBUF_E * 2 + 2 * KVSTAGE_B)   // 174080 B

__global__ void __launch_bounds__(256, 1) attn_tc() {
    extern __shared__ f16 sma[];
    f16* Qh = sma;

    const int t = threadIdx.x;
    const int lane = t & 31, w = t >> 5;
    const int g = lane >> 2, tg = lane & 3;
    const int qt = gridDim.x - 1 - blockIdx.x;
    const int q0 = qt * 128;
    const int h = blockIdx.y, kvh = h >> 2;
    const int wq = w * 16;

    const uint32_t kvb = smem_u32(sma) + QBUF_E * 2;

#define A_ISSUE(kt) do { \
    uint32_t base = kvb + ((kt) & 1) * KVSTAGE_B; \
    _Pragma("unroll") \
    for (int i = 0; i < 4; i++) { \
        int u = t + (i << 8); int r = u >> 4, cc = u & 15; \
        size_t so = ((size_t)(((kt) << 6) + r) * NKV + kvh) * HD + cc * 8; \
        uint32_t dd = base + (uint32_t)(r * 272 + cc * 16); \
        CP16(dd, g_kh + so); \
        CP16(dd + KVBUF_B, g_kl + so); \
        CP16(dd + 2 * KVBUF_B, g_vh + so); \
        CP16(dd + 3 * KVBUF_B, g_vl + so); \
    } } while (0)

    A_ISSUE(0); CP_COMMIT();

    // stage Q (hi only)
#pragma unroll
    for (int i = 0; i < 8; i++) {
        int u = t + i * 256;
        int r = u >> 4, cc = u & 15;
        size_t qo = ((size_t)(q0 + r) * NH + h) * HD + cc * 8;
        *(uint4*)((char*)Qh + r * 272 + cc * 16) = *(const uint4*)(g_qh + qo);
    }

    const int l15 = lane & 15, lh = lane >> 4;
    const uint32_t qb_h = smem_u32(Qh) + (wq + l15) * 272 + lh * 16;
    uint32_t kb[4];
#pragma unroll
    for (int jp = 0; jp < 4; jp++)
        kb[jp] = kvb + (jp * 16 + l15) * 272 + lh * 16;
    const uint32_t vb = kvb + 2 * KVBUF_B + l15 * 272 + lh * 16;

    float o[16][4];
#pragma unroll
    for (int dt = 0; dt < 16; dt++)
#pragma unroll
        for (int q = 0; q < 4; q++) o[dt][q] = 0.f;
    float mrow[2] = {-1e30f, -1e30f};
    float lrow[2] = {0.f, 0.f};

    const int nkt = 2 * (qt + 1);
    for (int kt = 0; kt < nkt; kt++) {
        CP_WAIT(0);
        __syncthreads();
        if (kt + 1 < nkt) { A_ISSUE(kt + 1); CP_COMMIT(); }
        const uint32_t kvo = (kt & 1) * KVSTAGE_B;
        const int k0 = kt * 64;

        // ---- scores ----
        float s[8][4];
#pragma unroll
        for (int j = 0; j < 8; j++)
#pragma unroll
            for (int q = 0; q < 4; q++) s[j][q] = 0.f;

#pragma unroll
        for (int ks = 0; ks < 8; ks++) {
            const uint32_t ko = ks * 32;
            uint32_t aqh[4];
            LDSM4(aqh, qb_h + ko);
#pragma unroll
            for (int jp = 0; jp < 4; jp++) {
                uint32_t kh4[4], kl4[4];
                LDSM4(kh4, kb[jp] + kvo + ko);
                LDSM4(kl4, kb[jp] + kvo + KVBUF_B + ko);
                MMA_H2(s[2 * jp], aqh, kh4[0], kh4[2]);
                MMA_H2(s[2 * jp], aqh, kl4[0], kl4[2]);
                MMA_H2(s[2 * jp + 1], aqh, kh4[1], kh4[3]);
                MMA_H2(s[2 * jp + 1], aqh, kl4[1], kl4[3]);
            }
        }

        // ---- causal mask (last two tiles only) ----
        if (kt >= nkt - 2) {
            const int rbase = q0 + wq + g;
#pragma unroll
            for (int j = 0; j < 8; j++) {
                int cg = k0 + 8 * j + 2 * tg;
                if (cg > rbase) s[j][0] = -1e9f;
                if (cg + 1 > rbase) s[j][1] = -1e9f;
                if (cg > rbase + 8) s[j][2] = -1e9f;
                if (cg + 1 > rbase + 8) s[j][3] = -1e9f;
            }
        }

        // ---- online softmax ----
#pragma unroll
        for (int rr = 0; rr < 2; rr++) {
            float tmax = -1e30f;
#pragma unroll
            for (int j = 0; j < 8; j++)
                tmax = fmaxf(tmax, fmaxf(s[j][rr * 2], s[j][rr * 2 + 1]));
            tmax = fmaxf(tmax, __shfl_xor_sync(0xffffffffu, tmax, 1));
            tmax = fmaxf(tmax, __shfl_xor_sync(0xffffffffu, tmax, 2));
            float mnew = fmaxf(mrow[rr], tmax);
            float scalef = __expf(mrow[rr] - mnew);
            mrow[rr] = mnew;
            float tsum = 0.f;
#pragma unroll
            for (int j = 0; j < 8; j++) {
                float p0 = __expf(s[j][rr * 2] - mnew);
                float p1 = __expf(s[j][rr * 2 + 1] - mnew);
                s[j][rr * 2] = p0;
                s[j][rr * 2 + 1] = p1;
                tsum += p0 + p1;
            }
            tsum += __shfl_xor_sync(0xffffffffu, tsum, 1);
            tsum += __shfl_xor_sync(0xffffffffu, tsum, 2);
            lrow[rr] = lrow[rr] * scalef + tsum;
#pragma unroll
            for (int dt = 0; dt < 16; dt++) {
                o[dt][rr * 2] *= scalef;
                o[dt][rr * 2 + 1] *= scalef;
            }
        }

        // ---- PV: P hi-only fragments; V hi+lo via ldmatrix.trans ----
#pragma unroll
        for (int c = 0; c < 4; c++) {
            uint32_t pah[4];
#pragma unroll
            for (int hq = 0; hq < 2; hq++) {
                pah[hq * 2 + 0] = packh(s[2 * c + hq][0], s[2 * c + hq][1]);
                pah[hq * 2 + 1] = packh(s[2 * c + hq][2], s[2 * c + hq][3]);
            }
            const uint32_t vrow = vb + kvo + c * (16 * 272);
#pragma unroll
            for (int dt16 = 0; dt16 < 8; dt16++) {
                uint32_t vh4[4], vl4[4];
                LDSM4T(vh4, vrow + dt16 * 32);
                LDSM4T(vl4, vrow + KVBUF_B + dt16 * 32);
                MMA_H2(o[2 * dt16], pah, vh4[0], vh4[1]);
                MMA_H2(o[2 * dt16], pah, vl4[0], vl4[1]);
                MMA_H2(o[2 * dt16 + 1], pah, vh4[2], vh4[3]);
                MMA_H2(o[2 * dt16 + 1], pah, vl4[2], vl4[3]);
            }
        }
    }

    // ---- epilogue: normalize, store fp16 hi ----
#pragma unroll
    for (int rr = 0; rr < 2; rr++) {
        float invl = 1.0f / lrow[rr];
        int row = q0 + wq + g + rr * 8;
#pragma unroll
        for (int dt = 0; dt < 16; dt++) {
            float x0 = o[dt][rr * 2] * invl;
            float x1 = o[dt][rr * 2 + 1] * invl;
            size_t off = (size_t)row * (NH * HD) + h * HD + dt * 8 + 2 * tg;
            *(uint32_t*)(g_ah + off) = packh(x0, x1);
        }
    }
#undef A_ISSUE
}

// ---------------- launch -----------------------------------------------------
extern "C" void kernel_launch(void* const* d_in, const int* in_sizes, int n_in,
                              void* d_out, int out_size) {
    const float* hidden = (const float*)d_in[0];
    const float* cosb   = (const float*)d_in[1];
    const float* sinb   = (const float*)d_in[2];
    const float* kcache = (const float*)d_in[3];
    const float* vcache = (const float*)d_in[4];
    const float* wqkv   = (const float*)d_in[6];
    const float* bqkv   = (const float*)d_in[7];
    const float* wo     = (const float*)d_in[8];
    const float* bo     = (const float*)d_in[9];
    const float* qw     = (const float*)d_in[10];
    const float* kw     = (const float*)d_in[11];
    const int*   widx   = (const int*)d_in[12];
    float* out = (float*)d_out;

    float* p_qkv;
    f16 *p_hidh, *p_wqh, *p_wql, *p_woh, *p_wol, *p_ah;
    cudaGetSymbolAddress((void**)&p_qkv, g_qkv);
    cudaGetSymbolAddress((void**)&p_hidh, g_hidh);
    cudaGetSymbolAddress((void**)&p_wqh, g_wqh);
    cudaGetSymbolAddress((void**)&p_wql, g_wql);
    cudaGetSymbolAddress((void**)&p_woh, g_woh);
    cudaGetSymbolAddress((void**)&p_wol, g_wol);
    cudaGetSymbolAddress((void**)&p_ah, g_ah);

    static bool attr_set = false;
    if (!attr_set) {
        cudaFuncSetAttribute(gemm_h, cudaFuncAttributeMaxDynamicSharedMemorySize, G_SMEM);
        cudaFuncSetAttribute(attn_tc, cudaFuncAttributeMaxDynamicSharedMemorySize, ATTN_SMEM);
        attr_set = true;
    }

    // 0. convert inputs
    conv_h<<<1024, 256>>>(hidden, p_hidh, S_LEN * HID / 4);
    split_h<<<1024, 256>>>(wqkv, p_wqh, p_wql, QKV_OUT * HID / 4);
    split_h<<<1024, 256>>>(wo, p_woh, p_wol, HID * HID / 4);

    // 1. QKV GEMM (fp16 2-term)
    gemm_h<<<dim3(QKV_OUT / 128, S_LEN / 128), 256, G_SMEM>>>(
        p_hidh, p_wqh, p_wql, bqkv, p_qkv, QKV_OUT, HID);

    // 2. caches -> split scratch
    copy_caches<<<256, 256>>>(kcache, vcache);

    // 3. RMSNorm + RoPE + scale + scatter
    norm_rope_scatter<<<dim3(S_LEN, 24), 128>>>(cosb, sinb, qw, kw, widx);

    // 4. fp16 flash attention
    attn_tc<<<dim3(S_LEN / 128, NH), 256, ATTN_SMEM>>>();

    // 5. output projection (fp16 2-term)
    gemm_h<<<dim3(HID / 128, S_LEN / 128), 256, G_SMEM>>>(
        p_ah, p_woh, p_wol, bo, out, HID, NH * HD);
}

// round 11
// speedup vs baseline: 2.0892x; 1.4658x over previous
#include <cuda_runtime.h>
#include <cuda_fp16.h>
#include <cstdint>
#include <math.h>

// Problem constants
#define S_LEN 2048
#define HID 2048
#define NH 16
#define NKV 4
#define HD 128
#define QKV_OUT 3072
#define Q_SZ 2048
#define KV_SZ 512
#define SCALE_Q 0.08838834764831845f

typedef __half f16;

// ---------------- scratch ----------------------------------------------------
__device__ float g_qkv[S_LEN * QKV_OUT];
__device__ f16 g_hidh[S_LEN * HID];
__device__ f16 g_wqh[QKV_OUT * HID];
__device__ f16 g_woh[HID * HID];
__device__ f16 g_qh[S_LEN * NH * HD];
__device__ f16 g_kh[S_LEN * NKV * HD], g_kl[S_LEN * NKV * HD];
__device__ f16 g_vh[S_LEN * NKV * HD];
__device__ f16 g_ah[S_LEN * NH * HD];

// ---------------- helpers ----------------------------------------------------
__device__ __forceinline__ uint32_t smem_u32(const void* p) {
    return (uint32_t)__cvta_generic_to_shared(p);
}
__device__ __forceinline__ uint32_t packh(float lo_v, float hi_v) {
    uint32_t r;
    asm("cvt.rn.f16x2.f32 %0, %1, %2;" : "=r"(r) : "f"(hi_v), "f"(lo_v));
    return r;
}

#define MMA_H2(d, a, b0, b1) \
    asm volatile( \
        "mma.sync.aligned.m16n8k16.row.col.f32.f16.f16.f32 " \
        "{%0,%1,%2,%3}, {%4,%5,%6,%7}, {%8,%9}, {%0,%1,%2,%3};" \
        : "+f"((d)[0]), "+f"((d)[1]), "+f"((d)[2]), "+f"((d)[3]) \
        : "r"((a)[0]), "r"((a)[1]), "r"((a)[2]), "r"((a)[3]), \
          "r"(b0), "r"(b1))

#define LDSM4(r, addr) \
    asm volatile("ldmatrix.sync.aligned.m8n8.x4.shared.b16 {%0,%1,%2,%3}, [%4];" \
        : "=r"((r)[0]), "=r"((r)[1]), "=r"((r)[2]), "=r"((r)[3]) : "r"(addr))

#define LDSM4T(r, addr) \
    asm volatile("ldmatrix.sync.aligned.m8n8.x4.trans.shared.b16 {%0,%1,%2,%3}, [%4];" \
        : "=r"((r)[0]), "=r"((r)[1]), "=r"((r)[2]), "=r"((r)[3]) : "r"(addr))

#define CP16(dst, src) \
    asm volatile("cp.async.cg.shared.global [%0], [%1], 16;" :: "r"(dst), "l"(src))
#define CP_COMMIT() asm volatile("cp.async.commit_group;" ::: "memory")
#define CP_WAIT(n) asm volatile("cp.async.wait_group %0;" :: "n"(n) : "memory")

// ---------------- conversion kernels ----------------------------------------
__global__ void conv_h(const float* __restrict__ src, f16* __restrict__ hi, int n4) {
    __half2* H = (__half2*)hi;
    for (int i = blockIdx.x * blockDim.x + threadIdx.x; i < n4;
         i += gridDim.x * blockDim.x) {
        float4 v = ((const float4*)src)[i];
        H[2 * i] = __floats2half2_rn(v.x, v.y);
        H[2 * i + 1] = __floats2half2_rn(v.z, v.w);
    }
}

__global__ void copy_caches(const float* __restrict__ kc, const float* __restrict__ vc) {
    int n = S_LEN * NKV * HD;
    for (int i = blockIdx.x * blockDim.x + threadIdx.x; i < n;
         i += gridDim.x * blockDim.x) {
        float k = kc[i];
        f16 kh = __float2half_rn(k);
        g_kh[i] = kh;
        g_kl[i] = __float2half_rn(k - __half2float(kh));
        g_vh[i] = __float2half_rn(vc[i]);
    }
}

// ---------------- fused RMSNorm + RoPE + scale + scatter ---------------------
__global__ void norm_rope_scatter(const float* __restrict__ cosb,
                                  const float* __restrict__ sinb,
                                  const float* __restrict__ qw,
                                  const float* __restrict__ kw,
                                  const int* __restrict__ widx) {
    const int s = blockIdx.x;
    const int head = blockIdx.y;
    const int d = threadIdx.x;
    __shared__ float sh[128];
    __shared__ float wsum[4];

    int col;
    if (head < 16)      col = head * HD + d;
    else if (head < 20) col = Q_SZ + (head - 16) * HD + d;
    else                col = Q_SZ + KV_SZ + (head - 20) * HD + d;

    float x = g_qkv[(size_t)s * QKV_OUT + col];

    if (head >= 20) {
        size_t o = ((size_t)widx[s] * NKV + (head - 20)) * HD + d;
        g_vh[o] = __float2half_rn(x);
        return;
    }

    float sq = x * x;
#pragma unroll
    for (int m = 16; m; m >>= 1) sq += __shfl_xor_sync(0xffffffffu, sq, m);
    if ((d & 31) == 0) wsum[d >> 5] = sq;
    __syncthreads();
    float ms = (wsum[0] + wsum[1] + wsum[2] + wsum[3]) * (1.0f / 128.0f);
    float inv = rsqrtf(ms + 1e-6f);
    const float* w = (head < 16) ? qw : kw;
    float y = x * inv * w[d];
    sh[d] = y;
    __syncthreads();

    if (d < 64) {
        float c = cosb[s * 64 + d], sn = sinb[s * 64 + d];
        float x1 = sh[d], x2 = sh[d + 64];
        float y1 = x1 * c - x2 * sn;
        float y2 = x1 * sn + x2 * c;
        if (head < 16) {
            y1 *= SCALE_Q; y2 *= SCALE_Q;
            size_t o = ((size_t)s * NH + head) * HD;
            g_qh[o + d] = __float2half_rn(y1);
            g_qh[o + d + 64] = __float2half_rn(y2);
        } else {
            size_t o = ((size_t)widx[s] * NKV + (head - 16)) * HD;
            f16 h1 = __float2half_rn(y1), h2 = __float2half_rn(y2);
            g_kh[o + d] = h1;
            g_kl[o + d] = __float2half_rn(y1 - __half2float(h1));
            g_kh[o + d + 64] = h2;
            g_kl[o + d + 64] = __float2half_rn(y2 - __half2float(h2));
        }
    }
}

// =================== pure fp16 GEMM ==========================================
// C[M,N] = Ah[M,K] @ Bh[N,K]^T + bias[N].
// CTA 128x128, 256 thr (8 warps 4x2), warp 32x64, k-chunk 32, 4-stage cp.async.
#define GSTRIDE 40
#define GB_E (128 * GSTRIDE)              // 5120 elems
#define GB_B (GB_E * 2)                   // 10240 bytes
#define GSTAGE_B (2 * GB_B)               // 20480 bytes
#define G_SMEM (4 * GSTAGE_B)             // 81920 bytes

__global__ void __launch_bounds__(256)
gemm_h(const f16* __restrict__ Ah_g, const f16* __restrict__ Bh_g,
       const float* __restrict__ bias, float* __restrict__ C, int N, int K) {
    extern __shared__ f16 smg[];
    const int t = threadIdx.x;
    const int lane = t & 31, wid = t >> 5;
    const int g = lane >> 2, tg = lane & 3;
    const int wm = (wid & 3) * 32, wn = (wid >> 2) * 64;
    const int m0 = blockIdx.y << 7, n0 = blockIdx.x << 7;
    const int nch = K >> 5;

    const int l15 = lane & 15, lh = lane >> 4;
    const uint32_t sb = smem_u32(smg);
    const uint32_t offA = (uint32_t)((wm + l15) * 80 + lh * 16);
    const uint32_t offB = (uint32_t)((wn + l15) * 80 + lh * 16);

    float d[2][8][4];
#pragma unroll
    for (int i = 0; i < 2; i++)
#pragma unroll
        for (int j = 0; j < 8; j++)
#pragma unroll
            for (int q = 0; q < 4; q++) d[i][j][q] = 0.f;

#define G_ISSUE(c) do { \
    uint32_t base = sb + ((c) & 3) * GSTAGE_B; \
    _Pragma("unroll") \
    for (int j = 0; j < 2; j++) { \
        int u = t + (j << 8); int row = u >> 2, q = u & 3; \
        uint32_t dst = base + (uint32_t)(row * GSTRIDE + (q << 3)) * 2; \
        size_t ao = (size_t)(m0 + row) * K + ((c) << 5) + (q << 3); \
        size_t bo = (size_t)(n0 + row) * K + ((c) << 5) + (q << 3); \
        CP16(dst, Ah_g + ao); \
        CP16(dst + GB_B, Bh_g + bo); \
    } } while (0)

    G_ISSUE(0); CP_COMMIT();
    G_ISSUE(1); CP_COMMIT();
    G_ISSUE(2); CP_COMMIT();

    for (int c = 0; c < nch; c++) {
        CP_WAIT(2);
        __syncthreads();
        const uint32_t base = sb + (c & 3) * GSTAGE_B;
#pragma unroll
        for (int ks = 0; ks < 2; ks++) {
            const uint32_t ko = ks * 32;
            uint32_t ah[2][4];
#pragma unroll
            for (int mt = 0; mt < 2; mt++)
                LDSM4(ah[mt], base + offA + mt * 1280 + ko);
#pragma unroll
            for (int jp = 0; jp < 4; jp++) {
                uint32_t bh4[4];
                LDSM4(bh4, base + GB_B + offB + jp * 1280 + ko);
#pragma unroll
                for (int mt = 0; mt < 2; mt++) {
                    MMA_H2(d[mt][2 * jp], ah[mt], bh4[0], bh4[2]);
                    MMA_H2(d[mt][2 * jp + 1], ah[mt], bh4[1], bh4[3]);
                }
            }
        }
        __syncthreads();
        if (c + 3 < nch) { G_ISSUE(c + 3); CP_COMMIT(); }
    }

    // epilogue
#pragma unroll
    for (int i = 0; i < 2; i++) {
        int r = m0 + wm + i * 16 + g;
#pragma unroll
        for (int j = 0; j < 8; j++) {
            int cix = n0 + wn + j * 8 + tg * 2;
            float2 b2 = *(const float2*)(bias + cix);
            float2 v0, v1;
            v0.x = d[i][j][0] + b2.x; v0.y = d[i][j][1] + b2.y;
            v1.x = d[i][j][2] + b2.x; v1.y = d[i][j][3] + b2.y;
            *(float2*)(C + (size_t)r * N + cix) = v0;
            *(float2*)(C + (size_t)(r + 8) * N + cix) = v1;
        }
    }
#undef G_ISSUE
}

// =================== fp16 flash attention ====================================
// 256 threads (8 warps), CTA = 128 q rows of one head; warp w owns rows
// [16w,16w+16). k-tiles of 64 keys, cp.async double-buffered.
// scores = Qh·(Kh+Kl)  [K 2-term: sensitive path];  PV = Ph·Vh  [1-term].
#define APAD 136
#define QBUF_E (128 * APAD)               // 17408 elems (34816 B)
#define KVBUF_E (64 * APAD)
#define KVBUF_B (KVBUF_E * 2)             // 17408 B
#define KVSTAGE_B (3 * KVBUF_B)           // 52224 B (Kh, Kl, Vh)
#define ATTN_SMEM (QBUF_E * 2 + 2 * KVSTAGE_B)   // 139264 B

__global__ void __launch_bounds__(256, 1) attn_tc() {
    extern __shared__ f16 sma[];
    f16* Qh = sma;

    const int t = threadIdx.x;
    const int lane = t & 31, w = t >> 5;
    const int g = lane >> 2, tg = lane & 3;
    const int qt = gridDim.x - 1 - blockIdx.x;
    const int q0 = qt * 128;
    const int h = blockIdx.y, kvh = h >> 2;
    const int wq = w * 16;

    const uint32_t kvb = smem_u32(sma) + QBUF_E * 2;

#define A_ISSUE(kt) do { \
    uint32_t base = kvb + ((kt) & 1) * KVSTAGE_B; \
    _Pragma("unroll") \
    for (int i = 0; i < 4; i++) { \
        int u = t + (i << 8); int r = u >> 4, cc = u & 15; \
        size_t so = ((size_t)(((kt) << 6) + r) * NKV + kvh) * HD + cc * 8; \
        uint32_t dd = base + (uint32_t)(r * 272 + cc * 16); \
        CP16(dd, g_kh + so); \
        CP16(dd + KVBUF_B, g_kl + so); \
        CP16(dd + 2 * KVBUF_B, g_vh + so); \
    } } while (0)

    A_ISSUE(0); CP_COMMIT();

    // stage Q (hi only)
#pragma unroll
    for (int i = 0; i < 8; i++) {
        int u = t + i * 256;
        int r = u >> 4, cc = u & 15;
        size_t qo = ((size_t)(q0 + r) * NH + h) * HD + cc * 8;
        *(uint4*)((char*)Qh + r * 272 + cc * 16) = *(const uint4*)(g_qh + qo);
    }

    const int l15 = lane & 15, lh = lane >> 4;
    const uint32_t qb_h = smem_u32(Qh) + (wq + l15) * 272 + lh * 16;
    uint32_t kb[4];
#pragma unroll
    for (int jp = 0; jp < 4; jp++)
        kb[jp] = kvb + (jp * 16 + l15) * 272 + lh * 16;
    const uint32_t vb = kvb + 2 * KVBUF_B + l15 * 272 + lh * 16;

    float o[16][4];
#pragma unroll
    for (int dt = 0; dt < 16; dt++)
#pragma unroll
        for (int q = 0; q < 4; q++) o[dt][q] = 0.f;
    float mrow[2] = {-1e30f, -1e30f};
    float lrow[2] = {0.f, 0.f};

    const int nkt = 2 * (qt + 1);
    for (int kt = 0; kt < nkt; kt++) {
        CP_WAIT(0);
        __syncthreads();
        if (kt + 1 < nkt) { A_ISSUE(kt + 1); CP_COMMIT(); }
        const uint32_t kvo = (kt & 1) * KVSTAGE_B;
        const int k0 = kt * 64;

        // ---- scores: Qh x (Kh + Kl) ----
        float s[8][4];
#pragma unroll
        for (int j = 0; j < 8; j++)
#pragma unroll
            for (int q = 0; q < 4; q++) s[j][q] = 0.f;

#pragma unroll
        for (int ks = 0; ks < 8; ks++) {
            const uint32_t ko = ks * 32;
            uint32_t aqh[4];
            LDSM4(aqh, qb_h + ko);
#pragma unroll
            for (int jp = 0; jp < 4; jp++) {
                uint32_t kh4[4], kl4[4];
                LDSM4(kh4, kb[jp] + kvo + ko);
                LDSM4(kl4, kb[jp] + kvo + KVBUF_B + ko);
                MMA_H2(s[2 * jp], aqh, kh4[0], kh4[2]);
                MMA_H2(s[2 * jp], aqh, kl4[0], kl4[2]);
                MMA_H2(s[2 * jp + 1], aqh, kh4[1], kh4[3]);
                MMA_H2(s[2 * jp + 1], aqh, kl4[1], kl4[3]);
            }
        }

        // ---- causal mask (last two tiles only) ----
        if (kt >= nkt - 2) {
            const int rbase = q0 + wq + g;
#pragma unroll
            for (int j = 0; j < 8; j++) {
                int cg = k0 + 8 * j + 2 * tg;
                if (cg > rbase) s[j][0] = -1e9f;
                if (cg + 1 > rbase) s[j][1] = -1e9f;
                if (cg > rbase + 8) s[j][2] = -1e9f;
                if (cg + 1 > rbase + 8) s[j][3] = -1e9f;
            }
        }

        // ---- online softmax ----
#pragma unroll
        for (int rr = 0; rr < 2; rr++) {
            float tmax = -1e30f;
#pragma unroll
            for (int j = 0; j < 8; j++)
                tmax = fmaxf(tmax, fmaxf(s[j][rr * 2], s[j][rr * 2 + 1]));
            tmax = fmaxf(tmax, __shfl_xor_sync(0xffffffffu, tmax, 1));
            tmax = fmaxf(tmax, __shfl_xor_sync(0xffffffffu, tmax, 2));
            float mnew = fmaxf(mrow[rr], tmax);
            float scalef = __expf(mrow[rr] - mnew);
            mrow[rr] = mnew;
            float tsum = 0.f;
#pragma unroll
            for (int j = 0; j < 8; j++) {
                float p0 = __expf(s[j][rr * 2] - mnew);
                float p1 = __expf(s[j][rr * 2 + 1] - mnew);
                s[j][rr * 2] = p0;
                s[j][rr * 2 + 1] = p1;
                tsum += p0 + p1;
            }
            tsum += __shfl_xor_sync(0xffffffffu, tsum, 1);
            tsum += __shfl_xor_sync(0xffffffffu, tsum, 2);
            lrow[rr] = lrow[rr] * scalef + tsum;
#pragma unroll
            for (int dt = 0; dt < 16; dt++) {
                o[dt][rr * 2] *= scalef;
                o[dt][rr * 2 + 1] *= scalef;
            }
        }

        // ---- PV: Ph x Vh (1-term) ----
#pragma unroll
        for (int c = 0; c < 4; c++) {
            uint32_t pah[4];
#pragma unroll
            for (int hq = 0; hq < 2; hq++) {
                pah[hq * 2 + 0] = packh(s[2 * c + hq][0], s[2 * c + hq][1]);
                pah[hq * 2 + 1] = packh(s[2 * c + hq][2], s[2 * c + hq][3]);
            }
            const uint32_t vrow = vb + kvo + c * (16 * 272);
#pragma unroll
            for (int dt16 = 0; dt16 < 8; dt16++) {
                uint32_t vh4[4];
                LDSM4T(vh4, vrow + dt16 * 32);
                MMA_H2(o[2 * dt16], pah, vh4[0], vh4[1]);
                MMA_H2(o[2 * dt16 + 1], pah, vh4[2], vh4[3]);
            }
        }
    }

    // ---- epilogue: normalize, store fp16 ----
#pragma unroll
    for (int rr = 0; rr < 2; rr++) {
        float invl = 1.0f / lrow[rr];
        int row = q0 + wq + g + rr * 8;
#pragma unroll
        for (int dt = 0; dt < 16; dt++) {
            float x0 = o[dt][rr * 2] * invl;
            float x1 = o[dt][rr * 2 + 1] * invl;
            size_t off = (size_t)row * (NH * HD) + h * HD + dt * 8 + 2 * tg;
            *(uint32_t*)(g_ah + off) = packh(x0, x1);
        }
    }
#undef A_ISSUE
}

// ---------------- launch -----------------------------------------------------
extern "C" void kernel_launch(void* const* d_in, const int* in_sizes, int n_in,
                              void* d_out, int out_size) {
    const float* hidden = (const float*)d_in[0];
    const float* cosb   = (const float*)d_in[1];
    const float* sinb   = (const float*)d_in[2];
    const float* kcache = (const float*)d_in[3];
    const float* vcache = (const float*)d_in[4];
    const float* wqkv   = (const float*)d_in[6];
    const float* bqkv   = (const float*)d_in[7];
    const float* wo     = (const float*)d_in[8];
    const float* bo     = (const float*)d_in[9];
    const float* qw     = (const float*)d_in[10];
    const float* kw     = (const float*)d_in[11];
    const int*   widx   = (const int*)d_in[12];
    float* out = (float*)d_out;

    float* p_qkv;
    f16 *p_hidh, *p_wqh, *p_woh, *p_ah;
    cudaGetSymbolAddress((void**)&p_qkv, g_qkv);
    cudaGetSymbolAddress((void**)&p_hidh, g_hidh);
    cudaGetSymbolAddress((void**)&p_wqh, g_wqh);
    cudaGetSymbolAddress((void**)&p_woh, g_woh);
    cudaGetSymbolAddress((void**)&p_ah, g_ah);

    static bool attr_set = false;
    if (!attr_set) {
        cudaFuncSetAttribute(gemm_h, cudaFuncAttributeMaxDynamicSharedMemorySize, G_SMEM);
        cudaFuncSetAttribute(attn_tc, cudaFuncAttributeMaxDynamicSharedMemorySize, ATTN_SMEM);
        attr_set = true;
    }

    // 0. convert inputs to fp16
    conv_h<<<1024, 256>>>(hidden, p_hidh, S_LEN * HID / 4);
    conv_h<<<1024, 256>>>(wqkv, p_wqh, QKV_OUT * HID / 4);
    conv_h<<<1024, 256>>>(wo, p_woh, HID * HID / 4);

    // 1. QKV GEMM (pure fp16)
    gemm_h<<<dim3(QKV_OUT / 128, S_LEN / 128), 256, G_SMEM>>>(
        p_hidh, p_wqh, bqkv, p_qkv, QKV_OUT, HID);

    // 2. caches -> scratch (K split, V hi)
    copy_caches<<<256, 256>>>(kcache, vcache);

    // 3. RMSNorm + RoPE + scale + scatter
    norm_rope_scatter<<<dim3(S_LEN, 24), 128>>>(cosb, sinb, qw, kw, widx);

    // 4. fp16 flash attention (K 2-term scores, 1-term PV)
    attn_tc<<<dim3(S_LEN / 128, NH), 256, ATTN_SMEM>>>();

    // 5. output projection (pure fp16)
    gemm_h<<<dim3(HID / 128, S_LEN / 128), 256, G_SMEM>>>(
        p_ah, p_woh, bo, out, HID, NH * HD);
}

// round 12
// speedup vs baseline: 2.3304x; 1.1155x over previous
#include <cuda_runtime.h>
#include <cuda_fp16.h>
#include <cstdint>
#include <math.h>

// Problem constants
#define S_LEN 2048
#define HID 2048
#define NH 16
#define NKV 4
#define HD 128
#define QKV_OUT 3072
#define Q_SZ 2048
#define KV_SZ 512
#define SCALE_Q 0.08838834764831845f

typedef __half f16;

// ---------------- scratch ----------------------------------------------------
__device__ float g_qkv[S_LEN * QKV_OUT];
__device__ f16 g_hidh[S_LEN * HID];
__device__ f16 g_wqh[QKV_OUT * HID];
__device__ f16 g_woh[HID * HID];
__device__ f16 g_qh[S_LEN * NH * HD];
__device__ f16 g_kh[S_LEN * NKV * HD];
__device__ f16 g_vh[S_LEN * NKV * HD];
__device__ f16 g_ah[S_LEN * NH * HD];

// ---------------- helpers ----------------------------------------------------
__device__ __forceinline__ uint32_t smem_u32(const void* p) {
    return (uint32_t)__cvta_generic_to_shared(p);
}
__device__ __forceinline__ uint32_t packh(float lo_v, float hi_v) {
    uint32_t r;
    asm("cvt.rn.f16x2.f32 %0, %1, %2;" : "=r"(r) : "f"(hi_v), "f"(lo_v));
    return r;
}

#define MMA_H2(d, a, b0, b1) \
    asm volatile( \
        "mma.sync.aligned.m16n8k16.row.col.f32.f16.f16.f32 " \
        "{%0,%1,%2,%3}, {%4,%5,%6,%7}, {%8,%9}, {%0,%1,%2,%3};" \
        : "+f"((d)[0]), "+f"((d)[1]), "+f"((d)[2]), "+f"((d)[3]) \
        : "r"((a)[0]), "r"((a)[1]), "r"((a)[2]), "r"((a)[3]), \
          "r"(b0), "r"(b1))

#define LDSM4(r, addr) \
    asm volatile("ldmatrix.sync.aligned.m8n8.x4.shared.b16 {%0,%1,%2,%3}, [%4];" \
        : "=r"((r)[0]), "=r"((r)[1]), "=r"((r)[2]), "=r"((r)[3]) : "r"(addr))

#define LDSM4T(r, addr) \
    asm volatile("ldmatrix.sync.aligned.m8n8.x4.trans.shared.b16 {%0,%1,%2,%3}, [%4];" \
        : "=r"((r)[0]), "=r"((r)[1]), "=r"((r)[2]), "=r"((r)[3]) : "r"(addr))

#define CP16(dst, src) \
    asm volatile("cp.async.cg.shared.global [%0], [%1], 16;" :: "r"(dst), "l"(src))
#define CP_COMMIT() asm volatile("cp.async.commit_group;" ::: "memory")
#define CP_WAIT(n) asm volatile("cp.async.wait_group %0;" :: "n"(n) : "memory")

// ---------------- conversion kernels ----------------------------------------
__global__ void conv_h(const float* __restrict__ src, f16* __restrict__ hi, int n4) {
    __half2* H = (__half2*)hi;
    for (int i = blockIdx.x * blockDim.x + threadIdx.x; i < n4;
         i += gridDim.x * blockDim.x) {
        float4 v = ((const float4*)src)[i];
        H[2 * i] = __floats2half2_rn(v.x, v.y);
        H[2 * i + 1] = __floats2half2_rn(v.z, v.w);
    }
}

__global__ void copy_caches(const float* __restrict__ kc, const float* __restrict__ vc) {
    int n = S_LEN * NKV * HD;
    for (int i = blockIdx.x * blockDim.x + threadIdx.x; i < n;
         i += gridDim.x * blockDim.x) {
        g_kh[i] = __float2half_rn(kc[i]);
        g_vh[i] = __float2half_rn(vc[i]);
    }
}

// ---------------- fused RMSNorm + RoPE + scale + scatter ---------------------
__global__ void norm_rope_scatter(const float* __restrict__ cosb,
                                  const float* __restrict__ sinb,
                                  const float* __restrict__ qw,
                                  const float* __restrict__ kw,
                                  const int* __restrict__ widx) {
    const int s = blockIdx.x;
    const int head = blockIdx.y;
    const int d = threadIdx.x;
    __shared__ float sh[128];
    __shared__ float wsum[4];

    int col;
    if (head < 16)      col = head * HD + d;
    else if (head < 20) col = Q_SZ + (head - 16) * HD + d;
    else                col = Q_SZ + KV_SZ + (head - 20) * HD + d;

    float x = g_qkv[(size_t)s * QKV_OUT + col];

    if (head >= 20) {
        size_t o = ((size_t)widx[s] * NKV + (head - 20)) * HD + d;
        g_vh[o] = __float2half_rn(x);
        return;
    }

    float sq = x * x;
#pragma unroll
    for (int m = 16; m; m >>= 1) sq += __shfl_xor_sync(0xffffffffu, sq, m);
    if ((d & 31) == 0) wsum[d >> 5] = sq;
    __syncthreads();
    float ms = (wsum[0] + wsum[1] + wsum[2] + wsum[3]) * (1.0f / 128.0f);
    float inv = rsqrtf(ms + 1e-6f);
    const float* w = (head < 16) ? qw : kw;
    float y = x * inv * w[d];
    sh[d] = y;
    __syncthreads();

    if (d < 64) {
        float c = cosb[s * 64 + d], sn = sinb[s * 64 + d];
        float x1 = sh[d], x2 = sh[d + 64];
        float y1 = x1 * c - x2 * sn;
        float y2 = x1 * sn + x2 * c;
        if (head < 16) {
            y1 *= SCALE_Q; y2 *= SCALE_Q;
            size_t o = ((size_t)s * NH + head) * HD;
            g_qh[o + d] = __float2half_rn(y1);
            g_qh[o + d + 64] = __float2half_rn(y2);
        } else {
            size_t o = ((size_t)widx[s] * NKV + (head - 16)) * HD;
            g_kh[o + d] = __float2half_rn(y1);
            g_kh[o + d + 64] = __float2half_rn(y2);
        }
    }
}

// =================== pure fp16 GEMM ==========================================
// C[M,N] = Ah[M,K] @ Bh[N,K]^T + bias[N].
// CTA 128x128, 256 thr (8 warps 4x2), warp 32x64, k-chunk 32, 4-stage cp.async.
#define GSTRIDE 40
#define GB_E (128 * GSTRIDE)              // 5120 elems
#define GB_B (GB_E * 2)                   // 10240 bytes
#define GSTAGE_B (2 * GB_B)               // 20480 bytes
#define G_SMEM (4 * GSTAGE_B)             // 81920 bytes

__global__ void __launch_bounds__(256)
gemm_h(const f16* __restrict__ Ah_g, const f16* __restrict__ Bh_g,
       const float* __restrict__ bias, float* __restrict__ C, int N, int K) {
    extern __shared__ f16 smg[];
    const int t = threadIdx.x;
    const int lane = t & 31, wid = t >> 5;
    const int g = lane >> 2, tg = lane & 3;
    const int wm = (wid & 3) * 32, wn = (wid >> 2) * 64;
    const int m0 = blockIdx.y << 7, n0 = blockIdx.x << 7;
    const int nch = K >> 5;

    const int l15 = lane & 15, lh = lane >> 4;
    const uint32_t sb = smem_u32(smg);
    const uint32_t offA = (uint32_t)((wm + l15) * 80 + lh * 16);
    const uint32_t offB = (uint32_t)((wn + l15) * 80 + lh * 16);

    float d[2][8][4];
#pragma unroll
    for (int i = 0; i < 2; i++)
#pragma unroll
        for (int j = 0; j < 8; j++)
#pragma unroll
            for (int q = 0; q < 4; q++) d[i][j][q] = 0.f;

#define G_ISSUE(c) do { \
    uint32_t base = sb + ((c) & 3) * GSTAGE_B; \
    _Pragma("unroll") \
    for (int j = 0; j < 2; j++) { \
        int u = t + (j << 8); int row = u >> 2, q = u & 3; \
        uint32_t dst = base + (uint32_t)(row * GSTRIDE + (q << 3)) * 2; \
        size_t ao = (size_t)(m0 + row) * K + ((c) << 5) + (q << 3); \
        size_t bo = (size_t)(n0 + row) * K + ((c) << 5) + (q << 3); \
        CP16(dst, Ah_g + ao); \
        CP16(dst + GB_B, Bh_g + bo); \
    } } while (0)

    G_ISSUE(0); CP_COMMIT();
    G_ISSUE(1); CP_COMMIT();
    G_ISSUE(2); CP_COMMIT();

    for (int c = 0; c < nch; c++) {
        CP_WAIT(2);
        __syncthreads();
        const uint32_t base = sb + (c & 3) * GSTAGE_B;
#pragma unroll
        for (int ks = 0; ks < 2; ks++) {
            const uint32_t ko = ks * 32;
            uint32_t ah[2][4];
#pragma unroll
            for (int mt = 0; mt < 2; mt++)
                LDSM4(ah[mt], base + offA + mt * 1280 + ko);
#pragma unroll
            for (int jp = 0; jp < 4; jp++) {
                uint32_t bh4[4];
                LDSM4(bh4, base + GB_B + offB + jp * 1280 + ko);
#pragma unroll
                for (int mt = 0; mt < 2; mt++) {
                    MMA_H2(d[mt][2 * jp], ah[mt], bh4[0], bh4[2]);
                    MMA_H2(d[mt][2 * jp + 1], ah[mt], bh4[1], bh4[3]);
                }
            }
        }
        __syncthreads();
        if (c + 3 < nch) { G_ISSUE(c + 3); CP_COMMIT(); }
    }

    // epilogue
#pragma unroll
    for (int i = 0; i < 2; i++) {
        int r = m0 + wm + i * 16 + g;
#pragma unroll
        for (int j = 0; j < 8; j++) {
            int cix = n0 + wn + j * 8 + tg * 2;
            float2 b2 = *(const float2*)(bias + cix);
            float2 v0, v1;
            v0.x = d[i][j][0] + b2.x; v0.y = d[i][j][1] + b2.y;
            v1.x = d[i][j][2] + b2.x; v1.y = d[i][j][3] + b2.y;
            *(float2*)(C + (size_t)r * N + cix) = v0;
            *(float2*)(C + (size_t)(r + 8) * N + cix) = v1;
        }
    }
#undef G_ISSUE
}

// =================== fp16 flash attention (all 1-term) =======================
// 256 threads (8 warps), CTA = 128 q rows of one head; warp w owns rows
// [16w,16w+16). k-tiles of 64 keys, cp.async double-buffered (Kh, Vh).
#define APAD 136
#define QBUF_E (128 * APAD)               // 17408 elems (34816 B)
#define KVBUF_E (64 * APAD)
#define KVBUF_B (KVBUF_E * 2)             // 17408 B
#define KVSTAGE_B (2 * KVBUF_B)           // 34816 B (Kh, Vh)
#define ATTN_SMEM (QBUF_E * 2 + 2 * KVSTAGE_B)   // 104448 B

__global__ void __launch_bounds__(256, 1) attn_tc() {
    extern __shared__ f16 sma[];
    f16* Qh = sma;

    const int t = threadIdx.x;
    const int lane = t & 31, w = t >> 5;
    const int g = lane >> 2, tg = lane & 3;
    const int qt = gridDim.x - 1 - blockIdx.x;
    const int q0 = qt * 128;
    const int h = blockIdx.y, kvh = h >> 2;
    const int wq = w * 16;

    const uint32_t kvb = smem_u32(sma) + QBUF_E * 2;

#define A_ISSUE(kt) do { \
    uint32_t base = kvb + ((kt) & 1) * KVSTAGE_B; \
    _Pragma("unroll") \
    for (int i = 0; i < 4; i++) { \
        int u = t + (i << 8); int r = u >> 4, cc = u & 15; \
        size_t so = ((size_t)(((kt) << 6) + r) * NKV + kvh) * HD + cc * 8; \
        uint32_t dd = base + (uint32_t)(r * 272 + cc * 16); \
        CP16(dd, g_kh + so); \
        CP16(dd + KVBUF_B, g_vh + so); \
    } } while (0)

    A_ISSUE(0); CP_COMMIT();

    // stage Q
#pragma unroll
    for (int i = 0; i < 8; i++) {
        int u = t + i * 256;
        int r = u >> 4, cc = u & 15;
        size_t qo = ((size_t)(q0 + r) * NH + h) * HD + cc * 8;
        *(uint4*)((char*)Qh + r * 272 + cc * 16) = *(const uint4*)(g_qh + qo);
    }

    const int l15 = lane & 15, lh = lane >> 4;
    const uint32_t qb_h = smem_u32(Qh) + (wq + l15) * 272 + lh * 16;
    uint32_t kb[4];
#pragma unroll
    for (int jp = 0; jp < 4; jp++)
        kb[jp] = kvb + (jp * 16 + l15) * 272 + lh * 16;
    const uint32_t vb = kvb + KVBUF_B + l15 * 272 + lh * 16;

    float o[16][4];
#pragma unroll
    for (int dt = 0; dt < 16; dt++)
#pragma unroll
        for (int q = 0; q < 4; q++) o[dt][q] = 0.f;
    float mrow[2] = {-1e30f, -1e30f};
    float lrow[2] = {0.f, 0.f};

    const int nkt = 2 * (qt + 1);
    for (int kt = 0; kt < nkt; kt++) {
        CP_WAIT(0);
        __syncthreads();
        if (kt + 1 < nkt) { A_ISSUE(kt + 1); CP_COMMIT(); }
        const uint32_t kvo = (kt & 1) * KVSTAGE_B;
        const int k0 = kt * 64;

        // ---- scores: Qh x Kh ----
        float s[8][4];
#pragma unroll
        for (int j = 0; j < 8; j++)
#pragma unroll
            for (int q = 0; q < 4; q++) s[j][q] = 0.f;

#pragma unroll
        for (int ks = 0; ks < 8; ks++) {
            const uint32_t ko = ks * 32;
            uint32_t aqh[4];
            LDSM4(aqh, qb_h + ko);
#pragma unroll
            for (int jp = 0; jp < 4; jp++) {
                uint32_t kh4[4];
                LDSM4(kh4, kb[jp] + kvo + ko);
                MMA_H2(s[2 * jp], aqh, kh4[0], kh4[2]);
                MMA_H2(s[2 * jp + 1], aqh, kh4[1], kh4[3]);
            }
        }

        // ---- causal mask (last two tiles only) ----
        if (kt >= nkt - 2) {
            const int rbase = q0 + wq + g;
#pragma unroll
            for (int j = 0; j < 8; j++) {
                int cg = k0 + 8 * j + 2 * tg;
                if (cg > rbase) s[j][0] = -1e9f;
                if (cg + 1 > rbase) s[j][1] = -1e9f;
                if (cg > rbase + 8) s[j][2] = -1e9f;
                if (cg + 1 > rbase + 8) s[j][3] = -1e9f;
            }
        }

        // ---- online softmax ----
#pragma unroll
        for (int rr = 0; rr < 2; rr++) {
            float tmax = -1e30f;
#pragma unroll
            for (int j = 0; j < 8; j++)
                tmax = fmaxf(tmax, fmaxf(s[j][rr * 2], s[j][rr * 2 + 1]));
            tmax = fmaxf(tmax, __shfl_xor_sync(0xffffffffu, tmax, 1));
            tmax = fmaxf(tmax, __shfl_xor_sync(0xffffffffu, tmax, 2));
            float mnew = fmaxf(mrow[rr], tmax);
            float scalef = __expf(mrow[rr] - mnew);
            mrow[rr] = mnew;
            float tsum = 0.f;
#pragma unroll
            for (int j = 0; j < 8; j++) {
                float p0 = __expf(s[j][rr * 2] - mnew);
                float p1 = __expf(s[j][rr * 2 + 1] - mnew);
                s[j][rr * 2] = p0;
                s[j][rr * 2 + 1] = p1;
                tsum += p0 + p1;
            }
            tsum += __shfl_xor_sync(0xffffffffu, tsum, 1);
            tsum += __shfl_xor_sync(0xffffffffu, tsum, 2);
            lrow[rr] = lrow[rr] * scalef + tsum;
#pragma unroll
            for (int dt = 0; dt < 16; dt++) {
                o[dt][rr * 2] *= scalef;
                o[dt][rr * 2 + 1] *= scalef;
            }
        }

        // ---- PV: Ph x Vh ----
#pragma unroll
        for (int c = 0; c < 4; c++) {
            uint32_t pah[4];
#pragma unroll
            for (int hq = 0; hq < 2; hq++) {
                pah[hq * 2 + 0] = packh(s[2 * c + hq][0], s[2 * c + hq][1]);
                pah[hq * 2 + 1] = packh(s[2 * c + hq][2], s[2 * c + hq][3]);
            }
            const uint32_t vrow = vb + kvo + c * (16 * 272);
#pragma unroll
            for (int dt16 = 0; dt16 < 8; dt16++) {
                uint32_t vh4[4];
                LDSM4T(vh4, vrow + dt16 * 32);
                MMA_H2(o[2 * dt16], pah, vh4[0], vh4[1]);
                MMA_H2(o[2 * dt16 + 1], pah, vh4[2], vh4[3]);
            }
        }
    }

    // ---- epilogue: normalize, store fp16 ----
#pragma unroll
    for (int rr = 0; rr < 2; rr++) {
        float invl = 1.0f / lrow[rr];
        int row = q0 + wq + g + rr * 8;
#pragma unroll
        for (int dt = 0; dt < 16; dt++) {
            float x0 = o[dt][rr * 2] * invl;
            float x1 = o[dt][rr * 2 + 1] * invl;
            size_t off = (size_t)row * (NH * HD) + h * HD + dt * 8 + 2 * tg;
            *(uint32_t*)(g_ah + off) = packh(x0, x1);
        }
    }
#undef A_ISSUE
}

// ---------------- launch -----------------------------------------------------
extern "C" void kernel_launch(void* const* d_in, const int* in_sizes, int n_in,
                              void* d_out, int out_size) {
    const float* hidden = (const float*)d_in[0];
    const float* cosb   = (const float*)d_in[1];
    const float* sinb   = (const float*)d_in[2];
    const float* kcache = (const float*)d_in[3];
    const float* vcache = (const float*)d_in[4];
    const float* wqkv   = (const float*)d_in[6];
    const float* bqkv   = (const float*)d_in[7];
    const float* wo     = (const float*)d_in[8];
    const float* bo     = (const float*)d_in[9];
    const float* qw     = (const float*)d_in[10];
    const float* kw     = (const float*)d_in[11];
    const int*   widx   = (const int*)d_in[12];
    float* out = (float*)d_out;

    float* p_qkv;
    f16 *p_hidh, *p_wqh, *p_woh, *p_ah;
    cudaGetSymbolAddress((void**)&p_qkv, g_qkv);
    cudaGetSymbolAddress((void**)&p_hidh, g_hidh);
    cudaGetSymbolAddress((void**)&p_wqh, g_wqh);
    cudaGetSymbolAddress((void**)&p_woh, g_woh);
    cudaGetSymbolAddress((void**)&p_ah, g_ah);

    static bool attr_set = false;
    if (!attr_set) {
        cudaFuncSetAttribute(gemm_h, cudaFuncAttributeMaxDynamicSharedMemorySize, G_SMEM);
        cudaFuncSetAttribute(attn_tc, cudaFuncAttributeMaxDynamicSharedMemorySize, ATTN_SMEM);
        attr_set = true;
    }

    // 0. convert inputs to fp16
    conv_h<<<1024, 256>>>(hidden, p_hidh, S_LEN * HID / 4);
    conv_h<<<1024, 256>>>(wqkv, p_wqh, QKV_OUT * HID / 4);
    conv_h<<<1024, 256>>>(wo, p_woh, HID * HID / 4);

    // 1. QKV GEMM (pure fp16)
    gemm_h<<<dim3(QKV_OUT / 128, S_LEN / 128), 256, G_SMEM>>>(
        p_hidh, p_wqh, bqkv, p_qkv, QKV_OUT, HID);

    // 2. caches -> scratch
    copy_caches<<<256, 256>>>(kcache, vcache);

    // 3. RMSNorm + RoPE + scale + scatter
    norm_rope_scatter<<<dim3(S_LEN, 24), 128>>>(cosb, sinb, qw, kw, widx);

    // 4. fp16 flash attention (1-term everywhere)
    attn_tc<<<dim3(S_LEN / 128, NH), 256, ATTN_SMEM>>>();

    // 5. output projection (pure fp16)
    gemm_h<<<dim3(HID / 128, S_LEN / 128), 256, G_SMEM>>>(
        p_ah, p_woh, bo, out, HID, NH * HD);
}

// round 13
// speedup vs baseline: 2.3908x; 1.0259x over previous
#include <cuda_runtime.h>
#include <cuda_fp16.h>
#include <cstdint>
#include <math.h>

// Problem constants
#define S_LEN 2048
#define HID 2048
#define NH 16
#define NKV 4
#define HD 128
#define QKV_OUT 3072
#define Q_SZ 2048
#define KV_SZ 512
#define SCALE_Q 0.08838834764831845f

typedef __half f16;

// ---------------- scratch ----------------------------------------------------
__device__ f16 g_qkvh[S_LEN * QKV_OUT];
__device__ f16 g_hidh[S_LEN * HID];
__device__ f16 g_wqh[QKV_OUT * HID];
__device__ f16 g_woh[HID * HID];
__device__ f16 g_qh[S_LEN * NH * HD];
__device__ f16 g_kh[S_LEN * NKV * HD];
__device__ f16 g_vh[S_LEN * NKV * HD];
__device__ f16 g_ah[S_LEN * NH * HD];

// ---------------- helpers ----------------------------------------------------
__device__ __forceinline__ uint32_t smem_u32(const void* p) {
    return (uint32_t)__cvta_generic_to_shared(p);
}
__device__ __forceinline__ uint32_t packh(float lo_v, float hi_v) {
    uint32_t r;
    asm("cvt.rn.f16x2.f32 %0, %1, %2;" : "=r"(r) : "f"(hi_v), "f"(lo_v));
    return r;
}

#define MMA_H2(d, a, b0, b1) \
    asm volatile( \
        "mma.sync.aligned.m16n8k16.row.col.f32.f16.f16.f32 " \
        "{%0,%1,%2,%3}, {%4,%5,%6,%7}, {%8,%9}, {%0,%1,%2,%3};" \
        : "+f"((d)[0]), "+f"((d)[1]), "+f"((d)[2]), "+f"((d)[3]) \
        : "r"((a)[0]), "r"((a)[1]), "r"((a)[2]), "r"((a)[3]), \
          "r"(b0), "r"(b1))

#define LDSM4(r, addr) \
    asm volatile("ldmatrix.sync.aligned.m8n8.x4.shared.b16 {%0,%1,%2,%3}, [%4];" \
        : "=r"((r)[0]), "=r"((r)[1]), "=r"((r)[2]), "=r"((r)[3]) : "r"(addr))

#define LDSM4T(r, addr) \
    asm volatile("ldmatrix.sync.aligned.m8n8.x4.trans.shared.b16 {%0,%1,%2,%3}, [%4];" \
        : "=r"((r)[0]), "=r"((r)[1]), "=r"((r)[2]), "=r"((r)[3]) : "r"(addr))

#define CP16(dst, src) \
    asm volatile("cp.async.cg.shared.global [%0], [%1], 16;" :: "r"(dst), "l"(src))
#define CP_COMMIT() asm volatile("cp.async.commit_group;" ::: "memory")
#define CP_WAIT(n) asm volatile("cp.async.wait_group %0;" :: "n"(n) : "memory")

// ---------------- conversion kernels ----------------------------------------
__global__ void conv_h(const float* __restrict__ src, f16* __restrict__ hi, int n4) {
    __half2* H = (__half2*)hi;
    for (int i = blockIdx.x * blockDim.x + threadIdx.x; i < n4;
         i += gridDim.x * blockDim.x) {
        float4 v = ((const float4*)src)[i];
        H[2 * i] = __floats2half2_rn(v.x, v.y);
        H[2 * i + 1] = __floats2half2_rn(v.z, v.w);
    }
}

__global__ void copy_caches(const float* __restrict__ kc, const float* __restrict__ vc) {
    int n = S_LEN * NKV * HD;
    for (int i = blockIdx.x * blockDim.x + threadIdx.x; i < n;
         i += gridDim.x * blockDim.x) {
        g_kh[i] = __float2half_rn(kc[i]);
        g_vh[i] = __float2half_rn(vc[i]);
    }
}

// ---------------- fused RMSNorm + RoPE + scale + scatter ---------------------
// grid (S, 6), block (128, 4). head = by*4 + ty. by=5 -> V heads (20..23),
// by=4 -> K heads (16..19), by 0..3 -> Q heads. Reads fp16 qkv.
__global__ void norm_rope_scatter(const float* __restrict__ cosb,
                                  const float* __restrict__ sinb,
                                  const float* __restrict__ qw,
                                  const float* __restrict__ kw,
                                  const int* __restrict__ widx) {
    const int s = blockIdx.x;
    const int ty = threadIdx.y;
    const int head = blockIdx.y * 4 + ty;
    const int d = threadIdx.x;
    __shared__ float sh[4][128];
    __shared__ float wsum[4][4];

    int col;
    if (head < 16)      col = head * HD + d;
    else if (head < 20) col = Q_SZ + (head - 16) * HD + d;
    else                col = Q_SZ + KV_SZ + (head - 20) * HD + d;

    float x = __half2float(g_qkvh[(size_t)s * QKV_OUT + col]);

    if (head >= 20) {  // whole block (by=5) takes this path; no barrier after
        size_t o = ((size_t)widx[s] * NKV + (head - 20)) * HD + d;
        g_vh[o] = __float2half_rn(x);
        return;
    }

    float sq = x * x;
#pragma unroll
    for (int m = 16; m; m >>= 1) sq += __shfl_xor_sync(0xffffffffu, sq, m);
    if ((d & 31) == 0) wsum[ty][d >> 5] = sq;
    __syncthreads();
    float ms = (wsum[ty][0] + wsum[ty][1] + wsum[ty][2] + wsum[ty][3]) * (1.0f / 128.0f);
    float inv = rsqrtf(ms + 1e-6f);
    const float* w = (head < 16) ? qw : kw;
    float y = x * inv * w[d];
    sh[ty][d] = y;
    __syncthreads();

    if (d < 64) {
        float c = cosb[s * 64 + d], sn = sinb[s * 64 + d];
        float x1 = sh[ty][d], x2 = sh[ty][d + 64];
        float y1 = x1 * c - x2 * sn;
        float y2 = x1 * sn + x2 * c;
        if (head < 16) {
            y1 *= SCALE_Q; y2 *= SCALE_Q;
            size_t o = ((size_t)s * NH + head) * HD;
            g_qh[o + d] = __float2half_rn(y1);
            g_qh[o + d + 64] = __float2half_rn(y2);
        } else {
            size_t o = ((size_t)widx[s] * NKV + (head - 16)) * HD;
            g_kh[o + d] = __float2half_rn(y1);
            g_kh[o + d + 64] = __float2half_rn(y2);
        }
    }
}

// =================== pure fp16 GEMM ==========================================
// CTA 128x128, 256 thr (8 warps 4x2), warp 32x64, k-chunk 32, 4-stage cp.async.
// half_out: store fp16 to Ch instead of fp32 to C.
#define GSTRIDE 40
#define GB_E (128 * GSTRIDE)              // 5120 elems
#define GB_B (GB_E * 2)                   // 10240 bytes
#define GSTAGE_B (2 * GB_B)               // 20480 bytes
#define G_SMEM (4 * GSTAGE_B)             // 81920 bytes

__global__ void __launch_bounds__(256)
gemm_h(const f16* __restrict__ Ah_g, const f16* __restrict__ Bh_g,
       const float* __restrict__ bias, float* __restrict__ C,
       f16* __restrict__ Ch, int N, int K, int half_out) {
    extern __shared__ f16 smg[];
    const int t = threadIdx.x;
    const int lane = t & 31, wid = t >> 5;
    const int g = lane >> 2, tg = lane & 3;
    const int wm = (wid & 3) * 32, wn = (wid >> 2) * 64;
    const int m0 = blockIdx.y << 7, n0 = blockIdx.x << 7;
    const int nch = K >> 5;

    const int l15 = lane & 15, lh = lane >> 4;
    const uint32_t sb = smem_u32(smg);
    const uint32_t offA = (uint32_t)((wm + l15) * 80 + lh * 16);
    const uint32_t offB = (uint32_t)((wn + l15) * 80 + lh * 16);

    float d[2][8][4];
#pragma unroll
    for (int i = 0; i < 2; i++)
#pragma unroll
        for (int j = 0; j < 8; j++)
#pragma unroll
            for (int q = 0; q < 4; q++) d[i][j][q] = 0.f;

#define G_ISSUE(c) do { \
    uint32_t base = sb + ((c) & 3) * GSTAGE_B; \
    _Pragma("unroll") \
    for (int j = 0; j < 2; j++) { \
        int u = t + (j << 8); int row = u >> 2, q = u & 3; \
        uint32_t dst = base + (uint32_t)(row * GSTRIDE + (q << 3)) * 2; \
        size_t ao = (size_t)(m0 + row) * K + ((c) << 5) + (q << 3); \
        size_t bo = (size_t)(n0 + row) * K + ((c) << 5) + (q << 3); \
        CP16(dst, Ah_g + ao); \
        CP16(dst + GB_B, Bh_g + bo); \
    } } while (0)

    G_ISSUE(0); CP_COMMIT();
    G_ISSUE(1); CP_COMMIT();
    G_ISSUE(2); CP_COMMIT();

    for (int c = 0; c < nch; c++) {
        CP_WAIT(2);
        __syncthreads();
        const uint32_t base = sb + (c & 3) * GSTAGE_B;
#pragma unroll
        for (int ks = 0; ks < 2; ks++) {
            const uint32_t ko = ks * 32;
            uint32_t ah[2][4];
#pragma unroll
            for (int mt = 0; mt < 2; mt++)
                LDSM4(ah[mt], base + offA + mt * 1280 + ko);
#pragma unroll
            for (int jp = 0; jp < 4; jp++) {
                uint32_t bh4[4];
                LDSM4(bh4, base + GB_B + offB + jp * 1280 + ko);
#pragma unroll
                for (int mt = 0; mt < 2; mt++) {
                    MMA_H2(d[mt][2 * jp], ah[mt], bh4[0], bh4[2]);
                    MMA_H2(d[mt][2 * jp + 1], ah[mt], bh4[1], bh4[3]);
                }
            }
        }
        __syncthreads();
        if (c + 3 < nch) { G_ISSUE(c + 3); CP_COMMIT(); }
    }

    // epilogue
#pragma unroll
    for (int i = 0; i < 2; i++) {
        int r = m0 + wm + i * 16 + g;
#pragma unroll
        for (int j = 0; j < 8; j++) {
            int cix = n0 + wn + j * 8 + tg * 2;
            float2 b2 = *(const float2*)(bias + cix);
            float v00 = d[i][j][0] + b2.x, v01 = d[i][j][1] + b2.y;
            float v10 = d[i][j][2] + b2.x, v11 = d[i][j][3] + b2.y;
            if (half_out) {
                *(uint32_t*)(Ch + (size_t)r * N + cix) = packh(v00, v01);
                *(uint32_t*)(Ch + (size_t)(r + 8) * N + cix) = packh(v10, v11);
            } else {
                float2 a0, a1;
                a0.x = v00; a0.y = v01;
                a1.x = v10; a1.y = v11;
                *(float2*)(C + (size_t)r * N + cix) = a0;
                *(float2*)(C + (size_t)(r + 8) * N + cix) = a1;
            }
        }
    }
#undef G_ISSUE
}

// =================== fp16 flash attention ====================================
#define APAD 136
#define QBUF_E (128 * APAD)
#define KVBUF_E (64 * APAD)
#define KVBUF_B (KVBUF_E * 2)
#define KVSTAGE_B (2 * KVBUF_B)           // 34816 B (Kh, Vh)
#define ATTN_SMEM (QBUF_E * 2 + 2 * KVSTAGE_B)   // 104448 B

__global__ void __launch_bounds__(256, 1) attn_tc() {
    extern __shared__ f16 sma[];
    f16* Qh = sma;

    const int t = threadIdx.x;
    const int lane = t & 31, w = t >> 5;
    const int g = lane >> 2, tg = lane & 3;
    const int qt = gridDim.x - 1 - blockIdx.x;
    const int q0 = qt * 128;
    const int h = blockIdx.y, kvh = h >> 2;
    const int wq = w * 16;

    const uint32_t kvb = smem_u32(sma) + QBUF_E * 2;

#define A_ISSUE(kt) do { \
    uint32_t base = kvb + ((kt) & 1) * KVSTAGE_B; \
    _Pragma("unroll") \
    for (int i = 0; i < 4; i++) { \
        int u = t + (i << 8); int r = u >> 4, cc = u & 15; \
        size_t so = ((size_t)(((kt) << 6) + r) * NKV + kvh) * HD + cc * 8; \
        uint32_t dd = base + (uint32_t)(r * 272 + cc * 16); \
        CP16(dd, g_kh + so); \
        CP16(dd + KVBUF_B, g_vh + so); \
    } } while (0)

    A_ISSUE(0); CP_COMMIT();

#pragma unroll
    for (int i = 0; i < 8; i++) {
        int u = t + i * 256;
        int r = u >> 4, cc = u & 15;
        size_t qo = ((size_t)(q0 + r) * NH + h) * HD + cc * 8;
        *(uint4*)((char*)Qh + r * 272 + cc * 16) = *(const uint4*)(g_qh + qo);
    }

    const int l15 = lane & 15, lh = lane >> 4;
    const uint32_t qb_h = smem_u32(Qh) + (wq + l15) * 272 + lh * 16;
    uint32_t kb[4];
#pragma unroll
    for (int jp = 0; jp < 4; jp++)
        kb[jp] = kvb + (jp * 16 + l15) * 272 + lh * 16;
    const uint32_t vb = kvb + KVBUF_B + l15 * 272 + lh * 16;

    float o[16][4];
#pragma unroll
    for (int dt = 0; dt < 16; dt++)
#pragma unroll
        for (int q = 0; q < 4; q++) o[dt][q] = 0.f;
    float mrow[2] = {-1e30f, -1e30f};
    float lrow[2] = {0.f, 0.f};

    const int nkt = 2 * (qt + 1);
    for (int kt = 0; kt < nkt; kt++) {
        CP_WAIT(0);
        __syncthreads();
        if (kt + 1 < nkt) { A_ISSUE(kt + 1); CP_COMMIT(); }
        const uint32_t kvo = (kt & 1) * KVSTAGE_B;
        const int k0 = kt * 64;

        float s[8][4];
#pragma unroll
        for (int j = 0; j < 8; j++)
#pragma unroll
            for (int q = 0; q < 4; q++) s[j][q] = 0.f;

#pragma unroll
        for (int ks = 0; ks < 8; ks++) {
            const uint32_t ko = ks * 32;
            uint32_t aqh[4];
            LDSM4(aqh, qb_h + ko);
#pragma unroll
            for (int jp = 0; jp < 4; jp++) {
                uint32_t kh4[4];
                LDSM4(kh4, kb[jp] + kvo + ko);
                MMA_H2(s[2 * jp], aqh, kh4[0], kh4[2]);
                MMA_H2(s[2 * jp + 1], aqh, kh4[1], kh4[3]);
            }
        }

        if (kt >= nkt - 2) {
            const int rbase = q0 + wq + g;
#pragma unroll
            for (int j = 0; j < 8; j++) {
                int cg = k0 + 8 * j + 2 * tg;
                if (cg > rbase) s[j][0] = -1e9f;
                if (cg + 1 > rbase) s[j][1] = -1e9f;
                if (cg > rbase + 8) s[j][2] = -1e9f;
                if (cg + 1 > rbase + 8) s[j][3] = -1e9f;
            }
        }

#pragma unroll
        for (int rr = 0; rr < 2; rr++) {
            float tmax = -1e30f;
#pragma unroll
            for (int j = 0; j < 8; j++)
                tmax = fmaxf(tmax, fmaxf(s[j][rr * 2], s[j][rr * 2 + 1]));
            tmax = fmaxf(tmax, __shfl_xor_sync(0xffffffffu, tmax, 1));
            tmax = fmaxf(tmax, __shfl_xor_sync(0xffffffffu, tmax, 2));
            float mnew = fmaxf(mrow[rr], tmax);
            float scalef = __expf(mrow[rr] - mnew);
            mrow[rr] = mnew;
            float tsum = 0.f;
#pragma unroll
            for (int j = 0; j < 8; j++) {
                float p0 = __expf(s[j][rr * 2] - mnew);
                float p1 = __expf(s[j][rr * 2 + 1] - mnew);
                s[j][rr * 2] = p0;
                s[j][rr * 2 + 1] = p1;
                tsum += p0 + p1;
            }
            tsum += __shfl_xor_sync(0xffffffffu, tsum, 1);
            tsum += __shfl_xor_sync(0xffffffffu, tsum, 2);
            lrow[rr] = lrow[rr] * scalef + tsum;
#pragma unroll
            for (int dt = 0; dt < 16; dt++) {
                o[dt][rr * 2] *= scalef;
                o[dt][rr * 2 + 1] *= scalef;
            }
        }

#pragma unroll
        for (int c = 0; c < 4; c++) {
            uint32_t pah[4];
#pragma unroll
            for (int hq = 0; hq < 2; hq++) {
                pah[hq * 2 + 0] = packh(s[2 * c + hq][0], s[2 * c + hq][1]);
                pah[hq * 2 + 1] = packh(s[2 * c + hq][2], s[2 * c + hq][3]);
            }
            const uint32_t vrow = vb + kvo + c * (16 * 272);
#pragma unroll
            for (int dt16 = 0; dt16 < 8; dt16++) {
                uint32_t vh4[4];
                LDSM4T(vh4, vrow + dt16 * 32);
                MMA_H2(o[2 * dt16], pah, vh4[0], vh4[1]);
                MMA_H2(o[2 * dt16 + 1], pah, vh4[2], vh4[3]);
            }
        }
    }

#pragma unroll
    for (int rr = 0; rr < 2; rr++) {
        float invl = 1.0f / lrow[rr];
        int row = q0 + wq + g + rr * 8;
#pragma unroll
        for (int dt = 0; dt < 16; dt++) {
            float x0 = o[dt][rr * 2] * invl;
            float x1 = o[dt][rr * 2 + 1] * invl;
            size_t off = (size_t)row * (NH * HD) + h * HD + dt * 8 + 2 * tg;
            *(uint32_t*)(g_ah + off) = packh(x0, x1);
        }
    }
#undef A_ISSUE
}

// ---------------- launch -----------------------------------------------------
extern "C" void kernel_launch(void* const* d_in, const int* in_sizes, int n_in,
                              void* d_out, int out_size) {
    const float* hidden = (const float*)d_in[0];
    const float* cosb   = (const float*)d_in[1];
    const float* sinb   = (const float*)d_in[2];
    const float* kcache = (const float*)d_in[3];
    const float* vcache = (const float*)d_in[4];
    const float* wqkv   = (const float*)d_in[6];
    const float* bqkv   = (const float*)d_in[7];
    const float* wo     = (const float*)d_in[8];
    const float* bo     = (const float*)d_in[9];
    const float* qw     = (const float*)d_in[10];
    const float* kw     = (const float*)d_in[11];
    const int*   widx   = (const int*)d_in[12];
    float* out = (float*)d_out;

    f16 *p_qkvh, *p_hidh, *p_wqh, *p_woh, *p_ah;
    cudaGetSymbolAddress((void**)&p_qkvh, g_qkvh);
    cudaGetSymbolAddress((void**)&p_hidh, g_hidh);
    cudaGetSymbolAddress((void**)&p_wqh, g_wqh);
    cudaGetSymbolAddress((void**)&p_woh, g_woh);
    cudaGetSymbolAddress((void**)&p_ah, g_ah);

    // streams/events created on the (uncaptured) first call, reused in capture
    static cudaStream_t s1 = nullptr, s2 = nullptr;
    static cudaEvent_t eRoot, eW1, eCache, eW2;
    static bool init = false;
    if (!init) {
        cudaStreamCreateWithFlags(&s1, cudaStreamNonBlocking);
        cudaStreamCreateWithFlags(&s2, cudaStreamNonBlocking);
        cudaEventCreateWithFlags(&eRoot, cudaEventDisableTiming);
        cudaEventCreateWithFlags(&eW1, cudaEventDisableTiming);
        cudaEventCreateWithFlags(&eCache, cudaEventDisableTiming);
        cudaEventCreateWithFlags(&eW2, cudaEventDisableTiming);
        cudaFuncSetAttribute(gemm_h, cudaFuncAttributeMaxDynamicSharedMemorySize, G_SMEM);
        cudaFuncSetAttribute(attn_tc, cudaFuncAttributeMaxDynamicSharedMemorySize, ATTN_SMEM);
        init = true;
    }

    // fork
    cudaEventRecord(eRoot, 0);
    cudaStreamWaitEvent(s1, eRoot, 0);
    cudaStreamWaitEvent(s2, eRoot, 0);

    // main stream: hidden conversion
    conv_h<<<1024, 256>>>(hidden, p_hidh, S_LEN * HID / 4);
    // s1: wqkv conversion, then caches
    conv_h<<<1024, 256, 0, s1>>>(wqkv, p_wqh, QKV_OUT * HID / 4);
    cudaEventRecord(eW1, s1);
    copy_caches<<<256, 256, 0, s1>>>(kcache, vcache);
    cudaEventRecord(eCache, s1);
    // s2: wo conversion
    conv_h<<<1024, 256, 0, s2>>>(wo, p_woh, HID * HID / 4);
    cudaEventRecord(eW2, s2);

    // QKV GEMM (needs hidden + wqkv)
    cudaStreamWaitEvent(0, eW1, 0);
    gemm_h<<<dim3(QKV_OUT / 128, S_LEN / 128), 256, G_SMEM>>>(
        p_hidh, p_wqh, bqkv, nullptr, p_qkvh, QKV_OUT, HID, 1);

    // norm/rope (needs caches staged first: scatter overwrites)
    cudaStreamWaitEvent(0, eCache, 0);
    norm_rope_scatter<<<dim3(S_LEN, 6), dim3(128, 4)>>>(cosb, sinb, qw, kw, widx);

    // attention
    attn_tc<<<dim3(S_LEN / 128, NH), 256, ATTN_SMEM>>>();

    // O-proj (needs wo conversion)
    cudaStreamWaitEvent(0, eW2, 0);
    gemm_h<<<dim3(HID / 128, S_LEN / 128), 256, G_SMEM>>>(
        p_ah, p_woh, bo, out, nullptr, HID, NH * HD, 0);
}

// round 14
// speedup vs baseline: 2.4092x; 1.0077x over previous
#include <cuda_runtime.h>
#include <cuda_fp16.h>
#include <cstdint>
#include <math.h>

// Problem constants
#define S_LEN 2048
#define HID 2048
#define NH 16
#define NKV 4
#define HD 128
#define QKV_OUT 3072
#define Q_SZ 2048
#define KV_SZ 512
#define SCALE_Q 0.08838834764831845f

typedef __half f16;

// ---------------- scratch ----------------------------------------------------
__device__ f16 g_qkvh[S_LEN * QKV_OUT];
__device__ f16 g_hidh[S_LEN * HID];
__device__ f16 g_wqh[QKV_OUT * HID];
__device__ f16 g_woh[HID * HID];
__device__ f16 g_qh[S_LEN * NH * HD];
__device__ f16 g_kh[S_LEN * NKV * HD];
__device__ f16 g_vh[S_LEN * NKV * HD];
__device__ f16 g_ah[S_LEN * NH * HD];

// ---------------- helpers ----------------------------------------------------
__device__ __forceinline__ uint32_t smem_u32(const void* p) {
    return (uint32_t)__cvta_generic_to_shared(p);
}
__device__ __forceinline__ uint32_t packh(float lo_v, float hi_v) {
    uint32_t r;
    asm("cvt.rn.f16x2.f32 %0, %1, %2;" : "=r"(r) : "f"(hi_v), "f"(lo_v));
    return r;
}

#define MMA_H2(d, a, b0, b1) \
    asm volatile( \
        "mma.sync.aligned.m16n8k16.row.col.f32.f16.f16.f32 " \
        "{%0,%1,%2,%3}, {%4,%5,%6,%7}, {%8,%9}, {%0,%1,%2,%3};" \
        : "+f"((d)[0]), "+f"((d)[1]), "+f"((d)[2]), "+f"((d)[3]) \
        : "r"((a)[0]), "r"((a)[1]), "r"((a)[2]), "r"((a)[3]), \
          "r"(b0), "r"(b1))

#define LDSM4(r, addr) \
    asm volatile("ldmatrix.sync.aligned.m8n8.x4.shared.b16 {%0,%1,%2,%3}, [%4];" \
        : "=r"((r)[0]), "=r"((r)[1]), "=r"((r)[2]), "=r"((r)[3]) : "r"(addr))

#define LDSM4T(r, addr) \
    asm volatile("ldmatrix.sync.aligned.m8n8.x4.trans.shared.b16 {%0,%1,%2,%3}, [%4];" \
        : "=r"((r)[0]), "=r"((r)[1]), "=r"((r)[2]), "=r"((r)[3]) : "r"(addr))

#define CP16(dst, src) \
    asm volatile("cp.async.cg.shared.global [%0], [%1], 16;" :: "r"(dst), "l"(src))
#define CP_COMMIT() asm volatile("cp.async.commit_group;" ::: "memory")
#define CP_WAIT(n) asm volatile("cp.async.wait_group %0;" :: "n"(n) : "memory")

// ---------------- conversion kernels ----------------------------------------
__global__ void conv_h(const float* __restrict__ src, f16* __restrict__ hi, int n4) {
    __half2* H = (__half2*)hi;
    for (int i = blockIdx.x * blockDim.x + threadIdx.x; i < n4;
         i += gridDim.x * blockDim.x) {
        float4 v = ((const float4*)src)[i];
        H[2 * i] = __floats2half2_rn(v.x, v.y);
        H[2 * i + 1] = __floats2half2_rn(v.z, v.w);
    }
}

__global__ void copy_caches(const float* __restrict__ kc, const float* __restrict__ vc) {
    int n = S_LEN * NKV * HD;
    for (int i = blockIdx.x * blockDim.x + threadIdx.x; i < n;
         i += gridDim.x * blockDim.x) {
        g_kh[i] = __float2half_rn(kc[i]);
        g_vh[i] = __float2half_rn(vc[i]);
    }
}

// ---------------- fused RMSNorm + RoPE + scale + scatter ---------------------
__global__ void norm_rope_scatter(const float* __restrict__ cosb,
                                  const float* __restrict__ sinb,
                                  const float* __restrict__ qw,
                                  const float* __restrict__ kw,
                                  const int* __restrict__ widx) {
    const int s = blockIdx.x;
    const int ty = threadIdx.y;
    const int head = blockIdx.y * 4 + ty;
    const int d = threadIdx.x;
    __shared__ float sh[4][128];
    __shared__ float wsum[4][4];

    int col;
    if (head < 16)      col = head * HD + d;
    else if (head < 20) col = Q_SZ + (head - 16) * HD + d;
    else                col = Q_SZ + KV_SZ + (head - 20) * HD + d;

    float x = __half2float(g_qkvh[(size_t)s * QKV_OUT + col]);

    if (head >= 20) {
        size_t o = ((size_t)widx[s] * NKV + (head - 20)) * HD + d;
        g_vh[o] = __float2half_rn(x);
        return;
    }

    float sq = x * x;
#pragma unroll
    for (int m = 16; m; m >>= 1) sq += __shfl_xor_sync(0xffffffffu, sq, m);
    if ((d & 31) == 0) wsum[ty][d >> 5] = sq;
    __syncthreads();
    float ms = (wsum[ty][0] + wsum[ty][1] + wsum[ty][2] + wsum[ty][3]) * (1.0f / 128.0f);
    float inv = rsqrtf(ms + 1e-6f);
    const float* w = (head < 16) ? qw : kw;
    float y = x * inv * w[d];
    sh[ty][d] = y;
    __syncthreads();

    if (d < 64) {
        float c = cosb[s * 64 + d], sn = sinb[s * 64 + d];
        float x1 = sh[ty][d], x2 = sh[ty][d + 64];
        float y1 = x1 * c - x2 * sn;
        float y2 = x1 * sn + x2 * c;
        if (head < 16) {
            y1 *= SCALE_Q; y2 *= SCALE_Q;
            size_t o = ((size_t)s * NH + head) * HD;
            g_qh[o + d] = __float2half_rn(y1);
            g_qh[o + d + 64] = __float2half_rn(y2);
        } else {
            size_t o = ((size_t)widx[s] * NKV + (head - 16)) * HD;
            g_kh[o + d] = __float2half_rn(y1);
            g_kh[o + d + 64] = __float2half_rn(y2);
        }
    }
}

// =================== pure fp16 GEMM ==========================================
// m_off: row-tile offset (for split launches).
#define GSTRIDE 40
#define GB_E (128 * GSTRIDE)
#define GB_B (GB_E * 2)
#define GSTAGE_B (2 * GB_B)
#define G_SMEM (4 * GSTAGE_B)             // 81920 bytes

__global__ void __launch_bounds__(256)
gemm_h(const f16* __restrict__ Ah_g, const f16* __restrict__ Bh_g,
       const float* __restrict__ bias, float* __restrict__ C,
       f16* __restrict__ Ch, int N, int K, int half_out, int m_off) {
    extern __shared__ f16 smg[];
    const int t = threadIdx.x;
    const int lane = t & 31, wid = t >> 5;
    const int g = lane >> 2, tg = lane & 3;
    const int wm = (wid & 3) * 32, wn = (wid >> 2) * 64;
    const int m0 = (blockIdx.y + m_off) << 7, n0 = blockIdx.x << 7;
    const int nch = K >> 5;

    const int l15 = lane & 15, lh = lane >> 4;
    const uint32_t sb = smem_u32(smg);
    const uint32_t offA = (uint32_t)((wm + l15) * 80 + lh * 16);
    const uint32_t offB = (uint32_t)((wn + l15) * 80 + lh * 16);

    float d[2][8][4];
#pragma unroll
    for (int i = 0; i < 2; i++)
#pragma unroll
        for (int j = 0; j < 8; j++)
#pragma unroll
            for (int q = 0; q < 4; q++) d[i][j][q] = 0.f;

#define G_ISSUE(c) do { \
    uint32_t base = sb + ((c) & 3) * GSTAGE_B; \
    _Pragma("unroll") \
    for (int j = 0; j < 2; j++) { \
        int u = t + (j << 8); int row = u >> 2, q = u & 3; \
        uint32_t dst = base + (uint32_t)(row * GSTRIDE + (q << 3)) * 2; \
        size_t ao = (size_t)(m0 + row) * K + ((c) << 5) + (q << 3); \
        size_t bo = (size_t)(n0 + row) * K + ((c) << 5) + (q << 3); \
        CP16(dst, Ah_g + ao); \
        CP16(dst + GB_B, Bh_g + bo); \
    } } while (0)

    G_ISSUE(0); CP_COMMIT();
    G_ISSUE(1); CP_COMMIT();
    G_ISSUE(2); CP_COMMIT();

    for (int c = 0; c < nch; c++) {
        CP_WAIT(2);
        __syncthreads();
        const uint32_t base = sb + (c & 3) * GSTAGE_B;
#pragma unroll
        for (int ks = 0; ks < 2; ks++) {
            const uint32_t ko = ks * 32;
            uint32_t ah[2][4];
#pragma unroll
            for (int mt = 0; mt < 2; mt++)
                LDSM4(ah[mt], base + offA + mt * 1280 + ko);
#pragma unroll
            for (int jp = 0; jp < 4; jp++) {
                uint32_t bh4[4];
                LDSM4(bh4, base + GB_B + offB + jp * 1280 + ko);
#pragma unroll
                for (int mt = 0; mt < 2; mt++) {
                    MMA_H2(d[mt][2 * jp], ah[mt], bh4[0], bh4[2]);
                    MMA_H2(d[mt][2 * jp + 1], ah[mt], bh4[1], bh4[3]);
                }
            }
        }
        __syncthreads();
        if (c + 3 < nch) { G_ISSUE(c + 3); CP_COMMIT(); }
    }

    // epilogue
#pragma unroll
    for (int i = 0; i < 2; i++) {
        int r = m0 + wm + i * 16 + g;
#pragma unroll
        for (int j = 0; j < 8; j++) {
            int cix = n0 + wn + j * 8 + tg * 2;
            float2 b2 = *(const float2*)(bias + cix);
            float v00 = d[i][j][0] + b2.x, v01 = d[i][j][1] + b2.y;
            float v10 = d[i][j][2] + b2.x, v11 = d[i][j][3] + b2.y;
            if (half_out) {
                *(uint32_t*)(Ch + (size_t)r * N + cix) = packh(v00, v01);
                *(uint32_t*)(Ch + (size_t)(r + 8) * N + cix) = packh(v10, v11);
            } else {
                float2 a0, a1;
                a0.x = v00; a0.y = v01;
                a1.x = v10; a1.y = v11;
                *(float2*)(C + (size_t)r * N + cix) = a0;
                *(float2*)(C + (size_t)(r + 8) * N + cix) = a1;
            }
        }
    }
#undef G_ISSUE
}

// =================== fp16 flash attention ====================================
// qt_base: first q-tile of this launch; qt = qt_base + (gridDim.x-1-bx)
#define APAD 136
#define QBUF_E (128 * APAD)
#define KVBUF_E (64 * APAD)
#define KVBUF_B (KVBUF_E * 2)
#define KVSTAGE_B (2 * KVBUF_B)
#define ATTN_SMEM (QBUF_E * 2 + 2 * KVSTAGE_B)   // 104448 B

__global__ void __launch_bounds__(256, 1) attn_tc(int qt_base) {
    extern __shared__ f16 sma[];
    f16* Qh = sma;

    const int t = threadIdx.x;
    const int lane = t & 31, w = t >> 5;
    const int g = lane >> 2, tg = lane & 3;
    const int qt = qt_base + (gridDim.x - 1 - blockIdx.x);   // heavy first
    const int q0 = qt * 128;
    const int h = blockIdx.y, kvh = h >> 2;
    const int wq = w * 16;

    const uint32_t kvb = smem_u32(sma) + QBUF_E * 2;

#define A_ISSUE(kt) do { \
    uint32_t base = kvb + ((kt) & 1) * KVSTAGE_B; \
    _Pragma("unroll") \
    for (int i = 0; i < 4; i++) { \
        int u = t + (i << 8); int r = u >> 4, cc = u & 15; \
        size_t so = ((size_t)(((kt) << 6) + r) * NKV + kvh) * HD + cc * 8; \
        uint32_t dd = base + (uint32_t)(r * 272 + cc * 16); \
        CP16(dd, g_kh + so); \
        CP16(dd + KVBUF_B, g_vh + so); \
    } } while (0)

    A_ISSUE(0); CP_COMMIT();

#pragma unroll
    for (int i = 0; i < 8; i++) {
        int u = t + i * 256;
        int r = u >> 4, cc = u & 15;
        size_t qo = ((size_t)(q0 + r) * NH + h) * HD + cc * 8;
        *(uint4*)((char*)Qh + r * 272 + cc * 16) = *(const uint4*)(g_qh + qo);
    }

    const int l15 = lane & 15, lh = lane >> 4;
    const uint32_t qb_h = smem_u32(Qh) + (wq + l15) * 272 + lh * 16;
    uint32_t kb[4];
#pragma unroll
    for (int jp = 0; jp < 4; jp++)
        kb[jp] = kvb + (jp * 16 + l15) * 272 + lh * 16;
    const uint32_t vb = kvb + KVBUF_B + l15 * 272 + lh * 16;

    float o[16][4];
#pragma unroll
    for (int dt = 0; dt < 16; dt++)
#pragma unroll
        for (int q = 0; q < 4; q++) o[dt][q] = 0.f;
    float mrow[2] = {-1e30f, -1e30f};
    float lrow[2] = {0.f, 0.f};

    const int nkt = 2 * (qt + 1);
    for (int kt = 0; kt < nkt; kt++) {
        CP_WAIT(0);
        __syncthreads();
        if (kt + 1 < nkt) { A_ISSUE(kt + 1); CP_COMMIT(); }
        const uint32_t kvo = (kt & 1) * KVSTAGE_B;
        const int k0 = kt * 64;

        float s[8][4];
#pragma unroll
        for (int j = 0; j < 8; j++)
#pragma unroll
            for (int q = 0; q < 4; q++) s[j][q] = 0.f;

#pragma unroll
        for (int ks = 0; ks < 8; ks++) {
            const uint32_t ko = ks * 32;
            uint32_t aqh[4];
            LDSM4(aqh, qb_h + ko);
#pragma unroll
            for (int jp = 0; jp < 4; jp++) {
                uint32_t kh4[4];
                LDSM4(kh4, kb[jp] + kvo + ko);
                MMA_H2(s[2 * jp], aqh, kh4[0], kh4[2]);
                MMA_H2(s[2 * jp + 1], aqh, kh4[1], kh4[3]);
            }
        }

        if (kt >= nkt - 2) {
            const int rbase = q0 + wq + g;
#pragma unroll
            for (int j = 0; j < 8; j++) {
                int cg = k0 + 8 * j + 2 * tg;
                if (cg > rbase) s[j][0] = -1e9f;
                if (cg + 1 > rbase) s[j][1] = -1e9f;
                if (cg > rbase + 8) s[j][2] = -1e9f;
                if (cg + 1 > rbase + 8) s[j][3] = -1e9f;
            }
        }

#pragma unroll
        for (int rr = 0; rr < 2; rr++) {
            float tmax = -1e30f;
#pragma unroll
            for (int j = 0; j < 8; j++)
                tmax = fmaxf(tmax, fmaxf(s[j][rr * 2], s[j][rr * 2 + 1]));
            tmax = fmaxf(tmax, __shfl_xor_sync(0xffffffffu, tmax, 1));
            tmax = fmaxf(tmax, __shfl_xor_sync(0xffffffffu, tmax, 2));
            float mnew = fmaxf(mrow[rr], tmax);
            float scalef = __expf(mrow[rr] - mnew);
            mrow[rr] = mnew;
            float tsum = 0.f;
#pragma unroll
            for (int j = 0; j < 8; j++) {
                float p0 = __expf(s[j][rr * 2] - mnew);
                float p1 = __expf(s[j][rr * 2 + 1] - mnew);
                s[j][rr * 2] = p0;
                s[j][rr * 2 + 1] = p1;
                tsum += p0 + p1;
            }
            tsum += __shfl_xor_sync(0xffffffffu, tsum, 1);
            tsum += __shfl_xor_sync(0xffffffffu, tsum, 2);
            lrow[rr] = lrow[rr] * scalef + tsum;
#pragma unroll
            for (int dt = 0; dt < 16; dt++) {
                o[dt][rr * 2] *= scalef;
                o[dt][rr * 2 + 1] *= scalef;
            }
        }

#pragma unroll
        for (int c = 0; c < 4; c++) {
            uint32_t pah[4];
#pragma unroll
            for (int hq = 0; hq < 2; hq++) {
                pah[hq * 2 + 0] = packh(s[2 * c + hq][0], s[2 * c + hq][1]);
                pah[hq * 2 + 1] = packh(s[2 * c + hq][2], s[2 * c + hq][3]);
            }
            const uint32_t vrow = vb + kvo + c * (16 * 272);
#pragma unroll
            for (int dt16 = 0; dt16 < 8; dt16++) {
                uint32_t vh4[4];
                LDSM4T(vh4, vrow + dt16 * 32);
                MMA_H2(o[2 * dt16], pah, vh4[0], vh4[1]);
                MMA_H2(o[2 * dt16 + 1], pah, vh4[2], vh4[3]);
            }
        }
    }

#pragma unroll
    for (int rr = 0; rr < 2; rr++) {
        float invl = 1.0f / lrow[rr];
        int row = q0 + wq + g + rr * 8;
#pragma unroll
        for (int dt = 0; dt < 16; dt++) {
            float x0 = o[dt][rr * 2] * invl;
            float x1 = o[dt][rr * 2 + 1] * invl;
            size_t off = (size_t)row * (NH * HD) + h * HD + dt * 8 + 2 * tg;
            *(uint32_t*)(g_ah + off) = packh(x0, x1);
        }
    }
#undef A_ISSUE
}

// ---------------- launch -----------------------------------------------------
extern "C" void kernel_launch(void* const* d_in, const int* in_sizes, int n_in,
                              void* d_out, int out_size) {
    const float* hidden = (const float*)d_in[0];
    const float* cosb   = (const float*)d_in[1];
    const float* sinb   = (const float*)d_in[2];
    const float* kcache = (const float*)d_in[3];
    const float* vcache = (const float*)d_in[4];
    const float* wqkv   = (const float*)d_in[6];
    const float* bqkv   = (const float*)d_in[7];
    const float* wo     = (const float*)d_in[8];
    const float* bo     = (const float*)d_in[9];
    const float* qw     = (const float*)d_in[10];
    const float* kw     = (const float*)d_in[11];
    const int*   widx   = (const int*)d_in[12];
    float* out = (float*)d_out;

    f16 *p_qkvh, *p_hidh, *p_wqh, *p_woh, *p_ah;
    cudaGetSymbolAddress((void**)&p_qkvh, g_qkvh);
    cudaGetSymbolAddress((void**)&p_hidh, g_hidh);
    cudaGetSymbolAddress((void**)&p_wqh, g_wqh);
    cudaGetSymbolAddress((void**)&p_woh, g_woh);
    cudaGetSymbolAddress((void**)&p_ah, g_ah);

    static cudaStream_t s1 = nullptr, s2 = nullptr;
    static cudaEvent_t eRoot, eW1, eCache, eW2, eAttnA, eOprojA;
    static bool init = false;
    if (!init) {
        cudaStreamCreateWithFlags(&s1, cudaStreamNonBlocking);
        cudaStreamCreateWithFlags(&s2, cudaStreamNonBlocking);
        cudaEventCreateWithFlags(&eRoot, cudaEventDisableTiming);
        cudaEventCreateWithFlags(&eW1, cudaEventDisableTiming);
        cudaEventCreateWithFlags(&eCache, cudaEventDisableTiming);
        cudaEventCreateWithFlags(&eW2, cudaEventDisableTiming);
        cudaEventCreateWithFlags(&eAttnA, cudaEventDisableTiming);
        cudaEventCreateWithFlags(&eOprojA, cudaEventDisableTiming);
        cudaFuncSetAttribute(gemm_h, cudaFuncAttributeMaxDynamicSharedMemorySize, G_SMEM);
        cudaFuncSetAttribute(attn_tc, cudaFuncAttributeMaxDynamicSharedMemorySize, ATTN_SMEM);
        init = true;
    }

    // fork
    cudaEventRecord(eRoot, 0);
    cudaStreamWaitEvent(s1, eRoot, 0);
    cudaStreamWaitEvent(s2, eRoot, 0);

    // main: hidden conversion
    conv_h<<<1024, 256>>>(hidden, p_hidh, S_LEN * HID / 4);
    // s1: wqkv conversion, then caches
    conv_h<<<1024, 256, 0, s1>>>(wqkv, p_wqh, QKV_OUT * HID / 4);
    cudaEventRecord(eW1, s1);
    copy_caches<<<256, 256, 0, s1>>>(kcache, vcache);
    cudaEventRecord(eCache, s1);
    // s2: wo conversion
    conv_h<<<1024, 256, 0, s2>>>(wo, p_woh, HID * HID / 4);
    cudaEventRecord(eW2, s2);

    // QKV GEMM
    cudaStreamWaitEvent(0, eW1, 0);
    gemm_h<<<dim3(QKV_OUT / 128, S_LEN / 128), 256, G_SMEM>>>(
        p_hidh, p_wqh, bqkv, nullptr, p_qkvh, QKV_OUT, HID, 1, 0);

    // norm/rope
    cudaStreamWaitEvent(0, eCache, 0);
    norm_rope_scatter<<<dim3(S_LEN, 6), dim3(128, 4)>>>(cosb, sinb, qw, kw, widx);

    // attention A: heavy q-tiles 8..15 (rows 1024..2047)
    attn_tc<<<dim3(8, NH), 256, ATTN_SMEM>>>(8);
    cudaEventRecord(eAttnA, 0);

    // attention B: light q-tiles 0..7 (rows 0..1023), on main stream
    attn_tc<<<dim3(8, NH), 256, ATTN_SMEM>>>(0);

    // O-proj A on s2: rows 1024..2047, concurrent with attention B
    cudaStreamWaitEvent(s2, eAttnA, 0);
    gemm_h<<<dim3(HID / 128, 8), 256, G_SMEM, s2>>>(
        p_ah, p_woh, bo, out, nullptr, HID, NH * HD, 0, 8);
    cudaEventRecord(eOprojA, s2);

    // O-proj B on main: rows 0..1023 (after attention B; wo already ready)
    cudaStreamWaitEvent(0, eW2, 0);
    gemm_h<<<dim3(HID / 128, 8), 256, G_SMEM>>>(
        p_ah, p_woh, bo, out, nullptr, HID, NH * HD, 0, 0);

    // join s2 back into main
    cudaStreamWaitEvent(0, eOprojA, 0);
}

// round 15
// speedup vs baseline: 2.5892x; 1.0747x over previous
#include <cuda_runtime.h>
#include <cuda_fp16.h>
#include <cstdint>
#include <math.h>

// Problem constants
#define S_LEN 2048
#define HID 2048
#define NH 16
#define NKV 4
#define HD 128
#define QKV_OUT 3072
#define Q_SZ 2048
#define KV_SZ 512
#define SCALE_Q 0.08838834764831845f

typedef __half f16;

// ---------------- scratch ----------------------------------------------------
__device__ f16 g_qkvh[S_LEN * QKV_OUT];
__device__ f16 g_hidh[S_LEN * HID];
__device__ f16 g_wqh[QKV_OUT * HID];
__device__ f16 g_woh[HID * HID];
__device__ f16 g_qh[S_LEN * NH * HD];
__device__ f16 g_kh[S_LEN * NKV * HD];
__device__ f16 g_vh[S_LEN * NKV * HD];
__device__ f16 g_ah[S_LEN * NH * HD];
// split-K partials
__device__ float g_op0[S_LEN * NH * HD];
__device__ float g_op1[S_LEN * NH * HD];
__device__ float2 g_ml0[S_LEN * NH];
__device__ float2 g_ml1[S_LEN * NH];

// ---------------- helpers ----------------------------------------------------
__device__ __forceinline__ uint32_t smem_u32(const void* p) {
    return (uint32_t)__cvta_generic_to_shared(p);
}
__device__ __forceinline__ uint32_t packh(float lo_v, float hi_v) {
    uint32_t r;
    asm("cvt.rn.f16x2.f32 %0, %1, %2;" : "=r"(r) : "f"(hi_v), "f"(lo_v));
    return r;
}

#define MMA_H2(d, a, b0, b1) \
    asm volatile( \
        "mma.sync.aligned.m16n8k16.row.col.f32.f16.f16.f32 " \
        "{%0,%1,%2,%3}, {%4,%5,%6,%7}, {%8,%9}, {%0,%1,%2,%3};" \
        : "+f"((d)[0]), "+f"((d)[1]), "+f"((d)[2]), "+f"((d)[3]) \
        : "r"((a)[0]), "r"((a)[1]), "r"((a)[2]), "r"((a)[3]), \
          "r"(b0), "r"(b1))

#define LDSM4(r, addr) \
    asm volatile("ldmatrix.sync.aligned.m8n8.x4.shared.b16 {%0,%1,%2,%3}, [%4];" \
        : "=r"((r)[0]), "=r"((r)[1]), "=r"((r)[2]), "=r"((r)[3]) : "r"(addr))

#define LDSM4T(r, addr) \
    asm volatile("ldmatrix.sync.aligned.m8n8.x4.trans.shared.b16 {%0,%1,%2,%3}, [%4];" \
        : "=r"((r)[0]), "=r"((r)[1]), "=r"((r)[2]), "=r"((r)[3]) : "r"(addr))

#define CP16(dst, src) \
    asm volatile("cp.async.cg.shared.global [%0], [%1], 16;" :: "r"(dst), "l"(src))
#define CP_COMMIT() asm volatile("cp.async.commit_group;" ::: "memory")
#define CP_WAIT(n) asm volatile("cp.async.wait_group %0;" :: "n"(n) : "memory")

// ---------------- conversion kernels ----------------------------------------
__global__ void conv_h(const float* __restrict__ src, f16* __restrict__ hi, int n4) {
    __half2* H = (__half2*)hi;
    for (int i = blockIdx.x * blockDim.x + threadIdx.x; i < n4;
         i += gridDim.x * blockDim.x) {
        float4 v = ((const float4*)src)[i];
        H[2 * i] = __floats2half2_rn(v.x, v.y);
        H[2 * i + 1] = __floats2half2_rn(v.z, v.w);
    }
}

__global__ void copy_caches(const float* __restrict__ kc, const float* __restrict__ vc) {
    int n = S_LEN * NKV * HD;
    for (int i = blockIdx.x * blockDim.x + threadIdx.x; i < n;
         i += gridDim.x * blockDim.x) {
        g_kh[i] = __float2half_rn(kc[i]);
        g_vh[i] = __float2half_rn(vc[i]);
    }
}

// ---------------- fused RMSNorm + RoPE + scale + scatter ---------------------
__global__ void norm_rope_scatter(const float* __restrict__ cosb,
                                  const float* __restrict__ sinb,
                                  const float* __restrict__ qw,
                                  const float* __restrict__ kw,
                                  const int* __restrict__ widx) {
    const int s = blockIdx.x;
    const int ty = threadIdx.y;
    const int head = blockIdx.y * 4 + ty;
    const int d = threadIdx.x;
    __shared__ float sh[4][128];
    __shared__ float wsum[4][4];

    int col;
    if (head < 16)      col = head * HD + d;
    else if (head < 20) col = Q_SZ + (head - 16) * HD + d;
    else                col = Q_SZ + KV_SZ + (head - 20) * HD + d;

    float x = __half2float(g_qkvh[(size_t)s * QKV_OUT + col]);

    if (head >= 20) {
        size_t o = ((size_t)widx[s] * NKV + (head - 20)) * HD + d;
        g_vh[o] = __float2half_rn(x);
        return;
    }

    float sq = x * x;
#pragma unroll
    for (int m = 16; m; m >>= 1) sq += __shfl_xor_sync(0xffffffffu, sq, m);
    if ((d & 31) == 0) wsum[ty][d >> 5] = sq;
    __syncthreads();
    float ms = (wsum[ty][0] + wsum[ty][1] + wsum[ty][2] + wsum[ty][3]) * (1.0f / 128.0f);
    float inv = rsqrtf(ms + 1e-6f);
    const float* w = (head < 16) ? qw : kw;
    float y = x * inv * w[d];
    sh[ty][d] = y;
    __syncthreads();

    if (d < 64) {
        float c = cosb[s * 64 + d], sn = sinb[s * 64 + d];
        float x1 = sh[ty][d], x2 = sh[ty][d + 64];
        float y1 = x1 * c - x2 * sn;
        float y2 = x1 * sn + x2 * c;
        if (head < 16) {
            y1 *= SCALE_Q; y2 *= SCALE_Q;
            size_t o = ((size_t)s * NH + head) * HD;
            g_qh[o + d] = __float2half_rn(y1);
            g_qh[o + d + 64] = __float2half_rn(y2);
        } else {
            size_t o = ((size_t)widx[s] * NKV + (head - 16)) * HD;
            g_kh[o + d] = __float2half_rn(y1);
            g_kh[o + d + 64] = __float2half_rn(y2);
        }
    }
}

// =================== pure fp16 GEMM ==========================================
#define GSTRIDE 40
#define GB_E (128 * GSTRIDE)
#define GB_B (GB_E * 2)
#define GSTAGE_B (2 * GB_B)
#define G_SMEM (4 * GSTAGE_B)             // 81920 bytes

__global__ void __launch_bounds__(256)
gemm_h(const f16* __restrict__ Ah_g, const f16* __restrict__ Bh_g,
       const float* __restrict__ bias, float* __restrict__ C,
       f16* __restrict__ Ch, int N, int K, int half_out) {
    extern __shared__ f16 smg[];
    const int t = threadIdx.x;
    const int lane = t & 31, wid = t >> 5;
    const int g = lane >> 2, tg = lane & 3;
    const int wm = (wid & 3) * 32, wn = (wid >> 2) * 64;
    const int m0 = blockIdx.y << 7, n0 = blockIdx.x << 7;
    const int nch = K >> 5;

    const int l15 = lane & 15, lh = lane >> 4;
    const uint32_t sb = smem_u32(smg);
    const uint32_t offA = (uint32_t)((wm + l15) * 80 + lh * 16);
    const uint32_t offB = (uint32_t)((wn + l15) * 80 + lh * 16);

    float d[2][8][4];
#pragma unroll
    for (int i = 0; i < 2; i++)
#pragma unroll
        for (int j = 0; j < 8; j++)
#pragma unroll
            for (int q = 0; q < 4; q++) d[i][j][q] = 0.f;

#define G_ISSUE(c) do { \
    uint32_t base = sb + ((c) & 3) * GSTAGE_B; \
    _Pragma("unroll") \
    for (int j = 0; j < 2; j++) { \
        int u = t + (j << 8); int row = u >> 2, q = u & 3; \
        uint32_t dst = base + (uint32_t)(row * GSTRIDE + (q << 3)) * 2; \
        size_t ao = (size_t)(m0 + row) * K + ((c) << 5) + (q << 3); \
        size_t bo = (size_t)(n0 + row) * K + ((c) << 5) + (q << 3); \
        CP16(dst, Ah_g + ao); \
        CP16(dst + GB_B, Bh_g + bo); \
    } } while (0)

    G_ISSUE(0); CP_COMMIT();
    G_ISSUE(1); CP_COMMIT();
    G_ISSUE(2); CP_COMMIT();

    for (int c = 0; c < nch; c++) {
        CP_WAIT(2);
        __syncthreads();
        const uint32_t base = sb + (c & 3) * GSTAGE_B;
#pragma unroll
        for (int ks = 0; ks < 2; ks++) {
            const uint32_t ko = ks * 32;
            uint32_t ah[2][4];
#pragma unroll
            for (int mt = 0; mt < 2; mt++)
                LDSM4(ah[mt], base + offA + mt * 1280 + ko);
#pragma unroll
            for (int jp = 0; jp < 4; jp++) {
                uint32_t bh4[4];
                LDSM4(bh4, base + GB_B + offB + jp * 1280 + ko);
#pragma unroll
                for (int mt = 0; mt < 2; mt++) {
                    MMA_H2(d[mt][2 * jp], ah[mt], bh4[0], bh4[2]);
                    MMA_H2(d[mt][2 * jp + 1], ah[mt], bh4[1], bh4[3]);
                }
            }
        }
        __syncthreads();
        if (c + 3 < nch) { G_ISSUE(c + 3); CP_COMMIT(); }
    }

    // epilogue
#pragma unroll
    for (int i = 0; i < 2; i++) {
        int r = m0 + wm + i * 16 + g;
#pragma unroll
        for (int j = 0; j < 8; j++) {
            int cix = n0 + wn + j * 8 + tg * 2;
            float2 b2 = *(const float2*)(bias + cix);
            float v00 = d[i][j][0] + b2.x, v01 = d[i][j][1] + b2.y;
            float v10 = d[i][j][2] + b2.x, v11 = d[i][j][3] + b2.y;
            if (half_out) {
                *(uint32_t*)(Ch + (size_t)r * N + cix) = packh(v00, v01);
                *(uint32_t*)(Ch + (size_t)(r + 8) * N + cix) = packh(v10, v11);
            } else {
                float2 a0, a1;
                a0.x = v00; a0.y = v01;
                a1.x = v10; a1.y = v11;
                *(float2*)(C + (size_t)r * N + cix) = a0;
                *(float2*)(C + (size_t)(r + 8) * N + cix) = a1;
            }
        }
    }
#undef G_ISSUE
}

// =================== fp16 flash attention, split-K ===========================
// grid (NH, 32): y -> (qt, part): qt = 15 - (y>>1), part = y&1 (heavy first).
// Each chunk covers k-tiles [part*(qt+1), (part+1)*(qt+1)) of 64 keys.
// Emits unnormalized fp32 partial O + per-row (m, l).
#define APAD 136
#define QBUF_E (128 * APAD)
#define KVBUF_E (64 * APAD)
#define KVBUF_B (KVBUF_E * 2)
#define KVSTAGE_B (2 * KVBUF_B)
#define ATTN_SMEM (QBUF_E * 2 + 2 * KVSTAGE_B)   // 104448 B

__global__ void __launch_bounds__(256, 1) attn_tc() {
    extern __shared__ f16 sma[];
    f16* Qh = sma;

    const int t = threadIdx.x;
    const int lane = t & 31, w = t >> 5;
    const int g = lane >> 2, tg = lane & 3;
    const int qt = 15 - (blockIdx.y >> 1);
    const int part = blockIdx.y & 1;
    const int q0 = qt * 128;
    const int h = blockIdx.x, kvh = h >> 2;
    const int wq = w * 16;

    float* g_op = part ? g_op1 : g_op0;
    float2* g_ml = part ? g_ml1 : g_ml0;

    const uint32_t kvb = smem_u32(sma) + QBUF_E * 2;

#define A_ISSUE(kt) do { \
    uint32_t base = kvb + ((kt) & 1) * KVSTAGE_B; \
    _Pragma("unroll") \
    for (int i = 0; i < 4; i++) { \
        int u = t + (i << 8); int r = u >> 4, cc = u & 15; \
        size_t so = ((size_t)(((kt) << 6) + r) * NKV + kvh) * HD + cc * 8; \
        uint32_t dd = base + (uint32_t)(r * 272 + cc * 16); \
        CP16(dd, g_kh + so); \
        CP16(dd + KVBUF_B, g_vh + so); \
    } } while (0)

    const int kt0 = part * (qt + 1);
    const int kt1 = kt0 + (qt + 1);
    const int nkt = 2 * (qt + 1);

    A_ISSUE(kt0); CP_COMMIT();

#pragma unroll
    for (int i = 0; i < 8; i++) {
        int u = t + i * 256;
        int r = u >> 4, cc = u & 15;
        size_t qo = ((size_t)(q0 + r) * NH + h) * HD + cc * 8;
        *(uint4*)((char*)Qh + r * 272 + cc * 16) = *(const uint4*)(g_qh + qo);
    }

    const int l15 = lane & 15, lh = lane >> 4;
    const uint32_t qb_h = smem_u32(Qh) + (wq + l15) * 272 + lh * 16;
    uint32_t kb[4];
#pragma unroll
    for (int jp = 0; jp < 4; jp++)
        kb[jp] = kvb + (jp * 16 + l15) * 272 + lh * 16;
    const uint32_t vb = kvb + KVBUF_B + l15 * 272 + lh * 16;

    float o[16][4];
#pragma unroll
    for (int dt = 0; dt < 16; dt++)
#pragma unroll
        for (int q = 0; q < 4; q++) o[dt][q] = 0.f;
    float mrow[2] = {-1e30f, -1e30f};
    float lrow[2] = {0.f, 0.f};

    for (int kt = kt0; kt < kt1; kt++) {
        CP_WAIT(0);
        __syncthreads();
        if (kt + 1 < kt1) { A_ISSUE(kt + 1); CP_COMMIT(); }
        const uint32_t kvo = (kt & 1) * KVSTAGE_B;
        const int k0 = kt * 64;

        float s[8][4];
#pragma unroll
        for (int j = 0; j < 8; j++)
#pragma unroll
            for (int q = 0; q < 4; q++) s[j][q] = 0.f;

#pragma unroll
        for (int ks = 0; ks < 8; ks++) {
            const uint32_t ko = ks * 32;
            uint32_t aqh[4];
            LDSM4(aqh, qb_h + ko);
#pragma unroll
            for (int jp = 0; jp < 4; jp++) {
                uint32_t kh4[4];
                LDSM4(kh4, kb[jp] + kvo + ko);
                MMA_H2(s[2 * jp], aqh, kh4[0], kh4[2]);
                MMA_H2(s[2 * jp + 1], aqh, kh4[1], kh4[3]);
            }
        }

        if (kt >= nkt - 2) {   // global causal boundary tiles
            const int rbase = q0 + wq + g;
#pragma unroll
            for (int j = 0; j < 8; j++) {
                int cg = k0 + 8 * j + 2 * tg;
                if (cg > rbase) s[j][0] = -1e9f;
                if (cg + 1 > rbase) s[j][1] = -1e9f;
                if (cg > rbase + 8) s[j][2] = -1e9f;
                if (cg + 1 > rbase + 8) s[j][3] = -1e9f;
            }
        }

#pragma unroll
        for (int rr = 0; rr < 2; rr++) {
            float tmax = -1e30f;
#pragma unroll
            for (int j = 0; j < 8; j++)
                tmax = fmaxf(tmax, fmaxf(s[j][rr * 2], s[j][rr * 2 + 1]));
            tmax = fmaxf(tmax, __shfl_xor_sync(0xffffffffu, tmax, 1));
            tmax = fmaxf(tmax, __shfl_xor_sync(0xffffffffu, tmax, 2));
            float mnew = fmaxf(mrow[rr], tmax);
            float scalef = __expf(mrow[rr] - mnew);
            mrow[rr] = mnew;
            float tsum = 0.f;
#pragma unroll
            for (int j = 0; j < 8; j++) {
                float p0 = __expf(s[j][rr * 2] - mnew);
                float p1 = __expf(s[j][rr * 2 + 1] - mnew);
                s[j][rr * 2] = p0;
                s[j][rr * 2 + 1] = p1;
                tsum += p0 + p1;
            }
            tsum += __shfl_xor_sync(0xffffffffu, tsum, 1);
            tsum += __shfl_xor_sync(0xffffffffu, tsum, 2);
            lrow[rr] = lrow[rr] * scalef + tsum;
#pragma unroll
            for (int dt = 0; dt < 16; dt++) {
                o[dt][rr * 2] *= scalef;
                o[dt][rr * 2 + 1] *= scalef;
            }
        }

#pragma unroll
        for (int c = 0; c < 4; c++) {
            uint32_t pah[4];
#pragma unroll
            for (int hq = 0; hq < 2; hq++) {
                pah[hq * 2 + 0] = packh(s[2 * c + hq][0], s[2 * c + hq][1]);
                pah[hq * 2 + 1] = packh(s[2 * c + hq][2], s[2 * c + hq][3]);
            }
            const uint32_t vrow = vb + kvo + c * (16 * 272);
#pragma unroll
            for (int dt16 = 0; dt16 < 8; dt16++) {
                uint32_t vh4[4];
                LDSM4T(vh4, vrow + dt16 * 32);
                MMA_H2(o[2 * dt16], pah, vh4[0], vh4[1]);
                MMA_H2(o[2 * dt16 + 1], pah, vh4[2], vh4[3]);
            }
        }
    }

    // ---- epilogue: unnormalized fp32 partials + (m, l) ----
#pragma unroll
    for (int rr = 0; rr < 2; rr++) {
        int row = q0 + wq + g + rr * 8;
        if (tg == 0) {
            float2 ml; ml.x = mrow[rr]; ml.y = lrow[rr];
            g_ml[row * NH + h] = ml;
        }
#pragma unroll
        for (int dt = 0; dt < 16; dt++) {
            float2 v;
            v.x = o[dt][rr * 2];
            v.y = o[dt][rr * 2 + 1];
            *(float2*)(g_op + (size_t)row * (NH * HD) + h * HD + dt * 8 + 2 * tg) = v;
        }
    }
#undef A_ISSUE
}

// ---------------- split-K combine --------------------------------------------
__global__ void combine_attn() {
    int i = blockIdx.x * blockDim.x + threadIdx.x;   // one float4 per thread
    int base = i * 4;
    int row = base >> 11;            // NH*HD = 2048 per row
    int h = (base & 2047) >> 7;
    float2 ml0 = g_ml0[row * NH + h];
    float2 ml1 = g_ml1[row * NH + h];
    float M = fmaxf(ml0.x, ml1.x);
    float w0 = __expf(ml0.x - M), w1 = __expf(ml1.x - M);
    float invl = 1.0f / (ml0.y * w0 + ml1.y * w1);
    float4 a = *(const float4*)(g_op0 + base);
    float4 b = *(const float4*)(g_op1 + base);
    float x0 = (a.x * w0 + b.x * w1) * invl;
    float x1 = (a.y * w0 + b.y * w1) * invl;
    float x2 = (a.z * w0 + b.z * w1) * invl;
    float x3 = (a.w * w0 + b.w * w1) * invl;
    uint2 r;
    r.x = packh(x0, x1);
    r.y = packh(x2, x3);
    *(uint2*)(g_ah + base) = r;
}

// ---------------- launch -----------------------------------------------------
extern "C" void kernel_launch(void* const* d_in, const int* in_sizes, int n_in,
                              void* d_out, int out_size) {
    const float* hidden = (const float*)d_in[0];
    const float* cosb   = (const float*)d_in[1];
    const float* sinb   = (const float*)d_in[2];
    const float* kcache = (const float*)d_in[3];
    const float* vcache = (const float*)d_in[4];
    const float* wqkv   = (const float*)d_in[6];
    const float* bqkv   = (const float*)d_in[7];
    const float* wo     = (const float*)d_in[8];
    const float* bo     = (const float*)d_in[9];
    const float* qw     = (const float*)d_in[10];
    const float* kw     = (const float*)d_in[11];
    const int*   widx   = (const int*)d_in[12];
    float* out = (float*)d_out;

    f16 *p_qkvh, *p_hidh, *p_wqh, *p_woh, *p_ah;
    cudaGetSymbolAddress((void**)&p_qkvh, g_qkvh);
    cudaGetSymbolAddress((void**)&p_hidh, g_hidh);
    cudaGetSymbolAddress((void**)&p_wqh, g_wqh);
    cudaGetSymbolAddress((void**)&p_woh, g_woh);
    cudaGetSymbolAddress((void**)&p_ah, g_ah);

    static cudaStream_t s1 = nullptr, s2 = nullptr;
    static cudaEvent_t eRoot, eW1, eCache, eW2;
    static bool init = false;
    if (!init) {
        cudaStreamCreateWithFlags(&s1, cudaStreamNonBlocking);
        cudaStreamCreateWithFlags(&s2, cudaStreamNonBlocking);
        cudaEventCreateWithFlags(&eRoot, cudaEventDisableTiming);
        cudaEventCreateWithFlags(&eW1, cudaEventDisableTiming);
        cudaEventCreateWithFlags(&eCache, cudaEventDisableTiming);
        cudaEventCreateWithFlags(&eW2, cudaEventDisableTiming);
        cudaFuncSetAttribute(gemm_h, cudaFuncAttributeMaxDynamicSharedMemorySize, G_SMEM);
        cudaFuncSetAttribute(attn_tc, cudaFuncAttributeMaxDynamicSharedMemorySize, ATTN_SMEM);
        init = true;
    }

    // fork
    cudaEventRecord(eRoot, 0);
    cudaStreamWaitEvent(s1, eRoot, 0);
    cudaStreamWaitEvent(s2, eRoot, 0);

    conv_h<<<1024, 256>>>(hidden, p_hidh, S_LEN * HID / 4);
    conv_h<<<1024, 256, 0, s1>>>(wqkv, p_wqh, QKV_OUT * HID / 4);
    cudaEventRecord(eW1, s1);
    copy_caches<<<256, 256, 0, s1>>>(kcache, vcache);
    cudaEventRecord(eCache, s1);
    conv_h<<<1024, 256, 0, s2>>>(wo, p_woh, HID * HID / 4);
    cudaEventRecord(eW2, s2);

    cudaStreamWaitEvent(0, eW1, 0);
    gemm_h<<<dim3(QKV_OUT / 128, S_LEN / 128), 256, G_SMEM>>>(
        p_hidh, p_wqh, bqkv, nullptr, p_qkvh, QKV_OUT, HID, 1);

    cudaStreamWaitEvent(0, eCache, 0);
    norm_rope_scatter<<<dim3(S_LEN, 6), dim3(128, 4)>>>(cosb, sinb, qw, kw, widx);

    // split-K attention: 512 chunk-CTAs, heavy chunks scheduled first
    attn_tc<<<dim3(NH, 32), 256, ATTN_SMEM>>>();

    // combine partials -> g_ah (fp16)
    combine_attn<<<(S_LEN * NH * HD / 4) / 256, 256>>>();

    // O-proj
    cudaStreamWaitEvent(0, eW2, 0);
    gemm_h<<<dim3(HID / 128, S_LEN / 128), 256, G_SMEM>>>(
        p_ah, p_woh, bo, out, nullptr, HID, NH * HD, 0);
}

// round 16
// speedup vs baseline: 2.7106x; 1.0469x over previous
#include <cuda_runtime.h>
#include <cuda_fp16.h>
#include <cstdint>
#include <math.h>

// Problem constants
#define S_LEN 2048
#define HID 2048
#define NH 16
#define NKV 4
#define HD 128
#define QKV_OUT 3072
#define Q_SZ 2048
#define KV_SZ 512
#define SCALE_Q 0.08838834764831845f

typedef __half f16;

// ---------------- scratch ----------------------------------------------------
__device__ f16 g_hidh[S_LEN * HID];
__device__ f16 g_wqh[QKV_OUT * HID];
__device__ f16 g_woh[HID * HID];
__device__ f16 g_qh[S_LEN * NH * HD];
__device__ f16 g_kh[S_LEN * NKV * HD];
__device__ f16 g_vh[S_LEN * NKV * HD];
__device__ f16 g_ah[S_LEN * NH * HD];
// split-K partials (fp16 unnormalized O, fp32 m/l)
__device__ f16 g_op0h[S_LEN * NH * HD];
__device__ f16 g_op1h[S_LEN * NH * HD];
__device__ float2 g_ml0[S_LEN * NH];
__device__ float2 g_ml1[S_LEN * NH];

// ---------------- helpers ----------------------------------------------------
__device__ __forceinline__ uint32_t smem_u32(const void* p) {
    return (uint32_t)__cvta_generic_to_shared(p);
}
__device__ __forceinline__ uint32_t packh(float lo_v, float hi_v) {
    uint32_t r;
    asm("cvt.rn.f16x2.f32 %0, %1, %2;" : "=r"(r) : "f"(hi_v), "f"(lo_v));
    return r;
}
__device__ __forceinline__ float2 unp(uint32_t u) {
    __half2 h = *(__half2*)&u;
    return __half22float2(h);
}

#define MMA_H2(d, a, b0, b1) \
    asm volatile( \
        "mma.sync.aligned.m16n8k16.row.col.f32.f16.f16.f32 " \
        "{%0,%1,%2,%3}, {%4,%5,%6,%7}, {%8,%9}, {%0,%1,%2,%3};" \
        : "+f"((d)[0]), "+f"((d)[1]), "+f"((d)[2]), "+f"((d)[3]) \
        : "r"((a)[0]), "r"((a)[1]), "r"((a)[2]), "r"((a)[3]), \
          "r"(b0), "r"(b1))

#define LDSM4(r, addr) \
    asm volatile("ldmatrix.sync.aligned.m8n8.x4.shared.b16 {%0,%1,%2,%3}, [%4];" \
        : "=r"((r)[0]), "=r"((r)[1]), "=r"((r)[2]), "=r"((r)[3]) : "r"(addr))

#define LDSM4T(r, addr) \
    asm volatile("ldmatrix.sync.aligned.m8n8.x4.trans.shared.b16 {%0,%1,%2,%3}, [%4];" \
        : "=r"((r)[0]), "=r"((r)[1]), "=r"((r)[2]), "=r"((r)[3]) : "r"(addr))

#define CP16(dst, src) \
    asm volatile("cp.async.cg.shared.global [%0], [%1], 16;" :: "r"(dst), "l"(src))
#define CP_COMMIT() asm volatile("cp.async.commit_group;" ::: "memory")
#define CP_WAIT(n) asm volatile("cp.async.wait_group %0;" :: "n"(n) : "memory")

// ---------------- conversion kernels ----------------------------------------
__global__ void conv_h(const float* __restrict__ src, f16* __restrict__ hi, int n4) {
    __half2* H = (__half2*)hi;
    for (int i = blockIdx.x * blockDim.x + threadIdx.x; i < n4;
         i += gridDim.x * blockDim.x) {
        float4 v = ((const float4*)src)[i];
        H[2 * i] = __floats2half2_rn(v.x, v.y);
        H[2 * i + 1] = __floats2half2_rn(v.z, v.w);
    }
}

__global__ void copy_caches(const float* __restrict__ kc, const float* __restrict__ vc) {
    int n = S_LEN * NKV * HD;
    for (int i = blockIdx.x * blockDim.x + threadIdx.x; i < n;
         i += gridDim.x * blockDim.x) {
        g_kh[i] = __float2half_rn(kc[i]);
        g_vh[i] = __float2half_rn(vc[i]);
    }
}

// =================== fp16 GEMM with optional fused QKV epilogue ==============
// mode 0: C[M,N] fp32 out + bias (O-proj).
// mode 2: QKV fused epilogue — n-tile == head; RMSNorm+RoPE+scatter in-CTA.
#define GSTRIDE 40
#define GB_E (128 * GSTRIDE)
#define GB_B (GB_E * 2)
#define GSTAGE_B (2 * GB_B)
#define G_SMEM (4 * GSTAGE_B)             // 81920 bytes

__global__ void __launch_bounds__(256)
gemm_h(const f16* __restrict__ Ah_g, const f16* __restrict__ Bh_g,
       const float* __restrict__ bias, float* __restrict__ C,
       int N, int K, int mode,
       const float* __restrict__ qw, const float* __restrict__ kw,
       const float* __restrict__ cosb, const float* __restrict__ sinb,
       const int* __restrict__ widx) {
    extern __shared__ f16 smg[];
    const int t = threadIdx.x;
    const int lane = t & 31, wid = t >> 5;
    const int g = lane >> 2, tg = lane & 3;
    const int wm = (wid & 3) * 32, wn = (wid >> 2) * 64;
    const int m0 = blockIdx.y << 7, n0 = blockIdx.x << 7;
    const int nch = K >> 5;

    const int l15 = lane & 15, lh = lane >> 4;
    const uint32_t sb = smem_u32(smg);
    const uint32_t offA = (uint32_t)((wm + l15) * 80 + lh * 16);
    const uint32_t offB = (uint32_t)((wn + l15) * 80 + lh * 16);

    float d[2][8][4];
#pragma unroll
    for (int i = 0; i < 2; i++)
#pragma unroll
        for (int j = 0; j < 8; j++)
#pragma unroll
            for (int q = 0; q < 4; q++) d[i][j][q] = 0.f;

#define G_ISSUE(c) do { \
    uint32_t base = sb + ((c) & 3) * GSTAGE_B; \
    _Pragma("unroll") \
    for (int j = 0; j < 2; j++) { \
        int u = t + (j << 8); int row = u >> 2, q = u & 3; \
        uint32_t dst = base + (uint32_t)(row * GSTRIDE + (q << 3)) * 2; \
        size_t ao = (size_t)(m0 + row) * K + ((c) << 5) + (q << 3); \
        size_t bo = (size_t)(n0 + row) * K + ((c) << 5) + (q << 3); \
        CP16(dst, Ah_g + ao); \
        CP16(dst + GB_B, Bh_g + bo); \
    } } while (0)

    G_ISSUE(0); CP_COMMIT();
    G_ISSUE(1); CP_COMMIT();
    G_ISSUE(2); CP_COMMIT();

    for (int c = 0; c < nch; c++) {
        CP_WAIT(2);
        __syncthreads();
        const uint32_t base = sb + (c & 3) * GSTAGE_B;
#pragma unroll
        for (int ks = 0; ks < 2; ks++) {
            const uint32_t ko = ks * 32;
            uint32_t ah[2][4];
#pragma unroll
            for (int mt = 0; mt < 2; mt++)
                LDSM4(ah[mt], base + offA + mt * 1280 + ko);
#pragma unroll
            for (int jp = 0; jp < 4; jp++) {
                uint32_t bh4[4];
                LDSM4(bh4, base + GB_B + offB + jp * 1280 + ko);
#pragma unroll
                for (int mt = 0; mt < 2; mt++) {
                    MMA_H2(d[mt][2 * jp], ah[mt], bh4[0], bh4[2]);
                    MMA_H2(d[mt][2 * jp + 1], ah[mt], bh4[1], bh4[3]);
                }
            }
        }
        __syncthreads();
        if (c + 3 < nch) { G_ISSUE(c + 3); CP_COMMIT(); }
    }

    // ---- add bias (both modes) ----
#pragma unroll
    for (int i = 0; i < 2; i++)
#pragma unroll
        for (int j = 0; j < 8; j++) {
            int cix = n0 + wn + j * 8 + tg * 2;
            float2 b2 = *(const float2*)(bias + cix);
            d[i][j][0] += b2.x; d[i][j][1] += b2.y;
            d[i][j][2] += b2.x; d[i][j][3] += b2.y;
        }

    if (mode == 0) {
#pragma unroll
        for (int i = 0; i < 2; i++) {
            int r = m0 + wm + i * 16 + g;
#pragma unroll
            for (int j = 0; j < 8; j++) {
                int cix = n0 + wn + j * 8 + tg * 2;
                float2 a0, a1;
                a0.x = d[i][j][0]; a0.y = d[i][j][1];
                a1.x = d[i][j][2]; a1.y = d[i][j][3];
                *(float2*)(C + (size_t)r * N + cix) = a0;
                *(float2*)(C + (size_t)(r + 8) * N + cix) = a1;
            }
        }
        return;
    }

    // ---- mode 2: fused QKV epilogue. n-tile == head (0..23). ----
    const int head = blockIdx.x;
    if (head >= 20) {  // V: convert + scatter
#pragma unroll
        for (int i = 0; i < 2; i++)
#pragma unroll
            for (int rr = 0; rr < 2; rr++) {
                int row = wm + 16 * i + g + 8 * rr;
                int s = m0 + row;
                size_t ob = ((size_t)widx[s] * NKV + (head - 20)) * HD;
#pragma unroll
                for (int j = 0; j < 8; j++) {
                    int col = wn + 8 * j + 2 * tg;
                    *(uint32_t*)(g_vh + ob + col) =
                        packh(d[i][j][2 * rr], d[i][j][2 * rr + 1]);
                }
            }
        return;
    }

    // Q/K: RMS norm over the 128-dim head (CTA-local), then RoPE + scatter.
    float* ytile = (float*)smg;            // [128][132] fp32
    float* psum = ytile + 128 * 132;       // [2][128]

    float ss[2][2] = {{0.f, 0.f}, {0.f, 0.f}};
#pragma unroll
    for (int i = 0; i < 2; i++)
#pragma unroll
        for (int j = 0; j < 8; j++) {
            ss[i][0] += d[i][j][0] * d[i][j][0] + d[i][j][1] * d[i][j][1];
            ss[i][1] += d[i][j][2] * d[i][j][2] + d[i][j][3] * d[i][j][3];
        }
#pragma unroll
    for (int i = 0; i < 2; i++)
#pragma unroll
        for (int rr = 0; rr < 2; rr++) {
            ss[i][rr] += __shfl_xor_sync(0xffffffffu, ss[i][rr], 1);
            ss[i][rr] += __shfl_xor_sync(0xffffffffu, ss[i][rr], 2);
        }
    const int half = wid >> 2;
    if (tg == 0) {
#pragma unroll
        for (int i = 0; i < 2; i++) {
            psum[half * 128 + wm + 16 * i + g] = ss[i][0];
            psum[half * 128 + wm + 16 * i + g + 8] = ss[i][1];
        }
    }
    __syncthreads();

    const float* wv = (head < 16) ? qw : kw;
#pragma unroll
    for (int i = 0; i < 2; i++)
#pragma unroll
        for (int rr = 0; rr < 2; rr++) {
            int row = wm + 16 * i + g + 8 * rr;
            float inv = rsqrtf((psum[row] + psum[128 + row]) * (1.0f / 128.0f) + 1e-6f);
#pragma unroll
            for (int j = 0; j < 8; j++) {
                int col = wn + 8 * j + 2 * tg;
                ytile[row * 132 + col] = d[i][j][2 * rr] * inv * wv[col];
                ytile[row * 132 + col + 1] = d[i][j][2 * rr + 1] * inv * wv[col + 1];
            }
        }
    __syncthreads();

    if (half == 0) {  // warps 0..3 handle RoPE for all 128 cols (pairs d, d+64)
        const bool isQ = (head < 16);
        const float scale = isQ ? SCALE_Q : 1.0f;
        f16* dstb = isQ ? g_qh : g_kh;
#pragma unroll
        for (int i = 0; i < 2; i++)
#pragma unroll
            for (int rr = 0; rr < 2; rr++) {
                int row = wm + 16 * i + g + 8 * rr;
                int s = m0 + row;
                size_t ob = isQ ? ((size_t)s * NH + head) * HD
                                : ((size_t)widx[s] * NKV + (head - 16)) * HD;
#pragma unroll
                for (int j = 0; j < 8; j++) {
                    int c0 = 8 * j + 2 * tg;
                    float x1a = ytile[row * 132 + c0];
                    float x1b = ytile[row * 132 + c0 + 1];
                    float x2a = ytile[row * 132 + c0 + 64];
                    float x2b = ytile[row * 132 + c0 + 65];
                    float ca = cosb[s * 64 + c0], sa = sinb[s * 64 + c0];
                    float cb = cosb[s * 64 + c0 + 1], sb2 = sinb[s * 64 + c0 + 1];
                    float y1a = (x1a * ca - x2a * sa) * scale;
                    float y1b = (x1b * cb - x2b * sb2) * scale;
                    float y2a = (x1a * sa + x2a * ca) * scale;
                    float y2b = (x1b * sb2 + x2b * cb) * scale;
                    *(uint32_t*)(dstb + ob + c0) = packh(y1a, y1b);
                    *(uint32_t*)(dstb + ob + c0 + 64) = packh(y2a, y2b);
                }
            }
    }
#undef G_ISSUE
}

// =================== fp16 flash attention, split-K ===========================
#define APAD 136
#define QBUF_E (128 * APAD)
#define KVBUF_E (64 * APAD)
#define KVBUF_B (KVBUF_E * 2)
#define KVSTAGE_B (2 * KVBUF_B)
#define ATTN_SMEM (QBUF_E * 2 + 2 * KVSTAGE_B)   // 104448 B

__global__ void __launch_bounds__(256, 1) attn_tc() {
    extern __shared__ f16 sma[];
    f16* Qh = sma;

    const int t = threadIdx.x;
    const int lane = t & 31, w = t >> 5;
    const int g = lane >> 2, tg = lane & 3;
    const int qt = 15 - (blockIdx.y >> 1);
    const int part = blockIdx.y & 1;
    const int q0 = qt * 128;
    const int h = blockIdx.x, kvh = h >> 2;
    const int wq = w * 16;

    f16* g_op = part ? g_op1h : g_op0h;
    float2* g_ml = part ? g_ml1 : g_ml0;

    const uint32_t kvb = smem_u32(sma) + QBUF_E * 2;

#define A_ISSUE(kt) do { \
    uint32_t base = kvb + ((kt) & 1) * KVSTAGE_B; \
    _Pragma("unroll") \
    for (int i = 0; i < 4; i++) { \
        int u = t + (i << 8); int r = u >> 4, cc = u & 15; \
        size_t so = ((size_t)(((kt) << 6) + r) * NKV + kvh) * HD + cc * 8; \
        uint32_t dd = base + (uint32_t)(r * 272 + cc * 16); \
        CP16(dd, g_kh + so); \
        CP16(dd + KVBUF_B, g_vh + so); \
    } } while (0)

    const int kt0 = part * (qt + 1);
    const int kt1 = kt0 + (qt + 1);
    const int nkt = 2 * (qt + 1);

    A_ISSUE(kt0); CP_COMMIT();

#pragma unroll
    for (int i = 0; i < 8; i++) {
        int u = t + i * 256;
        int r = u >> 4, cc = u & 15;
        size_t qo = ((size_t)(q0 + r) * NH + h) * HD + cc * 8;
        *(uint4*)((char*)Qh + r * 272 + cc * 16) = *(const uint4*)(g_qh + qo);
    }

    const int l15 = lane & 15, lh = lane >> 4;
    const uint32_t qb_h = smem_u32(Qh) + (wq + l15) * 272 + lh * 16;
    uint32_t kb[4];
#pragma unroll
    for (int jp = 0; jp < 4; jp++)
        kb[jp] = kvb + (jp * 16 + l15) * 272 + lh * 16;
    const uint32_t vb = kvb + KVBUF_B + l15 * 272 + lh * 16;

    float o[16][4];
#pragma unroll
    for (int dt = 0; dt < 16; dt++)
#pragma unroll
        for (int q = 0; q < 4; q++) o[dt][q] = 0.f;
    float mrow[2] = {-1e30f, -1e30f};
    float lrow[2] = {0.f, 0.f};

    for (int kt = kt0; kt < kt1; kt++) {
        CP_WAIT(0);
        __syncthreads();
        if (kt + 1 < kt1) { A_ISSUE(kt + 1); CP_COMMIT(); }
        const uint32_t kvo = (kt & 1) * KVSTAGE_B;
        const int k0 = kt * 64;

        float s[8][4];
#pragma unroll
        for (int j = 0; j < 8; j++)
#pragma unroll
            for (int q = 0; q < 4; q++) s[j][q] = 0.f;

#pragma unroll
        for (int ks = 0; ks < 8; ks++) {
            const uint32_t ko = ks * 32;
            uint32_t aqh[4];
            LDSM4(aqh, qb_h + ko);
#pragma unroll
            for (int jp = 0; jp < 4; jp++) {
                uint32_t kh4[4];
                LDSM4(kh4, kb[jp] + kvo + ko);
                MMA_H2(s[2 * jp], aqh, kh4[0], kh4[2]);
                MMA_H2(s[2 * jp + 1], aqh, kh4[1], kh4[3]);
            }
        }

        if (kt >= nkt - 2) {
            const int rbase = q0 + wq + g;
#pragma unroll
            for (int j = 0; j < 8; j++) {
                int cg = k0 + 8 * j + 2 * tg;
                if (cg > rbase) s[j][0] = -1e9f;
                if (cg + 1 > rbase) s[j][1] = -1e9f;
                if (cg > rbase + 8) s[j][2] = -1e9f;
                if (cg + 1 > rbase + 8) s[j][3] = -1e9f;
            }
        }

#pragma unroll
        for (int rr = 0; rr < 2; rr++) {
            float tmax = -1e30f;
#pragma unroll
            for (int j = 0; j < 8; j++)
                tmax = fmaxf(tmax, fmaxf(s[j][rr * 2], s[j][rr * 2 + 1]));
            tmax = fmaxf(tmax, __shfl_xor_sync(0xffffffffu, tmax, 1));
            tmax = fmaxf(tmax, __shfl_xor_sync(0xffffffffu, tmax, 2));
            float mnew = fmaxf(mrow[rr], tmax);
            float scalef = __expf(mrow[rr] - mnew);
            mrow[rr] = mnew;
            float tsum = 0.f;
#pragma unroll
            for (int j = 0; j < 8; j++) {
                float p0 = __expf(s[j][rr * 2] - mnew);
                float p1 = __expf(s[j][rr * 2 + 1] - mnew);
                s[j][rr * 2] = p0;
                s[j][rr * 2 + 1] = p1;
                tsum += p0 + p1;
            }
            tsum += __shfl_xor_sync(0xffffffffu, tsum, 1);
            tsum += __shfl_xor_sync(0xffffffffu, tsum, 2);
            lrow[rr] = lrow[rr] * scalef + tsum;
#pragma unroll
            for (int dt = 0; dt < 16; dt++) {
                o[dt][rr * 2] *= scalef;
                o[dt][rr * 2 + 1] *= scalef;
            }
        }

#pragma unroll
        for (int c = 0; c < 4; c++) {
            uint32_t pah[4];
#pragma unroll
            for (int hq = 0; hq < 2; hq++) {
                pah[hq * 2 + 0] = packh(s[2 * c + hq][0], s[2 * c + hq][1]);
                pah[hq * 2 + 1] = packh(s[2 * c + hq][2], s[2 * c + hq][3]);
            }
            const uint32_t vrow = vb + kvo + c * (16 * 272);
#pragma unroll
            for (int dt16 = 0; dt16 < 8; dt16++) {
                uint32_t vh4[4];
                LDSM4T(vh4, vrow + dt16 * 32);
                MMA_H2(o[2 * dt16], pah, vh4[0], vh4[1]);
                MMA_H2(o[2 * dt16 + 1], pah, vh4[2], vh4[3]);
            }
        }
    }

    // ---- epilogue: fp16 unnormalized partials + fp32 (m, l) ----
#pragma unroll
    for (int rr = 0; rr < 2; rr++) {
        int row = q0 + wq + g + rr * 8;
        if (tg == 0) {
            float2 ml; ml.x = mrow[rr]; ml.y = lrow[rr];
            g_ml[row * NH + h] = ml;
        }
#pragma unroll
        for (int dt = 0; dt < 16; dt++) {
            *(uint32_t*)(g_op + (size_t)row * (NH * HD) + h * HD + dt * 8 + 2 * tg) =
                packh(o[dt][rr * 2], o[dt][rr * 2 + 1]);
        }
    }
#undef A_ISSUE
}

// ---------------- split-K combine (fp16 partials) ----------------------------
__global__ void combine_attn() {
    int i = blockIdx.x * blockDim.x + threadIdx.x;   // 8 halves per thread
    int base = i * 8;
    int row = base >> 11;
    int h = (base & 2047) >> 7;
    float2 ml0 = g_ml0[row * NH + h];
    float2 ml1 = g_ml1[row * NH + h];
    float M = fmaxf(ml0.x, ml1.x);
    float w0 = __expf(ml0.x - M), w1 = __expf(ml1.x - M);
    float invl = 1.0f / (ml0.y * w0 + ml1.y * w1);
    uint4 a = *(const uint4*)(g_op0h + base);
    uint4 b = *(const uint4*)(g_op1h + base);
    uint4 r;
    float2 ax, bx;
    ax = unp(a.x); bx = unp(b.x);
    r.x = packh((ax.x * w0 + bx.x * w1) * invl, (ax.y * w0 + bx.y * w1) * invl);
    ax = unp(a.y); bx = unp(b.y);
    r.y = packh((ax.x * w0 + bx.x * w1) * invl, (ax.y * w0 + bx.y * w1) * invl);
    ax = unp(a.z); bx = unp(b.z);
    r.z = packh((ax.x * w0 + bx.x * w1) * invl, (ax.y * w0 + bx.y * w1) * invl);
    ax = unp(a.w); bx = unp(b.w);
    r.w = packh((ax.x * w0 + bx.x * w1) * invl, (ax.y * w0 + bx.y * w1) * invl);
    *(uint4*)(g_ah + base) = r;
}

// ---------------- launch -----------------------------------------------------
extern "C" void kernel_launch(void* const* d_in, const int* in_sizes, int n_in,
                              void* d_out, int out_size) {
    const float* hidden = (const float*)d_in[0];
    const float* cosb   = (const float*)d_in[1];
    const float* sinb   = (const float*)d_in[2];
    const float* kcache = (const float*)d_in[3];
    const float* vcache = (const float*)d_in[4];
    const float* wqkv   = (const float*)d_in[6];
    const float* bqkv   = (const float*)d_in[7];
    const float* wo     = (const float*)d_in[8];
    const float* bo     = (const float*)d_in[9];
    const float* qw     = (const float*)d_in[10];
    const float* kw     = (const float*)d_in[11];
    const int*   widx   = (const int*)d_in[12];
    float* out = (float*)d_out;

    f16 *p_hidh, *p_wqh, *p_woh, *p_ah;
    cudaGetSymbolAddress((void**)&p_hidh, g_hidh);
    cudaGetSymbolAddress((void**)&p_wqh, g_wqh);
    cudaGetSymbolAddress((void**)&p_woh, g_woh);
    cudaGetSymbolAddress((void**)&p_ah, g_ah);

    static cudaStream_t s1 = nullptr, s2 = nullptr;
    static cudaEvent_t eRoot, eW1, eCache, eW2;
    static bool init = false;
    if (!init) {
        cudaStreamCreateWithFlags(&s1, cudaStreamNonBlocking);
        cudaStreamCreateWithFlags(&s2, cudaStreamNonBlocking);
        cudaEventCreateWithFlags(&eRoot, cudaEventDisableTiming);
        cudaEventCreateWithFlags(&eW1, cudaEventDisableTiming);
        cudaEventCreateWithFlags(&eCache, cudaEventDisableTiming);
        cudaEventCreateWithFlags(&eW2, cudaEventDisableTiming);
        cudaFuncSetAttribute(gemm_h, cudaFuncAttributeMaxDynamicSharedMemorySize, G_SMEM);
        cudaFuncSetAttribute(attn_tc, cudaFuncAttributeMaxDynamicSharedMemorySize, ATTN_SMEM);
        init = true;
    }

    // fork
    cudaEventRecord(eRoot, 0);
    cudaStreamWaitEvent(s1, eRoot, 0);
    cudaStreamWaitEvent(s2, eRoot, 0);

    conv_h<<<1024, 256>>>(hidden, p_hidh, S_LEN * HID / 4);
    conv_h<<<1024, 256, 0, s1>>>(wqkv, p_wqh, QKV_OUT * HID / 4);
    cudaEventRecord(eW1, s1);
    copy_caches<<<256, 256, 0, s1>>>(kcache, vcache);
    cudaEventRecord(eCache, s1);
    conv_h<<<1024, 256, 0, s2>>>(wo, p_woh, HID * HID / 4);
    cudaEventRecord(eW2, s2);

    // QKV GEMM with fused RMSNorm+RoPE+scatter epilogue
    cudaStreamWaitEvent(0, eW1, 0);
    cudaStreamWaitEvent(0, eCache, 0);   // scatter overwrites staged caches
    gemm_h<<<dim3(QKV_OUT / 128, S_LEN / 128), 256, G_SMEM>>>(
        p_hidh, p_wqh, bqkv, nullptr, QKV_OUT, HID, 2,
        qw, kw, cosb, sinb, widx);

    // split-K attention
    attn_tc<<<dim3(NH, 32), 256, ATTN_SMEM>>>();

    // combine partials -> g_ah
    combine_attn<<<(S_LEN * NH * HD / 8) / 256, 256>>>();

    // O-proj
    cudaStreamWaitEvent(0, eW2, 0);
    gemm_h<<<dim3(HID / 128, S_LEN / 128), 256, G_SMEM>>>(
        p_ah, p_woh, bo, out, HID, NH * HD, 0,
        nullptr, nullptr, nullptr, nullptr, nullptr);
}

// round 17
// speedup vs baseline: 2.7568x; 1.0171x over previous
#include <cuda_runtime.h>
#include <cuda_fp16.h>
#include <cstdint>
#include <math.h>

// Problem constants
#define S_LEN 2048
#define HID 2048
#define NH 16
#define NKV 4
#define HD 128
#define QKV_OUT 3072
#define Q_SZ 2048
#define KV_SZ 512
#define SCALE_Q 0.08838834764831845f

typedef __half f16;

// ---------------- scratch ----------------------------------------------------
__device__ f16 g_hidh[S_LEN * HID];
__device__ f16 g_wqh[QKV_OUT * HID];
__device__ f16 g_woh[HID * HID];
__device__ f16 g_qh[S_LEN * NH * HD];
__device__ f16 g_kh[S_LEN * NKV * HD];
__device__ f16 g_vh[S_LEN * NKV * HD];
__device__ f16 g_ah[S_LEN * NH * HD];
// split-K partials (fp16 unnormalized O, fp32 m/l)
__device__ f16 g_op0h[S_LEN * NH * HD];
__device__ f16 g_op1h[S_LEN * NH * HD];
__device__ float2 g_ml0[S_LEN * NH];
__device__ float2 g_ml1[S_LEN * NH];

// ---------------- helpers ----------------------------------------------------
__device__ __forceinline__ uint32_t smem_u32(const void* p) {
    return (uint32_t)__cvta_generic_to_shared(p);
}
__device__ __forceinline__ uint32_t packh(float lo_v, float hi_v) {
    uint32_t r;
    asm("cvt.rn.f16x2.f32 %0, %1, %2;" : "=r"(r) : "f"(hi_v), "f"(lo_v));
    return r;
}
__device__ __forceinline__ float2 unp(uint32_t u) {
    __half2 h = *(__half2*)&u;
    return __half22float2(h);
}

#define MMA_H2(d, a, b0, b1) \
    asm volatile( \
        "mma.sync.aligned.m16n8k16.row.col.f32.f16.f16.f32 " \
        "{%0,%1,%2,%3}, {%4,%5,%6,%7}, {%8,%9}, {%0,%1,%2,%3};" \
        : "+f"((d)[0]), "+f"((d)[1]), "+f"((d)[2]), "+f"((d)[3]) \
        : "r"((a)[0]), "r"((a)[1]), "r"((a)[2]), "r"((a)[3]), \
          "r"(b0), "r"(b1))

#define LDSM4(r, addr) \
    asm volatile("ldmatrix.sync.aligned.m8n8.x4.shared.b16 {%0,%1,%2,%3}, [%4];" \
        : "=r"((r)[0]), "=r"((r)[1]), "=r"((r)[2]), "=r"((r)[3]) : "r"(addr))

#define LDSM4T(r, addr) \
    asm volatile("ldmatrix.sync.aligned.m8n8.x4.trans.shared.b16 {%0,%1,%2,%3}, [%4];" \
        : "=r"((r)[0]), "=r"((r)[1]), "=r"((r)[2]), "=r"((r)[3]) : "r"(addr))

#define CP16(dst, src) \
    asm volatile("cp.async.cg.shared.global [%0], [%1], 16;" :: "r"(dst), "l"(src))
#define CP_COMMIT() asm volatile("cp.async.commit_group;" ::: "memory")
#define CP_WAIT(n) asm volatile("cp.async.wait_group %0;" :: "n"(n) : "memory")

// ---------------- conversion kernels ----------------------------------------
__global__ void conv_h(const float* __restrict__ src, f16* __restrict__ hi, int n4) {
    __half2* H = (__half2*)hi;
    for (int i = blockIdx.x * blockDim.x + threadIdx.x; i < n4;
         i += gridDim.x * blockDim.x) {
        float4 v = ((const float4*)src)[i];
        H[2 * i] = __floats2half2_rn(v.x, v.y);
        H[2 * i + 1] = __floats2half2_rn(v.z, v.w);
    }
}

__global__ void copy_caches(const float* __restrict__ kc, const float* __restrict__ vc) {
    int n = S_LEN * NKV * HD;
    for (int i = blockIdx.x * blockDim.x + threadIdx.x; i < n;
         i += gridDim.x * blockDim.x) {
        g_kh[i] = __float2half_rn(kc[i]);
        g_vh[i] = __float2half_rn(vc[i]);
    }
}

// =================== fp16 GEMM with optional fused QKV epilogue ==============
// mode 0: C[M,N] fp32 out + bias (O-proj).
// mode 2: QKV fused epilogue — n-tile == head; RMSNorm+RoPE+scatter in-CTA.
#define GSTRIDE 40
#define GB_E (128 * GSTRIDE)
#define GB_B (GB_E * 2)
#define GSTAGE_B (2 * GB_B)
#define G_SMEM (4 * GSTAGE_B)             // 81920 bytes

__global__ void __launch_bounds__(256)
gemm_h(const f16* __restrict__ Ah_g, const f16* __restrict__ Bh_g,
       const float* __restrict__ bias, float* __restrict__ C,
       int N, int K, int mode,
       const float* __restrict__ qw, const float* __restrict__ kw,
       const float* __restrict__ cosb, const float* __restrict__ sinb,
       const int* __restrict__ widx) {
    extern __shared__ f16 smg[];
    const int t = threadIdx.x;
    const int lane = t & 31, wid = t >> 5;
    const int g = lane >> 2, tg = lane & 3;
    const int wm = (wid & 3) * 32, wn = (wid >> 2) * 64;
    const int m0 = blockIdx.y << 7, n0 = blockIdx.x << 7;
    const int nch = K >> 5;

    const int l15 = lane & 15, lh = lane >> 4;
    const uint32_t sb = smem_u32(smg);
    const uint32_t offA = (uint32_t)((wm + l15) * 80 + lh * 16);
    const uint32_t offB = (uint32_t)((wn + l15) * 80 + lh * 16);

    float d[2][8][4];
#pragma unroll
    for (int i = 0; i < 2; i++)
#pragma unroll
        for (int j = 0; j < 8; j++)
#pragma unroll
            for (int q = 0; q < 4; q++) d[i][j][q] = 0.f;

#define G_ISSUE(c) do { \
    uint32_t base = sb + ((c) & 3) * GSTAGE_B; \
    _Pragma("unroll") \
    for (int j = 0; j < 2; j++) { \
        int u = t + (j << 8); int row = u >> 2, q = u & 3; \
        uint32_t dst = base + (uint32_t)(row * GSTRIDE + (q << 3)) * 2; \
        size_t ao = (size_t)(m0 + row) * K + ((c) << 5) + (q << 3); \
        size_t bo = (size_t)(n0 + row) * K + ((c) << 5) + (q << 3); \
        CP16(dst, Ah_g + ao); \
        CP16(dst + GB_B, Bh_g + bo); \
    } } while (0)

    G_ISSUE(0); CP_COMMIT();
    G_ISSUE(1); CP_COMMIT();
    G_ISSUE(2); CP_COMMIT();

    for (int c = 0; c < nch; c++) {
        CP_WAIT(2);
        __syncthreads();
        const uint32_t base = sb + (c & 3) * GSTAGE_B;
#pragma unroll
        for (int ks = 0; ks < 2; ks++) {
            const uint32_t ko = ks * 32;
            uint32_t ah[2][4];
#pragma unroll
            for (int mt = 0; mt < 2; mt++)
                LDSM4(ah[mt], base + offA + mt * 1280 + ko);
#pragma unroll
            for (int jp = 0; jp < 4; jp++) {
                uint32_t bh4[4];
                LDSM4(bh4, base + GB_B + offB + jp * 1280 + ko);
#pragma unroll
                for (int mt = 0; mt < 2; mt++) {
                    MMA_H2(d[mt][2 * jp], ah[mt], bh4[0], bh4[2]);
                    MMA_H2(d[mt][2 * jp + 1], ah[mt], bh4[1], bh4[3]);
                }
            }
        }
        __syncthreads();
        if (c + 3 < nch) { G_ISSUE(c + 3); CP_COMMIT(); }
    }

    // ---- add bias (both modes) ----
#pragma unroll
    for (int i = 0; i < 2; i++)
#pragma unroll
        for (int j = 0; j < 8; j++) {
            int cix = n0 + wn + j * 8 + tg * 2;
            float2 b2 = *(const float2*)(bias + cix);
            d[i][j][0] += b2.x; d[i][j][1] += b2.y;
            d[i][j][2] += b2.x; d[i][j][3] += b2.y;
        }

    if (mode == 0) {
#pragma unroll
        for (int i = 0; i < 2; i++) {
            int r = m0 + wm + i * 16 + g;
#pragma unroll
            for (int j = 0; j < 8; j++) {
                int cix = n0 + wn + j * 8 + tg * 2;
                float2 a0, a1;
                a0.x = d[i][j][0]; a0.y = d[i][j][1];
                a1.x = d[i][j][2]; a1.y = d[i][j][3];
                *(float2*)(C + (size_t)r * N + cix) = a0;
                *(float2*)(C + (size_t)(r + 8) * N + cix) = a1;
            }
        }
        return;
    }

    // ---- mode 2: fused QKV epilogue. n-tile == head (0..23). ----
    const int head = blockIdx.x;
    if (head >= 20) {  // V: convert + scatter
#pragma unroll
        for (int i = 0; i < 2; i++)
#pragma unroll
            for (int rr = 0; rr < 2; rr++) {
                int row = wm + 16 * i + g + 8 * rr;
                int s = m0 + row;
                size_t ob = ((size_t)widx[s] * NKV + (head - 20)) * HD;
#pragma unroll
                for (int j = 0; j < 8; j++) {
                    int col = wn + 8 * j + 2 * tg;
                    *(uint32_t*)(g_vh + ob + col) =
                        packh(d[i][j][2 * rr], d[i][j][2 * rr + 1]);
                }
            }
        return;
    }

    // Q/K: RMS norm over the 128-dim head (CTA-local), then RoPE + scatter.
    float* ytile = (float*)smg;            // [128][132] fp32
    float* psum = ytile + 128 * 132;       // [2][128]

    float ss[2][2] = {{0.f, 0.f}, {0.f, 0.f}};
#pragma unroll
    for (int i = 0; i < 2; i++)
#pragma unroll
        for (int j = 0; j < 8; j++) {
            ss[i][0] += d[i][j][0] * d[i][j][0] + d[i][j][1] * d[i][j][1];
            ss[i][1] += d[i][j][2] * d[i][j][2] + d[i][j][3] * d[i][j][3];
        }
#pragma unroll
    for (int i = 0; i < 2; i++)
#pragma unroll
        for (int rr = 0; rr < 2; rr++) {
            ss[i][rr] += __shfl_xor_sync(0xffffffffu, ss[i][rr], 1);
            ss[i][rr] += __shfl_xor_sync(0xffffffffu, ss[i][rr], 2);
        }
    const int half = wid >> 2;
    if (tg == 0) {
#pragma unroll
        for (int i = 0; i < 2; i++) {
            psum[half * 128 + wm + 16 * i + g] = ss[i][0];
            psum[half * 128 + wm + 16 * i + g + 8] = ss[i][1];
        }
    }
    __syncthreads();

    const float* wv = (head < 16) ? qw : kw;
#pragma unroll
    for (int i = 0; i < 2; i++)
#pragma unroll
        for (int rr = 0; rr < 2; rr++) {
            int row = wm + 16 * i + g + 8 * rr;
            float inv = rsqrtf((psum[row] + psum[128 + row]) * (1.0f / 128.0f) + 1e-6f);
#pragma unroll
            for (int j = 0; j < 8; j++) {
                int col = wn + 8 * j + 2 * tg;
                ytile[row * 132 + col] = d[i][j][2 * rr] * inv * wv[col];
                ytile[row * 132 + col + 1] = d[i][j][2 * rr + 1] * inv * wv[col + 1];
            }
        }
    __syncthreads();

    // RoPE + scatter: all 8 warps participate. Warp (wm, half) handles
    // the 16 rows wm + half*16 .. wm + half*16 + 15 (reads via smem ytile).
    {
        const bool isQ = (head < 16);
        const float scale = isQ ? SCALE_Q : 1.0f;
        f16* dstb = isQ ? g_qh : g_kh;
        const int i = half;
#pragma unroll
        for (int rr = 0; rr < 2; rr++) {
            int row = wm + 16 * i + g + 8 * rr;
            int s = m0 + row;
            size_t ob = isQ ? ((size_t)s * NH + head) * HD
                            : ((size_t)widx[s] * NKV + (head - 16)) * HD;
#pragma unroll
            for (int j = 0; j < 8; j++) {
                int c0 = 8 * j + 2 * tg;
                float x1a = ytile[row * 132 + c0];
                float x1b = ytile[row * 132 + c0 + 1];
                float x2a = ytile[row * 132 + c0 + 64];
                float x2b = ytile[row * 132 + c0 + 65];
                float ca = cosb[s * 64 + c0], sa = sinb[s * 64 + c0];
                float cb = cosb[s * 64 + c0 + 1], sb2 = sinb[s * 64 + c0 + 1];
                float y1a = (x1a * ca - x2a * sa) * scale;
                float y1b = (x1b * cb - x2b * sb2) * scale;
                float y2a = (x1a * sa + x2a * ca) * scale;
                float y2b = (x1b * sb2 + x2b * cb) * scale;
                *(uint32_t*)(dstb + ob + c0) = packh(y1a, y1b);
                *(uint32_t*)(dstb + ob + c0 + 64) = packh(y2a, y2b);
            }
        }
    }
#undef G_ISSUE
}

// =================== fp16 flash attention, split-K ===========================
#define APAD 136
#define QBUF_E (128 * APAD)
#define KVBUF_E (64 * APAD)
#define KVBUF_B (KVBUF_E * 2)
#define KVSTAGE_B (2 * KVBUF_B)
#define ATTN_SMEM (QBUF_E * 2 + 2 * KVSTAGE_B)   // 104448 B

__global__ void __launch_bounds__(256, 1) attn_tc() {
    extern __shared__ f16 sma[];
    f16* Qh = sma;

    const int t = threadIdx.x;
    const int lane = t & 31, w = t >> 5;
    const int g = lane >> 2, tg = lane & 3;
    const int qt = 15 - (blockIdx.y >> 1);
    const int part = blockIdx.y & 1;
    const int q0 = qt * 128;
    const int h = blockIdx.x, kvh = h >> 2;
    const int wq = w * 16;

    f16* g_op = part ? g_op1h : g_op0h;
    float2* g_ml = part ? g_ml1 : g_ml0;

    const uint32_t kvb = smem_u32(sma) + QBUF_E * 2;

#define A_ISSUE(kt) do { \
    uint32_t base = kvb + ((kt) & 1) * KVSTAGE_B; \
    _Pragma("unroll") \
    for (int i = 0; i < 4; i++) { \
        int u = t + (i << 8); int r = u >> 4, cc = u & 15; \
        size_t so = ((size_t)(((kt) << 6) + r) * NKV + kvh) * HD + cc * 8; \
        uint32_t dd = base + (uint32_t)(r * 272 + cc * 16); \
        CP16(dd, g_kh + so); \
        CP16(dd + KVBUF_B, g_vh + so); \
    } } while (0)

    const int kt0 = part * (qt + 1);
    const int kt1 = kt0 + (qt + 1);
    const int nkt = 2 * (qt + 1);

    A_ISSUE(kt0); CP_COMMIT();

#pragma unroll
    for (int i = 0; i < 8; i++) {
        int u = t + i * 256;
        int r = u >> 4, cc = u & 15;
        size_t qo = ((size_t)(q0 + r) * NH + h) * HD + cc * 8;
        *(uint4*)((char*)Qh + r * 272 + cc * 16) = *(const uint4*)(g_qh + qo);
    }

    const int l15 = lane & 15, lh = lane >> 4;
    const uint32_t qb_h = smem_u32(Qh) + (wq + l15) * 272 + lh * 16;
    uint32_t kb[4];
#pragma unroll
    for (int jp = 0; jp < 4; jp++)
        kb[jp] = kvb + (jp * 16 + l15) * 272 + lh * 16;
    const uint32_t vb = kvb + KVBUF_B + l15 * 272 + lh * 16;

    float o[16][4];
#pragma unroll
    for (int dt = 0; dt < 16; dt++)
#pragma unroll
        for (int q = 0; q < 4; q++) o[dt][q] = 0.f;
    float mrow[2] = {-1e30f, -1e30f};
    float lrow[2] = {0.f, 0.f};

    for (int kt = kt0; kt < kt1; kt++) {
        CP_WAIT(0);
        __syncthreads();
        if (kt + 1 < kt1) { A_ISSUE(kt + 1); CP_COMMIT(); }
        const uint32_t kvo = (kt & 1) * KVSTAGE_B;
        const int k0 = kt * 64;

        float s[8][4];
#pragma unroll
        for (int j = 0; j < 8; j++)
#pragma unroll
            for (int q = 0; q < 4; q++) s[j][q] = 0.f;

#pragma unroll
        for (int ks = 0; ks < 8; ks++) {
            const uint32_t ko = ks * 32;
            uint32_t aqh[4];
            LDSM4(aqh, qb_h + ko);
#pragma unroll
            for (int jp = 0; jp < 4; jp++) {
                uint32_t kh4[4];
                LDSM4(kh4, kb[jp] + kvo + ko);
                MMA_H2(s[2 * jp], aqh, kh4[0], kh4[2]);
                MMA_H2(s[2 * jp + 1], aqh, kh4[1], kh4[3]);
            }
        }

        if (kt >= nkt - 2) {
            const int rbase = q0 + wq + g;
#pragma unroll
            for (int j = 0; j < 8; j++) {
                int cg = k0 + 8 * j + 2 * tg;
                if (cg > rbase) s[j][0] = -1e9f;
                if (cg + 1 > rbase) s[j][1] = -1e9f;
                if (cg > rbase + 8) s[j][2] = -1e9f;
                if (cg + 1 > rbase + 8) s[j][3] = -1e9f;
            }
        }

#pragma unroll
        for (int rr = 0; rr < 2; rr++) {
            float tmax = -1e30f;
#pragma unroll
            for (int j = 0; j < 8; j++)
                tmax = fmaxf(tmax, fmaxf(s[j][rr * 2], s[j][rr * 2 + 1]));
            tmax = fmaxf(tmax, __shfl_xor_sync(0xffffffffu, tmax, 1));
            tmax = fmaxf(tmax, __shfl_xor_sync(0xffffffffu, tmax, 2));
            float mnew = fmaxf(mrow[rr], tmax);
            float scalef = __expf(mrow[rr] - mnew);
            mrow[rr] = mnew;
            float tsum = 0.f;
#pragma unroll
            for (int j = 0; j < 8; j++) {
                float p0 = __expf(s[j][rr * 2] - mnew);
                float p1 = __expf(s[j][rr * 2 + 1] - mnew);
                s[j][rr * 2] = p0;
                s[j][rr * 2 + 1] = p1;
                tsum += p0 + p1;
            }
            tsum += __shfl_xor_sync(0xffffffffu, tsum, 1);
            tsum += __shfl_xor_sync(0xffffffffu, tsum, 2);
            lrow[rr] = lrow[rr] * scalef + tsum;
#pragma unroll
            for (int dt = 0; dt < 16; dt++) {
                o[dt][rr * 2] *= scalef;
                o[dt][rr * 2 + 1] *= scalef;
            }
        }

#pragma unroll
        for (int c = 0; c < 4; c++) {
            uint32_t pah[4];
#pragma unroll
            for (int hq = 0; hq < 2; hq++) {
                pah[hq * 2 + 0] = packh(s[2 * c + hq][0], s[2 * c + hq][1]);
                pah[hq * 2 + 1] = packh(s[2 * c + hq][2], s[2 * c + hq][3]);
            }
            const uint32_t vrow = vb + kvo + c * (16 * 272);
#pragma unroll
            for (int dt16 = 0; dt16 < 8; dt16++) {
                uint32_t vh4[4];
                LDSM4T(vh4, vrow + dt16 * 32);
                MMA_H2(o[2 * dt16], pah, vh4[0], vh4[1]);
                MMA_H2(o[2 * dt16 + 1], pah, vh4[2], vh4[3]);
            }
        }
    }

    // ---- epilogue: fp16 unnormalized partials + fp32 (m, l) ----
#pragma unroll
    for (int rr = 0; rr < 2; rr++) {
        int row = q0 + wq + g + rr * 8;
        if (tg == 0) {
            float2 ml; ml.x = mrow[rr]; ml.y = lrow[rr];
            g_ml[row * NH + h] = ml;
        }
#pragma unroll
        for (int dt = 0; dt < 16; dt++) {
            *(uint32_t*)(g_op + (size_t)row * (NH * HD) + h * HD + dt * 8 + 2 * tg) =
                packh(o[dt][rr * 2], o[dt][rr * 2 + 1]);
        }
    }
#undef A_ISSUE
}

// ---------------- split-K combine (fp16 partials) ----------------------------
__global__ void combine_attn() {
    int i = blockIdx.x * blockDim.x + threadIdx.x;   // 8 halves per thread
    int base = i * 8;
    int row = base >> 11;
    int h = (base & 2047) >> 7;
    float2 ml0 = g_ml0[row * NH + h];
    float2 ml1 = g_ml1[row * NH + h];
    float M = fmaxf(ml0.x, ml1.x);
    float w0 = __expf(ml0.x - M), w1 = __expf(ml1.x - M);
    float invl = 1.0f / (ml0.y * w0 + ml1.y * w1);
    uint4 a = *(const uint4*)(g_op0h + base);
    uint4 b = *(const uint4*)(g_op1h + base);
    uint4 r;
    float2 ax, bx;
    ax = unp(a.x); bx = unp(b.x);
    r.x = packh((ax.x * w0 + bx.x * w1) * invl, (ax.y * w0 + bx.y * w1) * invl);
    ax = unp(a.y); bx = unp(b.y);
    r.y = packh((ax.x * w0 + bx.x * w1) * invl, (ax.y * w0 + bx.y * w1) * invl);
    ax = unp(a.z); bx = unp(b.z);
    r.z = packh((ax.x * w0 + bx.x * w1) * invl, (ax.y * w0 + bx.y * w1) * invl);
    ax = unp(a.w); bx = unp(b.w);
    r.w = packh((ax.x * w0 + bx.x * w1) * invl, (ax.y * w0 + bx.y * w1) * invl);
    *(uint4*)(g_ah + base) = r;
}

// ---------------- launch -----------------------------------------------------
extern "C" void kernel_launch(void* const* d_in, const int* in_sizes, int n_in,
                              void* d_out, int out_size) {
    const float* hidden = (const float*)d_in[0];
    const float* cosb   = (const float*)d_in[1];
    const float* sinb   = (const float*)d_in[2];
    const float* kcache = (const float*)d_in[3];
    const float* vcache = (const float*)d_in[4];
    const float* wqkv   = (const float*)d_in[6];
    const float* bqkv   = (const float*)d_in[7];
    const float* wo     = (const float*)d_in[8];
    const float* bo     = (const float*)d_in[9];
    const float* qw     = (const float*)d_in[10];
    const float* kw     = (const float*)d_in[11];
    const int*   widx   = (const int*)d_in[12];
    float* out = (float*)d_out;

    f16 *p_hidh, *p_wqh, *p_woh, *p_ah;
    cudaGetSymbolAddress((void**)&p_hidh, g_hidh);
    cudaGetSymbolAddress((void**)&p_wqh, g_wqh);
    cudaGetSymbolAddress((void**)&p_woh, g_woh);
    cudaGetSymbolAddress((void**)&p_ah, g_ah);

    static cudaStream_t s1 = nullptr, s2 = nullptr;
    static cudaEvent_t eRoot, eW1, eCache, eW2;
    static bool init = false;
    if (!init) {
        cudaStreamCreateWithFlags(&s1, cudaStreamNonBlocking);
        cudaStreamCreateWithFlags(&s2, cudaStreamNonBlocking);
        cudaEventCreateWithFlags(&eRoot, cudaEventDisableTiming);
        cudaEventCreateWithFlags(&eW1, cudaEventDisableTiming);
        cudaEventCreateWithFlags(&eCache, cudaEventDisableTiming);
        cudaEventCreateWithFlags(&eW2, cudaEventDisableTiming);
        cudaFuncSetAttribute(gemm_h, cudaFuncAttributeMaxDynamicSharedMemorySize, G_SMEM);
        cudaFuncSetAttribute(attn_tc, cudaFuncAttributeMaxDynamicSharedMemorySize, ATTN_SMEM);
        init = true;
    }

    // fork
    cudaEventRecord(eRoot, 0);
    cudaStreamWaitEvent(s1, eRoot, 0);
    cudaStreamWaitEvent(s2, eRoot, 0);

    // main: hidden conversion.  s1: wqkv conversion.  s2: caches, then wo.
    conv_h<<<1024, 256>>>(hidden, p_hidh, S_LEN * HID / 4);
    conv_h<<<1024, 256, 0, s1>>>(wqkv, p_wqh, QKV_OUT * HID / 4);
    cudaEventRecord(eW1, s1);
    copy_caches<<<256, 256, 0, s2>>>(kcache, vcache);
    cudaEventRecord(eCache, s2);
    conv_h<<<1024, 256, 0, s2>>>(wo, p_woh, HID * HID / 4);
    cudaEventRecord(eW2, s2);

    // QKV GEMM with fused RMSNorm+RoPE+scatter epilogue
    cudaStreamWaitEvent(0, eW1, 0);
    cudaStreamWaitEvent(0, eCache, 0);   // scatter overwrites staged caches
    gemm_h<<<dim3(QKV_OUT / 128, S_LEN / 128), 256, G_SMEM>>>(
        p_hidh, p_wqh, bqkv, nullptr, QKV_OUT, HID, 2,
        qw, kw, cosb, sinb, widx);

    // split-K attention
    attn_tc<<<dim3(NH, 32), 256, ATTN_SMEM>>>();

    // combine partials -> g_ah
    combine_attn<<<(S_LEN * NH * HD / 8) / 256, 256>>>();

    // O-proj
    cudaStreamWaitEvent(0, eW2, 0);
    gemm_h<<<dim3(HID / 128, S_LEN / 128), 256, G_SMEM>>>(
        p_ah, p_woh, bo, out, HID, NH * HD, 0,
        nullptr, nullptr, nullptr, nullptr, nullptr);
}